// round 4
// baseline (speedup 1.0000x reference)
#include <cuda_runtime.h>

// Shapes are fixed by the problem: T=2048, B=2, E=1024, H=16, D=64.
#define T_DIM 2048
#define B_DIM 2
#define E_DIM 1024
#define H_DIM 16
#define D_DIM 64
#define NH    32           // B*H
#define M_DIM 4096         // T*B

// Scratch (device globals — no allocation allowed).
// Layout: [n = b*16 + h][t][d], n in [0,32)
__device__ float g_q[(size_t)NH * T_DIM * D_DIM];
__device__ float g_k[(size_t)NH * T_DIM * D_DIM];
__device__ float g_v[(size_t)NH * T_DIM * D_DIM];
// attn result in [m = t*2 + b][e = h*64 + d] layout (ready for out-proj GEMM)
__device__ float g_attnx[(size_t)M_DIM * E_DIM];

// ---------------------------------------------------------------------------
// Fused QKV projection: C = X @ W^T + bias, written into head-major scratch.
// X: [4096,1024] row-major (m = t*B + b). W: [1024,1024] row-major [n][k].
// grid: (32, 24). blockIdx.y: wsel = y>>3 (0=q,1=k,2=v), nblk = y&7.
// ---------------------------------------------------------------------------
__global__ __launch_bounds__(256) void gemm_qkv(
    const float* __restrict__ X,
    const float* __restrict__ wq, const float* __restrict__ wk, const float* __restrict__ wv,
    const float* __restrict__ bq, const float* __restrict__ bk, const float* __restrict__ bv)
{
    __shared__ float As[8][128];
    __shared__ float Bs[8][128];

    const int wsel = blockIdx.y >> 3;
    const int n0   = (blockIdx.y & 7) * 128;
    const int m0   = blockIdx.x * 128;

    const float* W    = (wsel == 0) ? wq : (wsel == 1) ? wk : wv;
    const float* bias = (wsel == 0) ? bq : (wsel == 1) ? bk : bv;
    float*       dst  = (wsel == 0) ? g_q : (wsel == 1) ? g_k : g_v;
    const float  scale = (wsel == 0) ? 0.125f : 1.0f;   // D^-0.5 applied to q

    const int tid  = threadIdx.x;
    const int tx   = tid & 15;
    const int ty   = tid >> 4;
    const int lrow = tid >> 1;          // 0..127
    const int lk   = (tid & 1) * 4;     // 0 or 4

    float c[8][8];
#pragma unroll
    for (int i = 0; i < 8; i++)
#pragma unroll
        for (int j = 0; j < 8; j++) c[i][j] = 0.f;

    const float* Aptr = X + (size_t)(m0 + lrow) * E_DIM + lk;
    const float* Bptr = W + (size_t)(n0 + lrow) * E_DIM + lk;

    for (int k0 = 0; k0 < E_DIM; k0 += 8) {
        float4 av  = *(const float4*)(Aptr + k0);
        float4 bv4 = *(const float4*)(Bptr + k0);
        __syncthreads();
        As[lk + 0][lrow] = av.x;  As[lk + 1][lrow] = av.y;
        As[lk + 2][lrow] = av.z;  As[lk + 3][lrow] = av.w;
        Bs[lk + 0][lrow] = bv4.x; Bs[lk + 1][lrow] = bv4.y;
        Bs[lk + 2][lrow] = bv4.z; Bs[lk + 3][lrow] = bv4.w;
        __syncthreads();
#pragma unroll
        for (int kk = 0; kk < 8; kk++) {
            float4 a0 = *(const float4*)&As[kk][ty * 8];
            float4 a1 = *(const float4*)&As[kk][ty * 8 + 4];
            float4 b0 = *(const float4*)&Bs[kk][tx * 8];
            float4 b1 = *(const float4*)&Bs[kk][tx * 8 + 4];
            float a[8] = {a0.x, a0.y, a0.z, a0.w, a1.x, a1.y, a1.z, a1.w};
            float b[8] = {b0.x, b0.y, b0.z, b0.w, b1.x, b1.y, b1.z, b1.w};
#pragma unroll
            for (int i = 0; i < 8; i++)
#pragma unroll
                for (int j = 0; j < 8; j++)
                    c[i][j] = fmaf(a[i], b[j], c[i][j]);
        }
    }

    // epilogue: scatter into head-major layout [(b*16+h)][t][d]
    float4 bl0 = *(const float4*)(bias + n0 + tx * 8);
    float4 bl1 = *(const float4*)(bias + n0 + tx * 8 + 4);
    float bb[8] = {bl0.x, bl0.y, bl0.z, bl0.w, bl1.x, bl1.y, bl1.z, bl1.w};

#pragma unroll
    for (int i = 0; i < 8; i++) {
        int m    = m0 + ty * 8 + i;
        int tt   = m >> 1;
        int bsel = m & 1;
#pragma unroll
        for (int jj = 0; jj < 8; jj += 4) {
            int nn = n0 + tx * 8 + jj;
            int h  = nn >> 6;
            int dd = nn & 63;
            float4 v;
            v.x = (c[i][jj + 0] + bb[jj + 0]) * scale;
            v.y = (c[i][jj + 1] + bb[jj + 1]) * scale;
            v.z = (c[i][jj + 2] + bb[jj + 2]) * scale;
            v.w = (c[i][jj + 3] + bb[jj + 3]) * scale;
            *(float4*)(dst + (size_t)((bsel << 4) + h) * (T_DIM * D_DIM)
                           + (size_t)tt * D_DIM + dd) = v;
        }
    }
}

// ---------------------------------------------------------------------------
// Attention: per (head n, q-block of 128 rows). Two-pass exact softmax.
//   pass 1: recomputable scores -> row max m_i and denominator l_i
//   pass 2: recompute scores, p = exp(s-m)/l  -> write attn_weights (once),
//           accumulate P @ V via smem.
// grid (16, 32), 512 threads, 165,888 B dyn smem.
// ---------------------------------------------------------------------------
__global__ __launch_bounds__(512) void attn_kernel(float* __restrict__ w_out)
{
    extern __shared__ float sm[];
    float* qT = sm;                         // [64][128]  (d-major)
    float* kT = sm + 64 * 128;              // [64][128]
    float* vS = sm + 2 * 64 * 128;          // [128][64]
    float* pS = sm + 2 * 64 * 128 + 128 * 64; // [128][132] padded stride

    const int n   = blockIdx.y;
    const int qb  = blockIdx.x * 128;
    const int tid = threadIdx.x;
    const int warp = tid >> 5;
    const int lane = tid & 31;
    const int r0   = warp * 8;              // this warp's 8 q-rows

    const float* qbase = g_q + (size_t)n * (T_DIM * D_DIM) + (size_t)qb * D_DIM;
    const float* kbase = g_k + (size_t)n * (T_DIM * D_DIM);
    const float* vbase = g_v + (size_t)n * (T_DIM * D_DIM);

    // Load Q tile transposed: qT[d][row]
    for (int i = tid; i < 128 * 16; i += 512) {
        int row = i >> 4, dv = (i & 15) * 4;
        float4 v4 = *(const float4*)(qbase + row * D_DIM + dv);
        qT[(dv + 0) * 128 + row] = v4.x;
        qT[(dv + 1) * 128 + row] = v4.y;
        qT[(dv + 2) * 128 + row] = v4.z;
        qT[(dv + 3) * 128 + row] = v4.w;
    }

    float m_i[8], l_i[8];
#pragma unroll
    for (int r = 0; r < 8; r++) { m_i[r] = -1e30f; l_i[r] = 0.f; }

    // ---------------- pass 1: statistics ----------------
    for (int sc = 0; sc < 16; sc++) {
        __syncthreads();
        const float* kc = kbase + (size_t)(sc * 128) * D_DIM;
        for (int i = tid; i < 128 * 16; i += 512) {
            int row = i >> 4, dv = (i & 15) * 4;
            float4 v4 = *(const float4*)(kc + row * D_DIM + dv);
            kT[(dv + 0) * 128 + row] = v4.x;
            kT[(dv + 1) * 128 + row] = v4.y;
            kT[(dv + 2) * 128 + row] = v4.z;
            kT[(dv + 3) * 128 + row] = v4.w;
        }
        __syncthreads();

        float acc[8][4];
#pragma unroll
        for (int r = 0; r < 8; r++)
#pragma unroll
            for (int j = 0; j < 4; j++) acc[r][j] = 0.f;

#pragma unroll 8
        for (int d = 0; d < 64; d++) {
            float4 a0  = *(const float4*)&qT[d * 128 + r0];
            float4 a1  = *(const float4*)&qT[d * 128 + r0 + 4];
            float4 bk4 = *(const float4*)&kT[d * 128 + lane * 4];
            float a[8] = {a0.x, a0.y, a0.z, a0.w, a1.x, a1.y, a1.z, a1.w};
            float b[4] = {bk4.x, bk4.y, bk4.z, bk4.w};
#pragma unroll
            for (int r = 0; r < 8; r++)
#pragma unroll
                for (int j = 0; j < 4; j++)
                    acc[r][j] = fmaf(a[r], b[j], acc[r][j]);
        }

#pragma unroll
        for (int r = 0; r < 8; r++) {
            float mx = fmaxf(fmaxf(acc[r][0], acc[r][1]), fmaxf(acc[r][2], acc[r][3]));
#pragma unroll
            for (int off = 16; off > 0; off >>= 1)
                mx = fmaxf(mx, __shfl_xor_sync(0xffffffffu, mx, off));
            float mn = fmaxf(m_i[r], mx);
            float ss = __expf(acc[r][0] - mn) + __expf(acc[r][1] - mn)
                     + __expf(acc[r][2] - mn) + __expf(acc[r][3] - mn);
#pragma unroll
            for (int off = 16; off > 0; off >>= 1)
                ss += __shfl_xor_sync(0xffffffffu, ss, off);
            l_i[r] = l_i[r] * __expf(m_i[r] - mn) + ss;
            m_i[r] = mn;
        }
    }

    float inv_l[8];
#pragma unroll
    for (int r = 0; r < 8; r++) inv_l[r] = 1.0f / l_i[r];

    float o[4][4];
#pragma unroll
    for (int i = 0; i < 4; i++)
#pragma unroll
        for (int j = 0; j < 4; j++) o[i][j] = 0.f;

    const int rg = tid >> 4;   // 0..31 (row-group of 4 for PV)
    const int dg = tid & 15;   // 0..15 (d-group of 4)

    // ---------------- pass 2: weights + PV ----------------
    for (int sc = 0; sc < 16; sc++) {
        __syncthreads();   // all prior PV reads of vS/pS done
        const float* kc = kbase + (size_t)(sc * 128) * D_DIM;
        const float* vc = vbase + (size_t)(sc * 128) * D_DIM;
        for (int i = tid; i < 128 * 16; i += 512) {
            int row = i >> 4, dv = (i & 15) * 4;
            float4 v4 = *(const float4*)(kc + row * D_DIM + dv);
            kT[(dv + 0) * 128 + row] = v4.x;
            kT[(dv + 1) * 128 + row] = v4.y;
            kT[(dv + 2) * 128 + row] = v4.z;
            kT[(dv + 3) * 128 + row] = v4.w;
            float4 v5 = *(const float4*)(vc + row * D_DIM + dv);
            *(float4*)&vS[row * D_DIM + dv] = v5;
        }
        __syncthreads();

        float acc[8][4];
#pragma unroll
        for (int r = 0; r < 8; r++)
#pragma unroll
            for (int j = 0; j < 4; j++) acc[r][j] = 0.f;

#pragma unroll 8
        for (int d = 0; d < 64; d++) {
            float4 a0  = *(const float4*)&qT[d * 128 + r0];
            float4 a1  = *(const float4*)&qT[d * 128 + r0 + 4];
            float4 bk4 = *(const float4*)&kT[d * 128 + lane * 4];
            float a[8] = {a0.x, a0.y, a0.z, a0.w, a1.x, a1.y, a1.z, a1.w};
            float b[4] = {bk4.x, bk4.y, bk4.z, bk4.w};
#pragma unroll
            for (int r = 0; r < 8; r++)
#pragma unroll
                for (int j = 0; j < 4; j++)
                    acc[r][j] = fmaf(a[r], b[j], acc[r][j]);
        }

        // normalized probabilities: smem (for PV) + gmem (attn_weights output)
        float* wb = w_out + (size_t)n * ((size_t)T_DIM * T_DIM)
                          + (size_t)(qb + r0) * T_DIM + sc * 128 + lane * 4;
#pragma unroll
        for (int r = 0; r < 8; r++) {
            float4 p;
            p.x = __expf(acc[r][0] - m_i[r]) * inv_l[r];
            p.y = __expf(acc[r][1] - m_i[r]) * inv_l[r];
            p.z = __expf(acc[r][2] - m_i[r]) * inv_l[r];
            p.w = __expf(acc[r][3] - m_i[r]) * inv_l[r];
            *(float4*)&pS[(r0 + r) * 132 + lane * 4] = p;
            *(float4*)(wb + (size_t)r * T_DIM) = p;
        }
        __syncthreads();

        // PV: o[128x64] += pS[128x128] @ vS[128x64]
#pragma unroll 4
        for (int s = 0; s < 128; s++) {
            float4 bv4 = *(const float4*)&vS[s * D_DIM + dg * 4];
#pragma unroll
            for (int i = 0; i < 4; i++) {
                float a = pS[(rg * 4 + i) * 132 + s];
                o[i][0] = fmaf(a, bv4.x, o[i][0]);
                o[i][1] = fmaf(a, bv4.y, o[i][1]);
                o[i][2] = fmaf(a, bv4.z, o[i][2]);
                o[i][3] = fmaf(a, bv4.w, o[i][3]);
            }
        }
    }

    // write attn into [m = t*2+b][e = h*64+d] layout for the output projection
    const int bsel = n >> 4;
    const int h    = n & 15;
#pragma unroll
    for (int i = 0; i < 4; i++) {
        int trow = qb + rg * 4 + i;
        float4 v;
        v.x = o[i][0]; v.y = o[i][1]; v.z = o[i][2]; v.w = o[i][3];
        *(float4*)(g_attnx + (size_t)(trow * 2 + bsel) * E_DIM + h * 64 + dg * 4) = v;
    }
}

// ---------------------------------------------------------------------------
// Output projection: out = g_attnx @ wo^T + bo. grid (32, 8).
// ---------------------------------------------------------------------------
__global__ __launch_bounds__(256) void gemm_out(
    const float* __restrict__ wo, const float* __restrict__ bo, float* __restrict__ out)
{
    __shared__ float As[8][128];
    __shared__ float Bs[8][128];

    const int n0 = blockIdx.y * 128;
    const int m0 = blockIdx.x * 128;

    const int tid  = threadIdx.x;
    const int tx   = tid & 15;
    const int ty   = tid >> 4;
    const int lrow = tid >> 1;
    const int lk   = (tid & 1) * 4;

    float c[8][8];
#pragma unroll
    for (int i = 0; i < 8; i++)
#pragma unroll
        for (int j = 0; j < 8; j++) c[i][j] = 0.f;

    const float* Aptr = g_attnx + (size_t)(m0 + lrow) * E_DIM + lk;
    const float* Bptr = wo + (size_t)(n0 + lrow) * E_DIM + lk;

    for (int k0 = 0; k0 < E_DIM; k0 += 8) {
        float4 av  = *(const float4*)(Aptr + k0);
        float4 bv4 = *(const float4*)(Bptr + k0);
        __syncthreads();
        As[lk + 0][lrow] = av.x;  As[lk + 1][lrow] = av.y;
        As[lk + 2][lrow] = av.z;  As[lk + 3][lrow] = av.w;
        Bs[lk + 0][lrow] = bv4.x; Bs[lk + 1][lrow] = bv4.y;
        Bs[lk + 2][lrow] = bv4.z; Bs[lk + 3][lrow] = bv4.w;
        __syncthreads();
#pragma unroll
        for (int kk = 0; kk < 8; kk++) {
            float4 a0 = *(const float4*)&As[kk][ty * 8];
            float4 a1 = *(const float4*)&As[kk][ty * 8 + 4];
            float4 b0 = *(const float4*)&Bs[kk][tx * 8];
            float4 b1 = *(const float4*)&Bs[kk][tx * 8 + 4];
            float a[8] = {a0.x, a0.y, a0.z, a0.w, a1.x, a1.y, a1.z, a1.w};
            float b[8] = {b0.x, b0.y, b0.z, b0.w, b1.x, b1.y, b1.z, b1.w};
#pragma unroll
            for (int i = 0; i < 8; i++)
#pragma unroll
                for (int j = 0; j < 8; j++)
                    c[i][j] = fmaf(a[i], b[j], c[i][j]);
        }
    }

    float4 bl0 = *(const float4*)(bo + n0 + tx * 8);
    float4 bl1 = *(const float4*)(bo + n0 + tx * 8 + 4);
    float bb[8] = {bl0.x, bl0.y, bl0.z, bl0.w, bl1.x, bl1.y, bl1.z, bl1.w};

#pragma unroll
    for (int i = 0; i < 8; i++) {
        int m = m0 + ty * 8 + i;
#pragma unroll
        for (int jj = 0; jj < 8; jj += 4) {
            float4 v;
            v.x = c[i][jj + 0] + bb[jj + 0];
            v.y = c[i][jj + 1] + bb[jj + 1];
            v.z = c[i][jj + 2] + bb[jj + 2];
            v.w = c[i][jj + 3] + bb[jj + 3];
            *(float4*)(out + (size_t)m * E_DIM + n0 + tx * 8 + jj) = v;
        }
    }
}

// ---------------------------------------------------------------------------
// Launch: QKV -> attention -> output projection (default stream, graph-safe).
// d_out = [ out (T*B*E floats) | attn_weights (32*2048*2048 floats) ]
// ---------------------------------------------------------------------------
extern "C" void kernel_launch(void* const* d_in, const int* in_sizes, int n_in,
                              void* d_out, int out_size)
{
    const float* query = (const float*)d_in[0];
    const float* wq    = (const float*)d_in[1];
    const float* bq    = (const float*)d_in[2];
    const float* wk    = (const float*)d_in[3];
    const float* bk    = (const float*)d_in[4];
    const float* wv    = (const float*)d_in[5];
    const float* bv    = (const float*)d_in[6];
    const float* wo    = (const float*)d_in[7];
    const float* bo    = (const float*)d_in[8];

    float* out   = (float*)d_out;
    float* w_out = out + (size_t)T_DIM * B_DIM * E_DIM;   // attn_weights region

    const int attn_smem = (2 * 64 * 128 + 128 * 64 + 128 * 132) * 4;  // 165,888 B
    cudaFuncSetAttribute(attn_kernel, cudaFuncAttributeMaxDynamicSharedMemorySize, attn_smem);

    gemm_qkv<<<dim3(32, 24), 256>>>(query, wq, wk, wv, bq, bk, bv);
    attn_kernel<<<dim3(16, 32), 512, attn_smem>>>(w_out);
    gemm_out<<<dim3(32, 8), 256>>>(wo, bo, out);
}

// round 5
// speedup vs baseline: 1.9524x; 1.9524x over previous
#include <cuda_runtime.h>
#include <cuda_bf16.h>

// T=2048, B=2, E=1024, H=16, D=64
#define T_DIM 2048
#define E_DIM 1024
#define NH    32            // B*H
#define M_DIM 4096          // T*B
#define HD    (T_DIM * 64)  // per-head plane: 131072 elems

// ---------------------------------------------------------------------------
// Scratch: bf16 hi/lo split planes (device globals; no allocation allowed).
// q/k/v layout: [n = b*16 + h][t][d].  attnx layout: [m = t*2+b][e = h*64+d].
// ---------------------------------------------------------------------------
__device__ __nv_bfloat16 g_qh[(size_t)NH * HD], g_ql[(size_t)NH * HD];
__device__ __nv_bfloat16 g_kh[(size_t)NH * HD], g_kl[(size_t)NH * HD];
__device__ __nv_bfloat16 g_vh[(size_t)NH * HD], g_vl[(size_t)NH * HD];
__device__ __nv_bfloat16 g_ah[(size_t)M_DIM * E_DIM], g_al[(size_t)M_DIM * E_DIM];

// ---------------------------------------------------------------------------
// MMA / ldmatrix helpers
// ---------------------------------------------------------------------------
__device__ __forceinline__ unsigned smem_u32(const void* p) {
    return (unsigned)__cvta_generic_to_shared(p);
}
__device__ __forceinline__ void ldmA(unsigned addr, unsigned& r0, unsigned& r1,
                                     unsigned& r2, unsigned& r3) {
    asm volatile("ldmatrix.sync.aligned.m8n8.x4.shared.b16 {%0,%1,%2,%3}, [%4];"
                 : "=r"(r0), "=r"(r1), "=r"(r2), "=r"(r3) : "r"(addr));
}
__device__ __forceinline__ void ldmB(unsigned addr, unsigned& r0, unsigned& r1) {
    asm volatile("ldmatrix.sync.aligned.m8n8.x2.shared.b16 {%0,%1}, [%2];"
                 : "=r"(r0), "=r"(r1) : "r"(addr));
}
__device__ __forceinline__ void ldmBT(unsigned addr, unsigned& r0, unsigned& r1) {
    asm volatile("ldmatrix.sync.aligned.m8n8.x2.trans.shared.b16 {%0,%1}, [%2];"
                 : "=r"(r0), "=r"(r1) : "r"(addr));
}
__device__ __forceinline__ void mma16816(float* c, unsigned a0, unsigned a1,
                                         unsigned a2, unsigned a3,
                                         unsigned b0, unsigned b1) {
    asm volatile(
        "mma.sync.aligned.m16n8k16.row.col.f32.bf16.bf16.f32 "
        "{%0,%1,%2,%3}, {%4,%5,%6,%7}, {%8,%9}, {%0,%1,%2,%3};"
        : "+f"(c[0]), "+f"(c[1]), "+f"(c[2]), "+f"(c[3])
        : "r"(a0), "r"(a1), "r"(a2), "r"(a3), "r"(b0), "r"(b1));
}

__device__ __forceinline__ unsigned bpack(__nv_bfloat16 a, __nv_bfloat16 b) {
    unsigned short ua = *(unsigned short*)&a, ub = *(unsigned short*)&b;
    return (unsigned)ua | ((unsigned)ub << 16);
}
// fp32 pair -> (hi,lo) bf16x2 packed regs.  hi = rn(x); lo = rn(x - hi).
__device__ __forceinline__ void split_pair(float x, float y, unsigned& hi, unsigned& lo) {
    __nv_bfloat16 xh = __float2bfloat16(x), yh = __float2bfloat16(y);
    float xr = x - __bfloat162float(xh), yr = y - __bfloat162float(yh);
    hi = bpack(xh, yh);
    lo = bpack(__float2bfloat16(xr), __float2bfloat16(yr));
}

// ---------------------------------------------------------------------------
// QKV projection GEMM (bf16x3): C = X @ W^T + bias, split planes out.
// X: [4096,1024] fp32 (m = t*2+b).  W: [1024,1024] fp32 [n][k].
// grid (32, 24): wsel = y>>3 (q/k/v), nblk = y&7. 256 threads, 8 warps 2x4.
// ---------------------------------------------------------------------------
__global__ __launch_bounds__(256) void gemm_qkv(
    const float* __restrict__ X,
    const float* __restrict__ wq, const float* __restrict__ wk, const float* __restrict__ wv,
    const float* __restrict__ bq, const float* __restrict__ bk, const float* __restrict__ bv)
{
    __shared__ __nv_bfloat16 Ah[128 * 40], Al[128 * 40];
    __shared__ __nv_bfloat16 Bh[128 * 40], Bl[128 * 40];

    const int wsel = blockIdx.y >> 3;
    const int n0   = (blockIdx.y & 7) * 128;
    const int m0   = blockIdx.x * 128;

    const float* W    = (wsel == 0) ? wq : (wsel == 1) ? wk : wv;
    const float* bias = (wsel == 0) ? bq : (wsel == 1) ? bk : bv;
    __nv_bfloat16* dh = (wsel == 0) ? g_qh : (wsel == 1) ? g_kh : g_vh;
    __nv_bfloat16* dl = (wsel == 0) ? g_ql : (wsel == 1) ? g_kl : g_vl;
    const float scale = (wsel == 0) ? 0.125f : 1.0f;

    const int tid = threadIdx.x, lane = tid & 31, wid = tid >> 5;
    const int wm = (wid >> 2) * 64, wn = (wid & 3) * 32;

    float acc[4][4][4];
#pragma unroll
    for (int i = 0; i < 4; i++)
#pragma unroll
        for (int j = 0; j < 4; j++)
#pragma unroll
            for (int q = 0; q < 4; q++) acc[i][j][q] = 0.f;

    const int ldr = tid >> 3;          // 0..31
    const int ldc = (tid & 7) * 4;     // 0..28

    for (int k0 = 0; k0 < 1024; k0 += 32) {
        __syncthreads();
#pragma unroll
        for (int r0 = 0; r0 < 128; r0 += 32) {
            int row = r0 + ldr;
            float4 a = *(const float4*)(X + (size_t)(m0 + row) * 1024 + k0 + ldc);
            unsigned h0, l0, h1, l1;
            split_pair(a.x, a.y, h0, l0); split_pair(a.z, a.w, h1, l1);
            *(unsigned*)&Ah[row * 40 + ldc] = h0; *(unsigned*)&Ah[row * 40 + ldc + 2] = h1;
            *(unsigned*)&Al[row * 40 + ldc] = l0; *(unsigned*)&Al[row * 40 + ldc + 2] = l1;
            float4 b = *(const float4*)(W + (size_t)(n0 + row) * 1024 + k0 + ldc);
            split_pair(b.x, b.y, h0, l0); split_pair(b.z, b.w, h1, l1);
            *(unsigned*)&Bh[row * 40 + ldc] = h0; *(unsigned*)&Bh[row * 40 + ldc + 2] = h1;
            *(unsigned*)&Bl[row * 40 + ldc] = l0; *(unsigned*)&Bl[row * 40 + ldc + 2] = l1;
        }
        __syncthreads();

#pragma unroll
        for (int kf = 0; kf < 2; kf++) {
            unsigned ah[4][4], al[4][4];
#pragma unroll
            for (int i = 0; i < 4; i++) {
                int aoff = (wm + i * 16 + (lane & 15)) * 40 + kf * 16 + (lane >> 4) * 8;
                ldmA(smem_u32(&Ah[aoff]), ah[i][0], ah[i][1], ah[i][2], ah[i][3]);
                ldmA(smem_u32(&Al[aoff]), al[i][0], al[i][1], al[i][2], al[i][3]);
            }
#pragma unroll
            for (int j = 0; j < 4; j++) {
                int boff = (wn + j * 8 + (lane & 7)) * 40 + kf * 16 + ((lane >> 3) & 1) * 8;
                unsigned bh0, bh1, bl0, bl1;
                ldmB(smem_u32(&Bh[boff]), bh0, bh1);
                ldmB(smem_u32(&Bl[boff]), bl0, bl1);
#pragma unroll
                for (int i = 0; i < 4; i++) {
                    mma16816(acc[i][j], ah[i][0], ah[i][1], ah[i][2], ah[i][3], bh0, bh1);
                    mma16816(acc[i][j], ah[i][0], ah[i][1], ah[i][2], ah[i][3], bl0, bl1);
                    mma16816(acc[i][j], al[i][0], al[i][1], al[i][2], al[i][3], bh0, bh1);
                }
            }
        }
    }

    // epilogue: bias, scale, split, scatter into head-major planes
#pragma unroll
    for (int i = 0; i < 4; i++) {
#pragma unroll
        for (int j = 0; j < 4; j++) {
            int col = n0 + wn + j * 8 + (lane & 3) * 2;
            float b0 = bias[col], b1 = bias[col + 1];
            int h = col >> 6, d = col & 63;
#pragma unroll
            for (int half = 0; half < 2; half++) {
                int r = m0 + wm + i * 16 + (lane >> 2) + half * 8;
                float v0 = (acc[i][j][2 * half + 0] + b0) * scale;
                float v1 = (acc[i][j][2 * half + 1] + b1) * scale;
                unsigned hi, lo;
                split_pair(v0, v1, hi, lo);
                size_t off = (size_t)((r & 1) * 16 + h) * HD + (size_t)(r >> 1) * 64 + d;
                *(unsigned*)&dh[off] = hi;
                *(unsigned*)&dl[off] = lo;
            }
        }
    }
}

// ---------------------------------------------------------------------------
// Attention score tile: acc[16][4] = Q(warp rows 16) @ K^T(128) via bf16x3 MMA
// ---------------------------------------------------------------------------
__device__ __forceinline__ void compute_scores(
    const __nv_bfloat16* Qh, const __nv_bfloat16* Ql,
    const __nv_bfloat16* Kh, const __nv_bfloat16* Kl,
    int wr, int lane, float acc[16][4])
{
#pragma unroll
    for (int j = 0; j < 16; j++)
#pragma unroll
        for (int q = 0; q < 4; q++) acc[j][q] = 0.f;

#pragma unroll
    for (int kf = 0; kf < 4; kf++) {
        unsigned ah[4], al[4];
        int qoff = (wr + (lane & 15)) * 72 + kf * 16 + (lane >> 4) * 8;
        ldmA(smem_u32(&Qh[qoff]), ah[0], ah[1], ah[2], ah[3]);
        ldmA(smem_u32(&Ql[qoff]), al[0], al[1], al[2], al[3]);
#pragma unroll
        for (int j = 0; j < 16; j++) {
            int koff = (j * 8 + (lane & 7)) * 72 + kf * 16 + ((lane >> 3) & 1) * 8;
            unsigned bh0, bh1, bl0, bl1;
            ldmB(smem_u32(&Kh[koff]), bh0, bh1);
            ldmB(smem_u32(&Kl[koff]), bl0, bl1);
            mma16816(acc[j], ah[0], ah[1], ah[2], ah[3], bh0, bh1);
            mma16816(acc[j], ah[0], ah[1], ah[2], ah[3], bl0, bl1);
            mma16816(acc[j], al[0], al[1], al[2], al[3], bh0, bh1);
        }
    }
}

// ---------------------------------------------------------------------------
// Attention: per (head n, 128-row q-block). Two-pass exact softmax, all MMA.
// grid (16, 32), 256 threads (8 warps x 16 rows), 110,592 B dyn smem.
// ---------------------------------------------------------------------------
__global__ __launch_bounds__(256) void attn_kernel(float* __restrict__ w_out)
{
    extern __shared__ __nv_bfloat16 sm[];
    __nv_bfloat16* Qh = sm;
    __nv_bfloat16* Ql = Qh + 128 * 72;
    __nv_bfloat16* Kh = Ql + 128 * 72;
    __nv_bfloat16* Kl = Kh + 128 * 72;
    __nv_bfloat16* Vh = Kl + 128 * 72;
    __nv_bfloat16* Vl = Vh + 128 * 72;

    const int n   = blockIdx.y;
    const int qb  = blockIdx.x * 128;
    const int tid = threadIdx.x, lane = tid & 31, wid = tid >> 5;
    const int wr  = wid * 16;

    const __nv_bfloat16* qhg = g_qh + (size_t)n * HD + (size_t)qb * 64;
    const __nv_bfloat16* qlg = g_ql + (size_t)n * HD + (size_t)qb * 64;
    const __nv_bfloat16* khg = g_kh + (size_t)n * HD;
    const __nv_bfloat16* klg = g_kl + (size_t)n * HD;
    const __nv_bfloat16* vhg = g_vh + (size_t)n * HD;
    const __nv_bfloat16* vlg = g_vl + (size_t)n * HD;

    // load Q tile (hi/lo) once
    for (int idx = tid; idx < 128 * 8; idx += 256) {
        int row = idx >> 3, c = (idx & 7) * 8;
        *(uint4*)&Qh[row * 72 + c] = *(const uint4*)(qhg + (size_t)row * 64 + c);
        *(uint4*)&Ql[row * 72 + c] = *(const uint4*)(qlg + (size_t)row * 64 + c);
    }

    float mv[2] = {-1e30f, -1e30f}, lv[2] = {0.f, 0.f};

    // ---------------- pass 1: softmax statistics ----------------
    for (int sc = 0; sc < 16; sc++) {
        __syncthreads();
        for (int idx = tid; idx < 128 * 8; idx += 256) {
            int row = idx >> 3, c = (idx & 7) * 8;
            size_t g = (size_t)(sc * 128 + row) * 64 + c;
            *(uint4*)&Kh[row * 72 + c] = *(const uint4*)(khg + g);
            *(uint4*)&Kl[row * 72 + c] = *(const uint4*)(klg + g);
        }
        __syncthreads();

        float acc[16][4];
        compute_scores(Qh, Ql, Kh, Kl, wr, lane, acc);

#pragma unroll
        for (int half = 0; half < 2; half++) {
            float mx = -1e30f;
#pragma unroll
            for (int j = 0; j < 16; j++)
                mx = fmaxf(mx, fmaxf(acc[j][2 * half], acc[j][2 * half + 1]));
            mx = fmaxf(mx, __shfl_xor_sync(0xffffffffu, mx, 1));
            mx = fmaxf(mx, __shfl_xor_sync(0xffffffffu, mx, 2));
            float mn = fmaxf(mv[half], mx);
            float s = 0.f;
#pragma unroll
            for (int j = 0; j < 16; j++)
                s += __expf(acc[j][2 * half] - mn) + __expf(acc[j][2 * half + 1] - mn);
            s += __shfl_xor_sync(0xffffffffu, s, 1);
            s += __shfl_xor_sync(0xffffffffu, s, 2);
            lv[half] = lv[half] * __expf(mv[half] - mn) + s;
            mv[half] = mn;
        }
    }

    const float invl0 = 1.0f / lv[0], invl1 = 1.0f / lv[1];

    float o[8][4];
#pragma unroll
    for (int j = 0; j < 8; j++)
#pragma unroll
        for (int q = 0; q < 4; q++) o[j][q] = 0.f;

    // ---------------- pass 2: weights out + P@V ----------------
    for (int sc = 0; sc < 16; sc++) {
        __syncthreads();
        for (int idx = tid; idx < 128 * 8; idx += 256) {
            int row = idx >> 3, c = (idx & 7) * 8;
            size_t g = (size_t)(sc * 128 + row) * 64 + c;
            *(uint4*)&Kh[row * 72 + c] = *(const uint4*)(khg + g);
            *(uint4*)&Kl[row * 72 + c] = *(const uint4*)(klg + g);
            *(uint4*)&Vh[row * 72 + c] = *(const uint4*)(vhg + g);
            *(uint4*)&Vl[row * 72 + c] = *(const uint4*)(vlg + g);
        }
        __syncthreads();

        float acc[16][4];
        compute_scores(Qh, Ql, Kh, Kl, wr, lane, acc);

        // normalized probabilities -> gmem (single write) + keep in regs for PV
        float* wb = w_out + (size_t)n * ((size_t)T_DIM * T_DIM)
                  + (size_t)(qb + wr + (lane >> 2)) * T_DIM + sc * 128 + (lane & 3) * 2;
#pragma unroll
        for (int j = 0; j < 16; j++) {
            float p0 = __expf(acc[j][0] - mv[0]) * invl0;
            float p1 = __expf(acc[j][1] - mv[0]) * invl0;
            float p2 = __expf(acc[j][2] - mv[1]) * invl1;
            float p3 = __expf(acc[j][3] - mv[1]) * invl1;
            acc[j][0] = p0; acc[j][1] = p1; acc[j][2] = p2; acc[j][3] = p3;
            float2 w0 = {p0, p1}, w1 = {p2, p3};
            *(float2*)(wb + j * 8) = w0;
            *(float2*)(wb + 8 * (size_t)T_DIM + j * 8) = w1;
        }

        // PV: C-frag layout of p == A-frag layout for m16n8k16 -> feed back
#pragma unroll
        for (int g = 0; g < 8; g++) {
            unsigned a0h, a0l, a1h, a1l, a2h, a2l, a3h, a3l;
            split_pair(acc[2 * g][0],     acc[2 * g][1],     a0h, a0l);
            split_pair(acc[2 * g][2],     acc[2 * g][3],     a1h, a1l);
            split_pair(acc[2 * g + 1][0], acc[2 * g + 1][1], a2h, a2l);
            split_pair(acc[2 * g + 1][2], acc[2 * g + 1][3], a3h, a3l);
#pragma unroll
            for (int j = 0; j < 8; j++) {
                int voff = (g * 16 + (lane & 15)) * 72 + j * 8;
                unsigned bh0, bh1, bl0, bl1;
                ldmBT(smem_u32(&Vh[voff]), bh0, bh1);
                ldmBT(smem_u32(&Vl[voff]), bl0, bl1);
                mma16816(o[j], a0h, a1h, a2h, a3h, bh0, bh1);
                mma16816(o[j], a0h, a1h, a2h, a3h, bl0, bl1);
                mma16816(o[j], a0l, a1l, a2l, a3l, bh0, bh1);
            }
        }
    }

    // epilogue: split attn result into planes at [m = t*2+b][e = h*64+d]
    const int bsel = n >> 4, h = n & 15;
    const int t0   = qb + wr + (lane >> 2);
    const int dcol = (lane & 3) * 2;
#pragma unroll
    for (int j = 0; j < 8; j++) {
        int d = j * 8 + dcol;
        unsigned hi, lo;
        split_pair(o[j][0], o[j][1], hi, lo);
        size_t off = (size_t)(t0 * 2 + bsel) * E_DIM + h * 64 + d;
        *(unsigned*)&g_ah[off] = hi; *(unsigned*)&g_al[off] = lo;
        split_pair(o[j][2], o[j][3], hi, lo);
        off = (size_t)((t0 + 8) * 2 + bsel) * E_DIM + h * 64 + d;
        *(unsigned*)&g_ah[off] = hi; *(unsigned*)&g_al[off] = lo;
    }
}

// ---------------------------------------------------------------------------
// Output projection (bf16x3): out = attnx @ wo^T + bo. grid (32, 8).
// A planes already bf16 in gmem; B (wo) split in smem stage.
// ---------------------------------------------------------------------------
__global__ __launch_bounds__(256) void gemm_out(
    const float* __restrict__ wo, const float* __restrict__ bo, float* __restrict__ out)
{
    __shared__ __nv_bfloat16 Ah[128 * 40], Al[128 * 40];
    __shared__ __nv_bfloat16 Bh[128 * 40], Bl[128 * 40];

    const int n0 = blockIdx.y * 128;
    const int m0 = blockIdx.x * 128;

    const int tid = threadIdx.x, lane = tid & 31, wid = tid >> 5;
    const int wm = (wid >> 2) * 64, wn = (wid & 3) * 32;

    float acc[4][4][4];
#pragma unroll
    for (int i = 0; i < 4; i++)
#pragma unroll
        for (int j = 0; j < 4; j++)
#pragma unroll
            for (int q = 0; q < 4; q++) acc[i][j][q] = 0.f;

    const int ldr = tid >> 3, ldc = (tid & 7) * 4;   // fp32 B loads
    const int ar  = tid >> 2, ac  = (tid & 3) * 8;   // bf16 A loads

    for (int k0 = 0; k0 < 1024; k0 += 32) {
        __syncthreads();
#pragma unroll
        for (int r0 = 0; r0 < 128; r0 += 64) {
            int row = r0 + ar;
            *(uint4*)&Ah[row * 40 + ac] =
                *(const uint4*)(g_ah + (size_t)(m0 + row) * 1024 + k0 + ac);
            *(uint4*)&Al[row * 40 + ac] =
                *(const uint4*)(g_al + (size_t)(m0 + row) * 1024 + k0 + ac);
        }
#pragma unroll
        for (int r0 = 0; r0 < 128; r0 += 32) {
            int row = r0 + ldr;
            float4 b = *(const float4*)(wo + (size_t)(n0 + row) * 1024 + k0 + ldc);
            unsigned h0, l0, h1, l1;
            split_pair(b.x, b.y, h0, l0); split_pair(b.z, b.w, h1, l1);
            *(unsigned*)&Bh[row * 40 + ldc] = h0; *(unsigned*)&Bh[row * 40 + ldc + 2] = h1;
            *(unsigned*)&Bl[row * 40 + ldc] = l0; *(unsigned*)&Bl[row * 40 + ldc + 2] = l1;
        }
        __syncthreads();

#pragma unroll
        for (int kf = 0; kf < 2; kf++) {
            unsigned ah[4][4], al[4][4];
#pragma unroll
            for (int i = 0; i < 4; i++) {
                int aoff = (wm + i * 16 + (lane & 15)) * 40 + kf * 16 + (lane >> 4) * 8;
                ldmA(smem_u32(&Ah[aoff]), ah[i][0], ah[i][1], ah[i][2], ah[i][3]);
                ldmA(smem_u32(&Al[aoff]), al[i][0], al[i][1], al[i][2], al[i][3]);
            }
#pragma unroll
            for (int j = 0; j < 4; j++) {
                int boff = (wn + j * 8 + (lane & 7)) * 40 + kf * 16 + ((lane >> 3) & 1) * 8;
                unsigned bh0, bh1, bl0, bl1;
                ldmB(smem_u32(&Bh[boff]), bh0, bh1);
                ldmB(smem_u32(&Bl[boff]), bl0, bl1);
#pragma unroll
                for (int i = 0; i < 4; i++) {
                    mma16816(acc[i][j], ah[i][0], ah[i][1], ah[i][2], ah[i][3], bh0, bh1);
                    mma16816(acc[i][j], ah[i][0], ah[i][1], ah[i][2], ah[i][3], bl0, bl1);
                    mma16816(acc[i][j], al[i][0], al[i][1], al[i][2], al[i][3], bh0, bh1);
                }
            }
        }
    }

#pragma unroll
    for (int i = 0; i < 4; i++) {
#pragma unroll
        for (int j = 0; j < 4; j++) {
            int col = n0 + wn + j * 8 + (lane & 3) * 2;
            float b0 = bo[col], b1 = bo[col + 1];
#pragma unroll
            for (int half = 0; half < 2; half++) {
                int r = m0 + wm + i * 16 + (lane >> 2) + half * 8;
                float2 v;
                v.x = acc[i][j][2 * half + 0] + b0;
                v.y = acc[i][j][2 * half + 1] + b1;
                *(float2*)(out + (size_t)r * 1024 + col) = v;
            }
        }
    }
}

// ---------------------------------------------------------------------------
// d_out = [ out (4096*1024 fp32) | attn_weights (32*2048*2048 fp32) ]
// ---------------------------------------------------------------------------
extern "C" void kernel_launch(void* const* d_in, const int* in_sizes, int n_in,
                              void* d_out, int out_size)
{
    const float* query = (const float*)d_in[0];
    const float* wq    = (const float*)d_in[1];
    const float* bq    = (const float*)d_in[2];
    const float* wk    = (const float*)d_in[3];
    const float* bk    = (const float*)d_in[4];
    const float* wv    = (const float*)d_in[5];
    const float* bv    = (const float*)d_in[6];
    const float* wo    = (const float*)d_in[7];
    const float* bo    = (const float*)d_in[8];

    float* out   = (float*)d_out;
    float* w_out = out + (size_t)M_DIM * E_DIM;

    const int attn_smem = 6 * 128 * 72 * (int)sizeof(__nv_bfloat16);  // 110,592 B
    cudaFuncSetAttribute(attn_kernel, cudaFuncAttributeMaxDynamicSharedMemorySize, attn_smem);

    gemm_qkv<<<dim3(32, 24), 256>>>(query, wq, wk, wv, bq, bk, bv);
    attn_kernel<<<dim3(16, 32), 256, attn_smem>>>(w_out);
    gemm_out<<<dim3(32, 8), 256>>>(wo, bo, out);
}

// round 6
// speedup vs baseline: 2.6526x; 1.3587x over previous
#include <cuda_runtime.h>
#include <cuda_bf16.h>

// T=2048, B=2, E=1024, H=16, D=64
#define T_DIM 2048
#define E_DIM 1024
#define NH    32            // B*H
#define M_DIM 4096          // T*B
#define HD    (T_DIM * 64)  // per-head plane elems

// ---------------------------------------------------------------------------
// Device-global scratch (no allocation allowed): bf16 hi/lo split planes.
// ---------------------------------------------------------------------------
__device__ __nv_bfloat16 g_xh[(size_t)M_DIM * E_DIM], g_xl[(size_t)M_DIM * E_DIM];
__device__ __nv_bfloat16 g_wqh[1024 * 1024], g_wql[1024 * 1024];
__device__ __nv_bfloat16 g_wkh[1024 * 1024], g_wkl[1024 * 1024];
__device__ __nv_bfloat16 g_wvh[1024 * 1024], g_wvl[1024 * 1024];
__device__ __nv_bfloat16 g_woh[1024 * 1024], g_wol[1024 * 1024];
// q/k/v planes: [n = b*16 + h][t][d]
__device__ __nv_bfloat16 g_qh[(size_t)NH * HD], g_ql[(size_t)NH * HD];
__device__ __nv_bfloat16 g_kh[(size_t)NH * HD], g_kl[(size_t)NH * HD];
__device__ __nv_bfloat16 g_vh[(size_t)NH * HD], g_vl[(size_t)NH * HD];
// attn result planes: [m = t*2+b][e = h*64+d]
__device__ __nv_bfloat16 g_ah[(size_t)M_DIM * E_DIM], g_al[(size_t)M_DIM * E_DIM];

// ---------------------------------------------------------------------------
// Helpers
// ---------------------------------------------------------------------------
__device__ __forceinline__ unsigned smem_u32(const void* p) {
    return (unsigned)__cvta_generic_to_shared(p);
}
__device__ __forceinline__ void cp16(unsigned dst, const void* src) {
    asm volatile("cp.async.cg.shared.global [%0], [%1], 16;" :: "r"(dst), "l"(src));
}
__device__ __forceinline__ void cp_commit() {
    asm volatile("cp.async.commit_group;");
}
template <int N> __device__ __forceinline__ void cp_wait() {
    asm volatile("cp.async.wait_group %0;" :: "n"(N));
}
__device__ __forceinline__ void ldmA(unsigned addr, unsigned& r0, unsigned& r1,
                                     unsigned& r2, unsigned& r3) {
    asm volatile("ldmatrix.sync.aligned.m8n8.x4.shared.b16 {%0,%1,%2,%3}, [%4];"
                 : "=r"(r0), "=r"(r1), "=r"(r2), "=r"(r3) : "r"(addr));
}
__device__ __forceinline__ void ldmB(unsigned addr, unsigned& r0, unsigned& r1) {
    asm volatile("ldmatrix.sync.aligned.m8n8.x2.shared.b16 {%0,%1}, [%2];"
                 : "=r"(r0), "=r"(r1) : "r"(addr));
}
__device__ __forceinline__ void ldmBT(unsigned addr, unsigned& r0, unsigned& r1) {
    asm volatile("ldmatrix.sync.aligned.m8n8.x2.trans.shared.b16 {%0,%1}, [%2];"
                 : "=r"(r0), "=r"(r1) : "r"(addr));
}
__device__ __forceinline__ void mma16816(float* c, unsigned a0, unsigned a1,
                                         unsigned a2, unsigned a3,
                                         unsigned b0, unsigned b1) {
    asm volatile(
        "mma.sync.aligned.m16n8k16.row.col.f32.bf16.bf16.f32 "
        "{%0,%1,%2,%3}, {%4,%5,%6,%7}, {%8,%9}, {%0,%1,%2,%3};"
        : "+f"(c[0]), "+f"(c[1]), "+f"(c[2]), "+f"(c[3])
        : "r"(a0), "r"(a1), "r"(a2), "r"(a3), "r"(b0), "r"(b1));
}
__device__ __forceinline__ unsigned bpack(__nv_bfloat16 a, __nv_bfloat16 b) {
    unsigned short ua = *(unsigned short*)&a, ub = *(unsigned short*)&b;
    return (unsigned)ua | ((unsigned)ub << 16);
}
__device__ __forceinline__ void split_pair(float x, float y, unsigned& hi, unsigned& lo) {
    __nv_bfloat16 xh = __float2bfloat16(x), yh = __float2bfloat16(y);
    float xr = x - __bfloat162float(xh), yr = y - __bfloat162float(yh);
    hi = bpack(xh, yh);
    lo = bpack(__float2bfloat16(xr), __float2bfloat16(yr));
}

// ---------------------------------------------------------------------------
// Split all fp32 inputs into bf16 hi/lo planes (one pass).
// grid covers 2,097,152 float4 = X (1M) + 4 weights (256K each).
// ---------------------------------------------------------------------------
__global__ __launch_bounds__(256) void split_all(
    const float* __restrict__ X, const float* __restrict__ wq,
    const float* __restrict__ wk, const float* __restrict__ wv,
    const float* __restrict__ wo)
{
    size_t i = (size_t)blockIdx.x * 256 + threadIdx.x;
    const float* src; __nv_bfloat16 *dh, *dl; size_t off;
    if (i < 1048576) { src = X; dh = g_xh; dl = g_xl; off = i; }
    else {
        size_t j = i - 1048576;
        int w = (int)(j >> 18);
        off = j & 262143;
        if      (w == 0) { src = wq; dh = g_wqh; dl = g_wql; }
        else if (w == 1) { src = wk; dh = g_wkh; dl = g_wkl; }
        else if (w == 2) { src = wv; dh = g_wvh; dl = g_wvl; }
        else             { src = wo; dh = g_woh; dl = g_wol; }
    }
    float4 v = ((const float4*)src)[off];
    unsigned h0, l0, h1, l1;
    split_pair(v.x, v.y, h0, l0); split_pair(v.z, v.w, h1, l1);
    ((unsigned*)dh)[off * 2] = h0; ((unsigned*)dh)[off * 2 + 1] = h1;
    ((unsigned*)dl)[off * 2] = l0; ((unsigned*)dl)[off * 2 + 1] = l1;
}

// ---------------------------------------------------------------------------
// GEMM tile constants (shared by qkv / out projections)
// ---------------------------------------------------------------------------
#define GSTR  40
#define GPL   (128 * GSTR)   // one plane: 5120 elems
#define GSTG  (4 * GPL)      // one stage: Ah,Al,Bh,Bl

// ---------------------------------------------------------------------------
// QKV projection GEMM (bf16x3, cp.async double-buffered).
// grid (32, 24): wsel = y>>3, nblk = y&7. 256 thr, 8 warps 2x4.
// ---------------------------------------------------------------------------
__global__ __launch_bounds__(256) void gemm_qkv(
    const float* __restrict__ bq, const float* __restrict__ bk, const float* __restrict__ bv)
{
    extern __shared__ __nv_bfloat16 sb[];

    const int wsel = blockIdx.y >> 3;
    const int n0   = (blockIdx.y & 7) * 128;
    const int m0   = blockIdx.x * 128;

    const __nv_bfloat16* Wh = (wsel == 0) ? g_wqh : (wsel == 1) ? g_wkh : g_wvh;
    const __nv_bfloat16* Wl = (wsel == 0) ? g_wql : (wsel == 1) ? g_wkl : g_wvl;
    const float* bias = (wsel == 0) ? bq : (wsel == 1) ? bk : bv;
    __nv_bfloat16* dh = (wsel == 0) ? g_qh : (wsel == 1) ? g_kh : g_vh;
    __nv_bfloat16* dl = (wsel == 0) ? g_ql : (wsel == 1) ? g_kl : g_vl;
    const float scale = (wsel == 0) ? 0.125f : 1.0f;

    const int tid = threadIdx.x, lane = tid & 31, wid = tid >> 5;
    const int wm = (wid >> 2) * 64, wn = (wid & 3) * 32;
    const int lr = tid >> 2;           // 0..63
    const int lc = (tid & 3) * 8;      // 16B chunk col (elems)

    float acc[4][4][4];
#pragma unroll
    for (int i = 0; i < 4; i++)
#pragma unroll
        for (int j = 0; j < 4; j++)
#pragma unroll
            for (int q = 0; q < 4; q++) acc[i][j][q] = 0.f;

    auto load_stage = [&](int s, int k0) {
        __nv_bfloat16* base = sb + s * GSTG;
#pragma unroll
        for (int rr = 0; rr < 128; rr += 64) {
            int row = rr + lr;
            size_t ga = (size_t)(m0 + row) * 1024 + k0 + lc;
            size_t gb = (size_t)(n0 + row) * 1024 + k0 + lc;
            unsigned d = smem_u32(base + row * GSTR + lc);
            cp16(d,               g_xh + ga);
            cp16(d + GPL * 2,     g_xl + ga);   // bytes: GPL elems * 2
            cp16(d + GPL * 4,     Wh + gb);
            cp16(d + GPL * 6,     Wl + gb);
        }
    };

    load_stage(0, 0); cp_commit();

    for (int kt = 0; kt < 32; kt++) {
        const int buf = kt & 1;
        if (kt < 31) { load_stage(buf ^ 1, (kt + 1) * 32); cp_commit(); cp_wait<1>(); }
        else         { cp_wait<0>(); }
        __syncthreads();

        const __nv_bfloat16* Ah = sb + buf * GSTG;
        const __nv_bfloat16* Al = Ah + GPL;
        const __nv_bfloat16* Bh = Al + GPL;
        const __nv_bfloat16* Bl = Bh + GPL;

#pragma unroll
        for (int kf = 0; kf < 2; kf++) {
            unsigned ah[4][4], al[4][4];
#pragma unroll
            for (int i = 0; i < 4; i++) {
                int aoff = (wm + i * 16 + (lane & 15)) * GSTR + kf * 16 + (lane >> 4) * 8;
                ldmA(smem_u32(&Ah[aoff]), ah[i][0], ah[i][1], ah[i][2], ah[i][3]);
                ldmA(smem_u32(&Al[aoff]), al[i][0], al[i][1], al[i][2], al[i][3]);
            }
#pragma unroll
            for (int j = 0; j < 4; j++) {
                int boff = (wn + j * 8 + (lane & 7)) * GSTR + kf * 16 + ((lane >> 3) & 1) * 8;
                unsigned bh0, bh1, bl0, bl1;
                ldmB(smem_u32(&Bh[boff]), bh0, bh1);
                ldmB(smem_u32(&Bl[boff]), bl0, bl1);
#pragma unroll
                for (int i = 0; i < 4; i++) {
                    mma16816(acc[i][j], ah[i][0], ah[i][1], ah[i][2], ah[i][3], bh0, bh1);
                    mma16816(acc[i][j], ah[i][0], ah[i][1], ah[i][2], ah[i][3], bl0, bl1);
                    mma16816(acc[i][j], al[i][0], al[i][1], al[i][2], al[i][3], bh0, bh1);
                }
            }
        }
        __syncthreads();
    }

    // epilogue: bias, scale, split, scatter into head-major planes
#pragma unroll
    for (int i = 0; i < 4; i++) {
#pragma unroll
        for (int j = 0; j < 4; j++) {
            int col = n0 + wn + j * 8 + (lane & 3) * 2;
            float b0 = bias[col], b1 = bias[col + 1];
            int h = col >> 6, d = col & 63;
#pragma unroll
            for (int half = 0; half < 2; half++) {
                int r = m0 + wm + i * 16 + (lane >> 2) + half * 8;
                float v0 = (acc[i][j][2 * half + 0] + b0) * scale;
                float v1 = (acc[i][j][2 * half + 1] + b1) * scale;
                unsigned hi, lo;
                split_pair(v0, v1, hi, lo);
                size_t off = (size_t)((r & 1) * 16 + h) * HD + (size_t)(r >> 1) * 64 + d;
                *(unsigned*)&dh[off] = hi;
                *(unsigned*)&dl[off] = lo;
            }
        }
    }
}

// ---------------------------------------------------------------------------
// Attention score tile: acc[16][4] = Q(16 rows) @ K^T(128) via bf16x3 MMA
// ---------------------------------------------------------------------------
#define ASTR 72
#define APL  (128 * ASTR)    // 9216 elems

__device__ __forceinline__ void compute_scores(
    const __nv_bfloat16* Qh, const __nv_bfloat16* Ql,
    const __nv_bfloat16* Kh, const __nv_bfloat16* Kl,
    int wr, int lane, float acc[16][4])
{
#pragma unroll
    for (int j = 0; j < 16; j++)
#pragma unroll
        for (int q = 0; q < 4; q++) acc[j][q] = 0.f;

#pragma unroll
    for (int kf = 0; kf < 4; kf++) {
        unsigned ah[4], al[4];
        int qoff = (wr + (lane & 15)) * ASTR + kf * 16 + (lane >> 4) * 8;
        ldmA(smem_u32(&Qh[qoff]), ah[0], ah[1], ah[2], ah[3]);
        ldmA(smem_u32(&Ql[qoff]), al[0], al[1], al[2], al[3]);
#pragma unroll
        for (int j = 0; j < 16; j++) {
            int koff = (j * 8 + (lane & 7)) * ASTR + kf * 16 + ((lane >> 3) & 1) * 8;
            unsigned bh0, bh1, bl0, bl1;
            ldmB(smem_u32(&Kh[koff]), bh0, bh1);
            ldmB(smem_u32(&Kl[koff]), bl0, bl1);
            mma16816(acc[j], ah[0], ah[1], ah[2], ah[3], bh0, bh1);
            mma16816(acc[j], ah[0], ah[1], ah[2], ah[3], bl0, bl1);
            mma16816(acc[j], al[0], al[1], al[2], al[3], bh0, bh1);
        }
    }
}

// ---------------------------------------------------------------------------
// Attention: per (head n, 128-row q-block). Two-pass exact softmax.
// cp.async double-buffered K (pass 1) and K+V (pass 2) tiles.
// grid (16, 32), 256 threads, 184,320 B dyn smem.
// ---------------------------------------------------------------------------
__global__ __launch_bounds__(256) void attn_kernel(float* __restrict__ w_out)
{
    extern __shared__ __nv_bfloat16 sm[];
    __nv_bfloat16* Qh = sm;
    __nv_bfloat16* Ql = sm + APL;
    // stage s base: sm + 2*APL + s*4*APL; planes within: Kh, Kl, Vh, Vl

    const int n   = blockIdx.y;
    const int qb  = blockIdx.x * 128;
    const int tid = threadIdx.x, lane = tid & 31, wid = tid >> 5;
    const int wr  = wid * 16;

    const __nv_bfloat16* qhg = g_qh + (size_t)n * HD + (size_t)qb * 64;
    const __nv_bfloat16* qlg = g_ql + (size_t)n * HD + (size_t)qb * 64;
    const __nv_bfloat16* khg = g_kh + (size_t)n * HD;
    const __nv_bfloat16* klg = g_kl + (size_t)n * HD;
    const __nv_bfloat16* vhg = g_vh + (size_t)n * HD;
    const __nv_bfloat16* vlg = g_vl + (size_t)n * HD;

    // Q tile once (plain vector loads)
    for (int idx = tid; idx < 128 * 8; idx += 256) {
        int row = idx >> 3, c = (idx & 7) * 8;
        *(uint4*)&Qh[row * ASTR + c] = *(const uint4*)(qhg + (size_t)row * 64 + c);
        *(uint4*)&Ql[row * ASTR + c] = *(const uint4*)(qlg + (size_t)row * 64 + c);
    }

    const int ar = tid >> 3, ac = (tid & 7) * 8;

    auto load_k = [&](int s, int sc) {
        __nv_bfloat16* kh = sm + 2 * APL + s * 4 * APL;
#pragma unroll
        for (int rr = 0; rr < 128; rr += 32) {
            int row = rr + ar;
            size_t g = (size_t)(sc * 128 + row) * 64 + ac;
            unsigned d = smem_u32(&kh[row * ASTR + ac]);
            cp16(d,               khg + g);
            cp16(d + APL * 2,     klg + g);
        }
    };
    auto load_kv = [&](int s, int sc) {
        __nv_bfloat16* kh = sm + 2 * APL + s * 4 * APL;
#pragma unroll
        for (int rr = 0; rr < 128; rr += 32) {
            int row = rr + ar;
            size_t g = (size_t)(sc * 128 + row) * 64 + ac;
            unsigned d = smem_u32(&kh[row * ASTR + ac]);
            cp16(d,               khg + g);
            cp16(d + APL * 2,     klg + g);
            cp16(d + APL * 4,     vhg + g);
            cp16(d + APL * 6,     vlg + g);
        }
    };

    float mv[2] = {-1e30f, -1e30f}, lv[2] = {0.f, 0.f};

    // ---------------- pass 1: softmax statistics ----------------
    load_k(0, 0); cp_commit();
    for (int sc = 0; sc < 16; sc++) {
        const int buf = sc & 1;
        if (sc < 15) { load_k(buf ^ 1, sc + 1); cp_commit(); cp_wait<1>(); }
        else         { cp_wait<0>(); }
        __syncthreads();

        const __nv_bfloat16* Kh = sm + 2 * APL + buf * 4 * APL;
        const __nv_bfloat16* Kl = Kh + APL;

        float acc[16][4];
        compute_scores(Qh, Ql, Kh, Kl, wr, lane, acc);
        __syncthreads();  // done reading this stage's smem

#pragma unroll
        for (int half = 0; half < 2; half++) {
            float mx = -1e30f;
#pragma unroll
            for (int j = 0; j < 16; j++)
                mx = fmaxf(mx, fmaxf(acc[j][2 * half], acc[j][2 * half + 1]));
            mx = fmaxf(mx, __shfl_xor_sync(0xffffffffu, mx, 1));
            mx = fmaxf(mx, __shfl_xor_sync(0xffffffffu, mx, 2));
            float mn = fmaxf(mv[half], mx);
            float s = 0.f;
#pragma unroll
            for (int j = 0; j < 16; j++)
                s += __expf(acc[j][2 * half] - mn) + __expf(acc[j][2 * half + 1] - mn);
            s += __shfl_xor_sync(0xffffffffu, s, 1);
            s += __shfl_xor_sync(0xffffffffu, s, 2);
            lv[half] = lv[half] * __expf(mv[half] - mn) + s;
            mv[half] = mn;
        }
    }

    const float invl0 = 1.0f / lv[0], invl1 = 1.0f / lv[1];

    float o[8][4];
#pragma unroll
    for (int j = 0; j < 8; j++)
#pragma unroll
        for (int q = 0; q < 4; q++) o[j][q] = 0.f;

    // ---------------- pass 2: weights out + P@V ----------------
    load_kv(0, 0); cp_commit();
    for (int sc = 0; sc < 16; sc++) {
        const int buf = sc & 1;
        if (sc < 15) { load_kv(buf ^ 1, sc + 1); cp_commit(); cp_wait<1>(); }
        else         { cp_wait<0>(); }
        __syncthreads();

        const __nv_bfloat16* Kh = sm + 2 * APL + buf * 4 * APL;
        const __nv_bfloat16* Kl = Kh + APL;
        const __nv_bfloat16* Vh = Kl + APL;
        const __nv_bfloat16* Vl = Vh + APL;

        float acc[16][4];
        compute_scores(Qh, Ql, Kh, Kl, wr, lane, acc);

        // normalized probabilities -> gmem + registers (C-frag == A-frag layout)
        float* wb = w_out + (size_t)n * ((size_t)T_DIM * T_DIM)
                  + (size_t)(qb + wr + (lane >> 2)) * T_DIM + sc * 128 + (lane & 3) * 2;
#pragma unroll
        for (int j = 0; j < 16; j++) {
            float p0 = __expf(acc[j][0] - mv[0]) * invl0;
            float p1 = __expf(acc[j][1] - mv[0]) * invl0;
            float p2 = __expf(acc[j][2] - mv[1]) * invl1;
            float p3 = __expf(acc[j][3] - mv[1]) * invl1;
            acc[j][0] = p0; acc[j][1] = p1; acc[j][2] = p2; acc[j][3] = p3;
            float2 w0 = {p0, p1}, w1 = {p2, p3};
            *(float2*)(wb + j * 8) = w0;
            *(float2*)(wb + 8 * (size_t)T_DIM + j * 8) = w1;
        }

        // PV accumulate
#pragma unroll
        for (int g = 0; g < 8; g++) {
            unsigned a0h, a0l, a1h, a1l, a2h, a2l, a3h, a3l;
            split_pair(acc[2 * g][0],     acc[2 * g][1],     a0h, a0l);
            split_pair(acc[2 * g][2],     acc[2 * g][3],     a1h, a1l);
            split_pair(acc[2 * g + 1][0], acc[2 * g + 1][1], a2h, a2l);
            split_pair(acc[2 * g + 1][2], acc[2 * g + 1][3], a3h, a3l);
#pragma unroll
            for (int j = 0; j < 8; j++) {
                int voff = (g * 16 + (lane & 15)) * ASTR + j * 8;
                unsigned bh0, bh1, bl0, bl1;
                ldmBT(smem_u32(&Vh[voff]), bh0, bh1);
                ldmBT(smem_u32(&Vl[voff]), bl0, bl1);
                mma16816(o[j], a0h, a1h, a2h, a3h, bh0, bh1);
                mma16816(o[j], a0h, a1h, a2h, a3h, bl0, bl1);
                mma16816(o[j], a0l, a1l, a2l, a3l, bh0, bh1);
            }
        }
        __syncthreads();  // all smem reads of this stage done before overwrite
    }

    // epilogue: split attn result into planes at [m = t*2+b][e = h*64+d]
    const int bsel = n >> 4, h = n & 15;
    const int t0   = qb + wr + (lane >> 2);
    const int dcol = (lane & 3) * 2;
#pragma unroll
    for (int j = 0; j < 8; j++) {
        int d = j * 8 + dcol;
        unsigned hi, lo;
        split_pair(o[j][0], o[j][1], hi, lo);
        size_t off = (size_t)(t0 * 2 + bsel) * E_DIM + h * 64 + d;
        *(unsigned*)&g_ah[off] = hi; *(unsigned*)&g_al[off] = lo;
        split_pair(o[j][2], o[j][3], hi, lo);
        off = (size_t)((t0 + 8) * 2 + bsel) * E_DIM + h * 64 + d;
        *(unsigned*)&g_ah[off] = hi; *(unsigned*)&g_al[off] = lo;
    }
}

// ---------------------------------------------------------------------------
// Output projection (bf16x3, cp.async double-buffered): out = attnx @ wo^T + bo
// grid (32, 8), 256 threads.
// ---------------------------------------------------------------------------
__global__ __launch_bounds__(256) void gemm_out(
    const float* __restrict__ bo, float* __restrict__ out)
{
    extern __shared__ __nv_bfloat16 sb[];

    const int n0 = blockIdx.y * 128;
    const int m0 = blockIdx.x * 128;

    const int tid = threadIdx.x, lane = tid & 31, wid = tid >> 5;
    const int wm = (wid >> 2) * 64, wn = (wid & 3) * 32;
    const int lr = tid >> 2;
    const int lc = (tid & 3) * 8;

    float acc[4][4][4];
#pragma unroll
    for (int i = 0; i < 4; i++)
#pragma unroll
        for (int j = 0; j < 4; j++)
#pragma unroll
            for (int q = 0; q < 4; q++) acc[i][j][q] = 0.f;

    auto load_stage = [&](int s, int k0) {
        __nv_bfloat16* base = sb + s * GSTG;
#pragma unroll
        for (int rr = 0; rr < 128; rr += 64) {
            int row = rr + lr;
            size_t ga = (size_t)(m0 + row) * 1024 + k0 + lc;
            size_t gb = (size_t)(n0 + row) * 1024 + k0 + lc;
            unsigned d = smem_u32(base + row * GSTR + lc);
            cp16(d,           g_ah + ga);
            cp16(d + GPL * 2, g_al + ga);
            cp16(d + GPL * 4, g_woh + gb);
            cp16(d + GPL * 6, g_wol + gb);
        }
    };

    load_stage(0, 0); cp_commit();

    for (int kt = 0; kt < 32; kt++) {
        const int buf = kt & 1;
        if (kt < 31) { load_stage(buf ^ 1, (kt + 1) * 32); cp_commit(); cp_wait<1>(); }
        else         { cp_wait<0>(); }
        __syncthreads();

        const __nv_bfloat16* Ah = sb + buf * GSTG;
        const __nv_bfloat16* Al = Ah + GPL;
        const __nv_bfloat16* Bh = Al + GPL;
        const __nv_bfloat16* Bl = Bh + GPL;

#pragma unroll
        for (int kf = 0; kf < 2; kf++) {
            unsigned ah[4][4], al[4][4];
#pragma unroll
            for (int i = 0; i < 4; i++) {
                int aoff = (wm + i * 16 + (lane & 15)) * GSTR + kf * 16 + (lane >> 4) * 8;
                ldmA(smem_u32(&Ah[aoff]), ah[i][0], ah[i][1], ah[i][2], ah[i][3]);
                ldmA(smem_u32(&Al[aoff]), al[i][0], al[i][1], al[i][2], al[i][3]);
            }
#pragma unroll
            for (int j = 0; j < 4; j++) {
                int boff = (wn + j * 8 + (lane & 7)) * GSTR + kf * 16 + ((lane >> 3) & 1) * 8;
                unsigned bh0, bh1, bl0, bl1;
                ldmB(smem_u32(&Bh[boff]), bh0, bh1);
                ldmB(smem_u32(&Bl[boff]), bl0, bl1);
#pragma unroll
                for (int i = 0; i < 4; i++) {
                    mma16816(acc[i][j], ah[i][0], ah[i][1], ah[i][2], ah[i][3], bh0, bh1);
                    mma16816(acc[i][j], ah[i][0], ah[i][1], ah[i][2], ah[i][3], bl0, bl1);
                    mma16816(acc[i][j], al[i][0], al[i][1], al[i][2], al[i][3], bh0, bh1);
                }
            }
        }
        __syncthreads();
    }

#pragma unroll
    for (int i = 0; i < 4; i++) {
#pragma unroll
        for (int j = 0; j < 4; j++) {
            int col = n0 + wn + j * 8 + (lane & 3) * 2;
            float b0 = bo[col], b1 = bo[col + 1];
#pragma unroll
            for (int half = 0; half < 2; half++) {
                int r = m0 + wm + i * 16 + (lane >> 2) + half * 8;
                float2 v;
                v.x = acc[i][j][2 * half + 0] + b0;
                v.y = acc[i][j][2 * half + 1] + b1;
                *(float2*)(out + (size_t)r * 1024 + col) = v;
            }
        }
    }
}

// ---------------------------------------------------------------------------
// d_out = [ out (4096*1024 fp32) | attn_weights (32*2048*2048 fp32) ]
// ---------------------------------------------------------------------------
extern "C" void kernel_launch(void* const* d_in, const int* in_sizes, int n_in,
                              void* d_out, int out_size)
{
    const float* query = (const float*)d_in[0];
    const float* wq    = (const float*)d_in[1];
    const float* bq    = (const float*)d_in[2];
    const float* wk    = (const float*)d_in[3];
    const float* bk    = (const float*)d_in[4];
    const float* wv    = (const float*)d_in[5];
    const float* bv    = (const float*)d_in[6];
    const float* wo    = (const float*)d_in[7];
    const float* bo    = (const float*)d_in[8];

    float* out   = (float*)d_out;
    float* w_out = out + (size_t)M_DIM * E_DIM;

    const int gemm_smem = 2 * GSTG * (int)sizeof(__nv_bfloat16);     // 81,920 B
    const int attn_smem = 10 * APL * (int)sizeof(__nv_bfloat16);     // 184,320 B
    cudaFuncSetAttribute(gemm_qkv,  cudaFuncAttributeMaxDynamicSharedMemorySize, gemm_smem);
    cudaFuncSetAttribute(attn_kernel, cudaFuncAttributeMaxDynamicSharedMemorySize, attn_smem);
    cudaFuncSetAttribute(gemm_out,  cudaFuncAttributeMaxDynamicSharedMemorySize, gemm_smem);

    split_all<<<8192, 256>>>(query, wq, wk, wv, wo);
    gemm_qkv<<<dim3(32, 24), 256, gemm_smem>>>(bq, bk, bv);
    attn_kernel<<<dim3(16, 32), 256, attn_smem>>>(w_out);
    gemm_out<<<dim3(32, 8), 256, gemm_smem>>>(bo, out);
}

// round 7
// speedup vs baseline: 2.9000x; 1.0933x over previous
#include <cuda_runtime.h>
#include <cuda_bf16.h>

// T=2048, B=2, E=1024, H=16, D=64
#define T_DIM 2048
#define E_DIM 1024
#define NH    32            // B*H
#define M_DIM 4096          // T*B
#define HD    (T_DIM * 64)  // per-head plane elems

// ---------------------------------------------------------------------------
// Device-global scratch: bf16 hi/lo split planes.
// ---------------------------------------------------------------------------
__device__ __nv_bfloat16 g_xh[(size_t)M_DIM * E_DIM], g_xl[(size_t)M_DIM * E_DIM];
__device__ __nv_bfloat16 g_wqh[1024 * 1024], g_wql[1024 * 1024];
__device__ __nv_bfloat16 g_wkh[1024 * 1024], g_wkl[1024 * 1024];
__device__ __nv_bfloat16 g_wvh[1024 * 1024], g_wvl[1024 * 1024];
__device__ __nv_bfloat16 g_woh[1024 * 1024], g_wol[1024 * 1024];
__device__ __nv_bfloat16 g_qh[(size_t)NH * HD], g_ql[(size_t)NH * HD];
__device__ __nv_bfloat16 g_kh[(size_t)NH * HD], g_kl[(size_t)NH * HD];
__device__ __nv_bfloat16 g_vh[(size_t)NH * HD], g_vl[(size_t)NH * HD];
__device__ __nv_bfloat16 g_ah[(size_t)M_DIM * E_DIM], g_al[(size_t)M_DIM * E_DIM];

// ---------------------------------------------------------------------------
// Helpers
// ---------------------------------------------------------------------------
__device__ __forceinline__ unsigned smem_u32(const void* p) {
    return (unsigned)__cvta_generic_to_shared(p);
}
__device__ __forceinline__ void cp16(unsigned dst, const void* src) {
    asm volatile("cp.async.cg.shared.global [%0], [%1], 16;" :: "r"(dst), "l"(src));
}
__device__ __forceinline__ void cp_commit() {
    asm volatile("cp.async.commit_group;");
}
template <int N> __device__ __forceinline__ void cp_wait() {
    asm volatile("cp.async.wait_group %0;" :: "n"(N));
}
__device__ __forceinline__ void ldmA(unsigned addr, unsigned& r0, unsigned& r1,
                                     unsigned& r2, unsigned& r3) {
    asm volatile("ldmatrix.sync.aligned.m8n8.x4.shared.b16 {%0,%1,%2,%3}, [%4];"
                 : "=r"(r0), "=r"(r1), "=r"(r2), "=r"(r3) : "r"(addr));
}
__device__ __forceinline__ void ldmB(unsigned addr, unsigned& r0, unsigned& r1) {
    asm volatile("ldmatrix.sync.aligned.m8n8.x2.shared.b16 {%0,%1}, [%2];"
                 : "=r"(r0), "=r"(r1) : "r"(addr));
}
__device__ __forceinline__ void ldmBT(unsigned addr, unsigned& r0, unsigned& r1) {
    asm volatile("ldmatrix.sync.aligned.m8n8.x2.trans.shared.b16 {%0,%1}, [%2];"
                 : "=r"(r0), "=r"(r1) : "r"(addr));
}
__device__ __forceinline__ void mma16816(float* c, unsigned a0, unsigned a1,
                                         unsigned a2, unsigned a3,
                                         unsigned b0, unsigned b1) {
    asm volatile(
        "mma.sync.aligned.m16n8k16.row.col.f32.bf16.bf16.f32 "
        "{%0,%1,%2,%3}, {%4,%5,%6,%7}, {%8,%9}, {%0,%1,%2,%3};"
        : "+f"(c[0]), "+f"(c[1]), "+f"(c[2]), "+f"(c[3])
        : "r"(a0), "r"(a1), "r"(a2), "r"(a3), "r"(b0), "r"(b1));
}
__device__ __forceinline__ unsigned bpack(__nv_bfloat16 a, __nv_bfloat16 b) {
    unsigned short ua = *(unsigned short*)&a, ub = *(unsigned short*)&b;
    return (unsigned)ua | ((unsigned)ub << 16);
}
__device__ __forceinline__ void split_pair(float x, float y, unsigned& hi, unsigned& lo) {
    __nv_bfloat16 xh = __float2bfloat16(x), yh = __float2bfloat16(y);
    float xr = x - __bfloat162float(xh), yr = y - __bfloat162float(yh);
    hi = bpack(xh, yh);
    lo = bpack(__float2bfloat16(xr), __float2bfloat16(yr));
}
__device__ __forceinline__ void stg_cs_f2(float* p, float a, float b) {
    asm volatile("st.global.cs.v2.f32 [%0], {%1,%2};" :: "l"(p), "f"(a), "f"(b));
}

// ---------------------------------------------------------------------------
// Split all fp32 inputs into bf16 hi/lo planes.
// ---------------------------------------------------------------------------
__global__ __launch_bounds__(256) void split_all(
    const float* __restrict__ X, const float* __restrict__ wq,
    const float* __restrict__ wk, const float* __restrict__ wv,
    const float* __restrict__ wo)
{
    size_t i = (size_t)blockIdx.x * 256 + threadIdx.x;
    const float* src; __nv_bfloat16 *dh, *dl; size_t off;
    if (i < 1048576) { src = X; dh = g_xh; dl = g_xl; off = i; }
    else {
        size_t j = i - 1048576;
        int w = (int)(j >> 18);
        off = j & 262143;
        if      (w == 0) { src = wq; dh = g_wqh; dl = g_wql; }
        else if (w == 1) { src = wk; dh = g_wkh; dl = g_wkl; }
        else if (w == 2) { src = wv; dh = g_wvh; dl = g_wvl; }
        else             { src = wo; dh = g_woh; dl = g_wol; }
    }
    float4 v = ((const float4*)src)[off];
    unsigned h0, l0, h1, l1;
    split_pair(v.x, v.y, h0, l0); split_pair(v.z, v.w, h1, l1);
    ((unsigned*)dh)[off * 2] = h0; ((unsigned*)dh)[off * 2 + 1] = h1;
    ((unsigned*)dl)[off * 2] = l0; ((unsigned*)dl)[off * 2 + 1] = l1;
}

// ---------------------------------------------------------------------------
// GEMM tile constants
// ---------------------------------------------------------------------------
#define GSTR  40
#define GPL   (128 * GSTR)
#define GSTG  (4 * GPL)

// ---------------------------------------------------------------------------
// QKV projection GEMM (bf16x3, cp.async double-buffered, 2 CTAs/SM).
// ---------------------------------------------------------------------------
__global__ __launch_bounds__(256, 2) void gemm_qkv(
    const float* __restrict__ bq, const float* __restrict__ bk, const float* __restrict__ bv)
{
    extern __shared__ __nv_bfloat16 sb[];

    const int wsel = blockIdx.y >> 3;
    const int n0   = (blockIdx.y & 7) * 128;
    const int m0   = blockIdx.x * 128;

    const __nv_bfloat16* Wh = (wsel == 0) ? g_wqh : (wsel == 1) ? g_wkh : g_wvh;
    const __nv_bfloat16* Wl = (wsel == 0) ? g_wql : (wsel == 1) ? g_wkl : g_wvl;
    const float* bias = (wsel == 0) ? bq : (wsel == 1) ? bk : bv;
    __nv_bfloat16* dh = (wsel == 0) ? g_qh : (wsel == 1) ? g_kh : g_vh;
    __nv_bfloat16* dl = (wsel == 0) ? g_ql : (wsel == 1) ? g_kl : g_vl;
    const float scale = (wsel == 0) ? 0.125f : 1.0f;

    const int tid = threadIdx.x, lane = tid & 31, wid = tid >> 5;
    const int wm = (wid >> 2) * 64, wn = (wid & 3) * 32;
    const int lr = tid >> 2;
    const int lc = (tid & 3) * 8;

    float acc[4][4][4];
#pragma unroll
    for (int i = 0; i < 4; i++)
#pragma unroll
        for (int j = 0; j < 4; j++)
#pragma unroll
            for (int q = 0; q < 4; q++) acc[i][j][q] = 0.f;

    auto load_stage = [&](int s, int k0) {
        __nv_bfloat16* base = sb + s * GSTG;
#pragma unroll
        for (int rr = 0; rr < 128; rr += 64) {
            int row = rr + lr;
            size_t ga = (size_t)(m0 + row) * 1024 + k0 + lc;
            size_t gb = (size_t)(n0 + row) * 1024 + k0 + lc;
            unsigned d = smem_u32(base + row * GSTR + lc);
            cp16(d,           g_xh + ga);
            cp16(d + GPL * 2, g_xl + ga);
            cp16(d + GPL * 4, Wh + gb);
            cp16(d + GPL * 6, Wl + gb);
        }
    };

    load_stage(0, 0); cp_commit();

    for (int kt = 0; kt < 32; kt++) {
        const int buf = kt & 1;
        if (kt < 31) { load_stage(buf ^ 1, (kt + 1) * 32); cp_commit(); cp_wait<1>(); }
        else         { cp_wait<0>(); }
        __syncthreads();

        const __nv_bfloat16* Ah = sb + buf * GSTG;
        const __nv_bfloat16* Al = Ah + GPL;
        const __nv_bfloat16* Bh = Al + GPL;
        const __nv_bfloat16* Bl = Bh + GPL;

#pragma unroll
        for (int kf = 0; kf < 2; kf++) {
            unsigned ah[4][4], al[4][4];
#pragma unroll
            for (int i = 0; i < 4; i++) {
                int aoff = (wm + i * 16 + (lane & 15)) * GSTR + kf * 16 + (lane >> 4) * 8;
                ldmA(smem_u32(&Ah[aoff]), ah[i][0], ah[i][1], ah[i][2], ah[i][3]);
                ldmA(smem_u32(&Al[aoff]), al[i][0], al[i][1], al[i][2], al[i][3]);
            }
#pragma unroll
            for (int j = 0; j < 4; j++) {
                int boff = (wn + j * 8 + (lane & 7)) * GSTR + kf * 16 + ((lane >> 3) & 1) * 8;
                unsigned bh0, bh1, bl0, bl1;
                ldmB(smem_u32(&Bh[boff]), bh0, bh1);
                ldmB(smem_u32(&Bl[boff]), bl0, bl1);
#pragma unroll
                for (int i = 0; i < 4; i++) {
                    mma16816(acc[i][j], ah[i][0], ah[i][1], ah[i][2], ah[i][3], bh0, bh1);
                    mma16816(acc[i][j], ah[i][0], ah[i][1], ah[i][2], ah[i][3], bl0, bl1);
                    mma16816(acc[i][j], al[i][0], al[i][1], al[i][2], al[i][3], bh0, bh1);
                }
            }
        }
        __syncthreads();
    }

#pragma unroll
    for (int i = 0; i < 4; i++) {
#pragma unroll
        for (int j = 0; j < 4; j++) {
            int col = n0 + wn + j * 8 + (lane & 3) * 2;
            float b0 = bias[col], b1 = bias[col + 1];
            int h = col >> 6, d = col & 63;
#pragma unroll
            for (int hf = 0; hf < 2; hf++) {
                int r = m0 + wm + i * 16 + (lane >> 2) + hf * 8;
                float v0 = (acc[i][j][2 * hf + 0] + b0) * scale;
                float v1 = (acc[i][j][2 * hf + 1] + b1) * scale;
                unsigned hi, lo;
                split_pair(v0, v1, hi, lo);
                size_t off = (size_t)((r & 1) * 16 + h) * HD + (size_t)(r >> 1) * 64 + d;
                *(unsigned*)&dh[off] = hi;
                *(unsigned*)&dl[off] = lo;
            }
        }
    }
}

// ---------------------------------------------------------------------------
// Attention score half-tile: acc[8][4] = Q(16 rows) @ K^T(64 cols at `co`)
// ---------------------------------------------------------------------------
#define ASTR 72
#define APL  (128 * ASTR)

__device__ __forceinline__ void compute_scores8(
    const __nv_bfloat16* Qh, const __nv_bfloat16* Ql,
    const __nv_bfloat16* Kh, const __nv_bfloat16* Kl,
    int wr, int co, int lane, float acc[8][4])
{
#pragma unroll
    for (int j = 0; j < 8; j++)
#pragma unroll
        for (int q = 0; q < 4; q++) acc[j][q] = 0.f;

#pragma unroll
    for (int kf = 0; kf < 4; kf++) {
        unsigned ah[4], al[4];
        int qoff = (wr + (lane & 15)) * ASTR + kf * 16 + (lane >> 4) * 8;
        ldmA(smem_u32(&Qh[qoff]), ah[0], ah[1], ah[2], ah[3]);
        ldmA(smem_u32(&Ql[qoff]), al[0], al[1], al[2], al[3]);
#pragma unroll
        for (int j = 0; j < 8; j++) {
            int koff = (co + j * 8 + (lane & 7)) * ASTR + kf * 16 + ((lane >> 3) & 1) * 8;
            unsigned bh0, bh1, bl0, bl1;
            ldmB(smem_u32(&Kh[koff]), bh0, bh1);
            ldmB(smem_u32(&Kl[koff]), bl0, bl1);
            mma16816(acc[j], ah[0], ah[1], ah[2], ah[3], bh0, bh1);
            mma16816(acc[j], ah[0], ah[1], ah[2], ah[3], bl0, bl1);
            mma16816(acc[j], al[0], al[1], al[2], al[3], bh0, bh1);
        }
    }
}

// ---------------------------------------------------------------------------
// Attention: per (head n, 128-row q-block). 512 threads / 16 warps.
// Row-group rowgrp = wid&7 (16 rows); column half hv = wid>>3 (64 of 128 cols).
// Independent running (m,l) per half; exact merge between passes.
// ---------------------------------------------------------------------------
__global__ __launch_bounds__(512, 1) void attn_kernel(float* __restrict__ w_out)
{
    extern __shared__ __nv_bfloat16 sm[];
    __nv_bfloat16* Qh = sm;
    __nv_bfloat16* Ql = sm + APL;
    // stage s: sm + 2*APL + s*4*APL -> Kh, Kl, Vh, Vl

    const int n   = blockIdx.y;
    const int qb  = blockIdx.x * 128;
    const int tid = threadIdx.x, lane = tid & 31, wid = tid >> 5;
    const int rowgrp = wid & 7, hv = wid >> 3;
    const int wr = rowgrp * 16, co = hv * 64;

    const __nv_bfloat16* qhg = g_qh + (size_t)n * HD + (size_t)qb * 64;
    const __nv_bfloat16* qlg = g_ql + (size_t)n * HD + (size_t)qb * 64;
    const __nv_bfloat16* khg = g_kh + (size_t)n * HD;
    const __nv_bfloat16* klg = g_kl + (size_t)n * HD;
    const __nv_bfloat16* vhg = g_vh + (size_t)n * HD;
    const __nv_bfloat16* vlg = g_vl + (size_t)n * HD;

    // Q tile once
    for (int idx = tid; idx < 128 * 8; idx += 512) {
        int row = idx >> 3, c = (idx & 7) * 8;
        *(uint4*)&Qh[row * ASTR + c] = *(const uint4*)(qhg + (size_t)row * 64 + c);
        *(uint4*)&Ql[row * ASTR + c] = *(const uint4*)(qlg + (size_t)row * 64 + c);
    }

    const int ar = tid >> 3, ac = (tid & 7) * 8;   // rows 0..63 per iter

    auto load_k = [&](int s, int sc) {
        __nv_bfloat16* kh = sm + 2 * APL + s * 4 * APL;
#pragma unroll
        for (int rr = 0; rr < 128; rr += 64) {
            int row = rr + ar;
            size_t g = (size_t)(sc * 128 + row) * 64 + ac;
            unsigned d = smem_u32(&kh[row * ASTR + ac]);
            cp16(d,           khg + g);
            cp16(d + APL * 2, klg + g);
        }
    };
    auto load_kv = [&](int s, int sc) {
        __nv_bfloat16* kh = sm + 2 * APL + s * 4 * APL;
#pragma unroll
        for (int rr = 0; rr < 128; rr += 64) {
            int row = rr + ar;
            size_t g = (size_t)(sc * 128 + row) * 64 + ac;
            unsigned d = smem_u32(&kh[row * ASTR + ac]);
            cp16(d,           khg + g);
            cp16(d + APL * 2, klg + g);
            cp16(d + APL * 4, vhg + g);
            cp16(d + APL * 6, vlg + g);
        }
    };

    float mv[2] = {-1e30f, -1e30f}, lv[2] = {0.f, 0.f};

    // ---------------- pass 1: per-half softmax statistics ----------------
    load_k(0, 0); cp_commit();
    for (int sc = 0; sc < 16; sc++) {
        const int buf = sc & 1;
        if (sc < 15) { load_k(buf ^ 1, sc + 1); cp_commit(); cp_wait<1>(); }
        else         { cp_wait<0>(); }
        __syncthreads();

        const __nv_bfloat16* Kh = sm + 2 * APL + buf * 4 * APL;
        const __nv_bfloat16* Kl = Kh + APL;

        float acc[8][4];
        compute_scores8(Qh, Ql, Kh, Kl, wr, co, lane, acc);
        __syncthreads();

#pragma unroll
        for (int hf = 0; hf < 2; hf++) {
            float mx = -1e30f;
#pragma unroll
            for (int j = 0; j < 8; j++)
                mx = fmaxf(mx, fmaxf(acc[j][2 * hf], acc[j][2 * hf + 1]));
            mx = fmaxf(mx, __shfl_xor_sync(0xffffffffu, mx, 1));
            mx = fmaxf(mx, __shfl_xor_sync(0xffffffffu, mx, 2));
            float mn = fmaxf(mv[hf], mx);
            float s = 0.f;
#pragma unroll
            for (int j = 0; j < 8; j++)
                s += __expf(acc[j][2 * hf] - mn) + __expf(acc[j][2 * hf + 1] - mn);
            s += __shfl_xor_sync(0xffffffffu, s, 1);
            s += __shfl_xor_sync(0xffffffffu, s, 2);
            lv[hf] = lv[hf] * __expf(mv[hf] - mn) + s;
            mv[hf] = mn;
        }
    }

    // ---------------- merge the two column-halves' stats ----------------
    float* st = (float*)(sm + 2 * APL);   // 512 floats; stage bufs idle now
    __syncthreads();
    if ((lane & 3) == 0) {
        int r_ = lane >> 2;
        st[((hv * 8 + rowgrp) * 16 + r_) * 2 + 0]     = mv[0];
        st[((hv * 8 + rowgrp) * 16 + r_) * 2 + 1]     = lv[0];
        st[((hv * 8 + rowgrp) * 16 + r_ + 8) * 2 + 0] = mv[1];
        st[((hv * 8 + rowgrp) * 16 + r_ + 8) * 2 + 1] = lv[1];
    }
    __syncthreads();
    float mfin[2], invl[2];
#pragma unroll
    for (int hf = 0; hf < 2; hf++) {
        int r_ = (lane >> 2) + hf * 8;
        float ma = st[((0 + rowgrp) * 16 + r_) * 2 + 0];
        float la = st[((0 + rowgrp) * 16 + r_) * 2 + 1];
        float mb = st[((8 + rowgrp) * 16 + r_) * 2 + 0];
        float lb = st[((8 + rowgrp) * 16 + r_) * 2 + 1];
        float mm = fmaxf(ma, mb);
        float ll = la * __expf(ma - mm) + lb * __expf(mb - mm);
        mfin[hf] = mm; invl[hf] = 1.0f / ll;
    }
    __syncthreads();   // scratch reads done before pass-2 loads overwrite

    float o[8][4];
#pragma unroll
    for (int j = 0; j < 8; j++)
#pragma unroll
        for (int q = 0; q < 4; q++) o[j][q] = 0.f;

    // ---------------- pass 2: weights out + partial P@V ----------------
    load_kv(0, 0); cp_commit();
    for (int sc = 0; sc < 16; sc++) {
        const int buf = sc & 1;
        if (sc < 15) { load_kv(buf ^ 1, sc + 1); cp_commit(); cp_wait<1>(); }
        else         { cp_wait<0>(); }
        __syncthreads();

        const __nv_bfloat16* Kh = sm + 2 * APL + buf * 4 * APL;
        const __nv_bfloat16* Kl = Kh + APL;
        const __nv_bfloat16* Vh = Kl + APL;
        const __nv_bfloat16* Vl = Vh + APL;

        float acc[8][4];
        compute_scores8(Qh, Ql, Kh, Kl, wr, co, lane, acc);

        // normalized probabilities: streaming store + keep for PV
        float* wb = w_out + (size_t)n * ((size_t)T_DIM * T_DIM)
                  + (size_t)(qb + wr + (lane >> 2)) * T_DIM + sc * 128 + co + (lane & 3) * 2;
#pragma unroll
        for (int j = 0; j < 8; j++) {
            float p0 = __expf(acc[j][0] - mfin[0]) * invl[0];
            float p1 = __expf(acc[j][1] - mfin[0]) * invl[0];
            float p2 = __expf(acc[j][2] - mfin[1]) * invl[1];
            float p3 = __expf(acc[j][3] - mfin[1]) * invl[1];
            acc[j][0] = p0; acc[j][1] = p1; acc[j][2] = p2; acc[j][3] = p3;
            stg_cs_f2(wb + j * 8, p0, p1);
            stg_cs_f2(wb + 8 * (size_t)T_DIM + j * 8, p2, p3);
        }

        // partial PV over this warp's 64 s-columns
#pragma unroll
        for (int g = 0; g < 4; g++) {
            unsigned a0h, a0l, a1h, a1l, a2h, a2l, a3h, a3l;
            split_pair(acc[2 * g][0],     acc[2 * g][1],     a0h, a0l);
            split_pair(acc[2 * g][2],     acc[2 * g][3],     a1h, a1l);
            split_pair(acc[2 * g + 1][0], acc[2 * g + 1][1], a2h, a2l);
            split_pair(acc[2 * g + 1][2], acc[2 * g + 1][3], a3h, a3l);
#pragma unroll
            for (int j = 0; j < 8; j++) {
                int voff = (co + g * 16 + (lane & 15)) * ASTR + j * 8;
                unsigned bh0, bh1, bl0, bl1;
                ldmBT(smem_u32(&Vh[voff]), bh0, bh1);
                ldmBT(smem_u32(&Vl[voff]), bl0, bl1);
                mma16816(o[j], a0h, a1h, a2h, a3h, bh0, bh1);
                mma16816(o[j], a0h, a1h, a2h, a3h, bl0, bl1);
                mma16816(o[j], a0l, a1l, a2l, a3l, bh0, bh1);
            }
        }
        __syncthreads();
    }

    // ---------------- merge partial O across the two halves ----------------
    float* os = (float*)sm;   // 32 KB; Q region no longer needed
    if (hv == 1) {
#pragma unroll
        for (int j = 0; j < 8; j++)
#pragma unroll
            for (int q = 0; q < 4; q++)
                os[(rowgrp * 32 + lane) * 32 + j * 4 + q] = o[j][q];
    }
    __syncthreads();
    if (hv == 0) {
#pragma unroll
        for (int j = 0; j < 8; j++)
#pragma unroll
            for (int q = 0; q < 4; q++)
                o[j][q] += os[(rowgrp * 32 + lane) * 32 + j * 4 + q];

        // epilogue: split into planes at [m = t*2+b][e = h*64+d]
        const int bsel = n >> 4, h = n & 15;
        const int t0   = qb + wr + (lane >> 2);
        const int dcol = (lane & 3) * 2;
#pragma unroll
        for (int j = 0; j < 8; j++) {
            int d = j * 8 + dcol;
            unsigned hi, lo;
            split_pair(o[j][0], o[j][1], hi, lo);
            size_t off = (size_t)(t0 * 2 + bsel) * E_DIM + h * 64 + d;
            *(unsigned*)&g_ah[off] = hi; *(unsigned*)&g_al[off] = lo;
            split_pair(o[j][2], o[j][3], hi, lo);
            off = (size_t)((t0 + 8) * 2 + bsel) * E_DIM + h * 64 + d;
            *(unsigned*)&g_ah[off] = hi; *(unsigned*)&g_al[off] = lo;
        }
    }
}

// ---------------------------------------------------------------------------
// Output projection (bf16x3, cp.async double-buffered, 2 CTAs/SM).
// ---------------------------------------------------------------------------
__global__ __launch_bounds__(256, 2) void gemm_out(
    const float* __restrict__ bo, float* __restrict__ out)
{
    extern __shared__ __nv_bfloat16 sb[];

    const int n0 = blockIdx.y * 128;
    const int m0 = blockIdx.x * 128;

    const int tid = threadIdx.x, lane = tid & 31, wid = tid >> 5;
    const int wm = (wid >> 2) * 64, wn = (wid & 3) * 32;
    const int lr = tid >> 2;
    const int lc = (tid & 3) * 8;

    float acc[4][4][4];
#pragma unroll
    for (int i = 0; i < 4; i++)
#pragma unroll
        for (int j = 0; j < 4; j++)
#pragma unroll
            for (int q = 0; q < 4; q++) acc[i][j][q] = 0.f;

    auto load_stage = [&](int s, int k0) {
        __nv_bfloat16* base = sb + s * GSTG;
#pragma unroll
        for (int rr = 0; rr < 128; rr += 64) {
            int row = rr + lr;
            size_t ga = (size_t)(m0 + row) * 1024 + k0 + lc;
            size_t gb = (size_t)(n0 + row) * 1024 + k0 + lc;
            unsigned d = smem_u32(base + row * GSTR + lc);
            cp16(d,           g_ah + ga);
            cp16(d + GPL * 2, g_al + ga);
            cp16(d + GPL * 4, g_woh + gb);
            cp16(d + GPL * 6, g_wol + gb);
        }
    };

    load_stage(0, 0); cp_commit();

    for (int kt = 0; kt < 32; kt++) {
        const int buf = kt & 1;
        if (kt < 31) { load_stage(buf ^ 1, (kt + 1) * 32); cp_commit(); cp_wait<1>(); }
        else         { cp_wait<0>(); }
        __syncthreads();

        const __nv_bfloat16* Ah = sb + buf * GSTG;
        const __nv_bfloat16* Al = Ah + GPL;
        const __nv_bfloat16* Bh = Al + GPL;
        const __nv_bfloat16* Bl = Bh + GPL;

#pragma unroll
        for (int kf = 0; kf < 2; kf++) {
            unsigned ah[4][4], al[4][4];
#pragma unroll
            for (int i = 0; i < 4; i++) {
                int aoff = (wm + i * 16 + (lane & 15)) * GSTR + kf * 16 + (lane >> 4) * 8;
                ldmA(smem_u32(&Ah[aoff]), ah[i][0], ah[i][1], ah[i][2], ah[i][3]);
                ldmA(smem_u32(&Al[aoff]), al[i][0], al[i][1], al[i][2], al[i][3]);
            }
#pragma unroll
            for (int j = 0; j < 4; j++) {
                int boff = (wn + j * 8 + (lane & 7)) * GSTR + kf * 16 + ((lane >> 3) & 1) * 8;
                unsigned bh0, bh1, bl0, bl1;
                ldmB(smem_u32(&Bh[boff]), bh0, bh1);
                ldmB(smem_u32(&Bl[boff]), bl0, bl1);
#pragma unroll
                for (int i = 0; i < 4; i++) {
                    mma16816(acc[i][j], ah[i][0], ah[i][1], ah[i][2], ah[i][3], bh0, bh1);
                    mma16816(acc[i][j], ah[i][0], ah[i][1], ah[i][2], ah[i][3], bl0, bl1);
                    mma16816(acc[i][j], al[i][0], al[i][1], al[i][2], al[i][3], bh0, bh1);
                }
            }
        }
        __syncthreads();
    }

#pragma unroll
    for (int i = 0; i < 4; i++) {
#pragma unroll
        for (int j = 0; j < 4; j++) {
            int col = n0 + wn + j * 8 + (lane & 3) * 2;
            float b0 = bo[col], b1 = bo[col + 1];
#pragma unroll
            for (int hf = 0; hf < 2; hf++) {
                int r = m0 + wm + i * 16 + (lane >> 2) + hf * 8;
                float2 v;
                v.x = acc[i][j][2 * hf + 0] + b0;
                v.y = acc[i][j][2 * hf + 1] + b1;
                *(float2*)(out + (size_t)r * 1024 + col) = v;
            }
        }
    }
}

// ---------------------------------------------------------------------------
// d_out = [ out (4096*1024 fp32) | attn_weights (32*2048*2048 fp32) ]
// ---------------------------------------------------------------------------
extern "C" void kernel_launch(void* const* d_in, const int* in_sizes, int n_in,
                              void* d_out, int out_size)
{
    const float* query = (const float*)d_in[0];
    const float* bq    = (const float*)d_in[2];
    const float* bk    = (const float*)d_in[4];
    const float* bv    = (const float*)d_in[6];
    const float* bo    = (const float*)d_in[8];
    const float* wq    = (const float*)d_in[1];
    const float* wk    = (const float*)d_in[3];
    const float* wv    = (const float*)d_in[5];
    const float* wo    = (const float*)d_in[7];

    float* out   = (float*)d_out;
    float* w_out = out + (size_t)M_DIM * E_DIM;

    const int gemm_smem = 2 * GSTG * (int)sizeof(__nv_bfloat16);   // 81,920 B
    const int attn_smem = 10 * APL * (int)sizeof(__nv_bfloat16);   // 184,320 B
    cudaFuncSetAttribute(gemm_qkv,   cudaFuncAttributeMaxDynamicSharedMemorySize, gemm_smem);
    cudaFuncSetAttribute(attn_kernel, cudaFuncAttributeMaxDynamicSharedMemorySize, attn_smem);
    cudaFuncSetAttribute(gemm_out,   cudaFuncAttributeMaxDynamicSharedMemorySize, gemm_smem);

    split_all<<<8192, 256>>>(query, wq, wk, wv, wo);
    gemm_qkv<<<dim3(32, 24), 256, gemm_smem>>>(bq, bk, bv);
    attn_kernel<<<dim3(16, 32), 512, attn_smem>>>(w_out);
    gemm_out<<<dim3(32, 8), 256, gemm_smem>>>(bo, out);
}

// round 10
// speedup vs baseline: 3.1705x; 1.0933x over previous
#include <cuda_runtime.h>
#include <cuda_bf16.h>

// T=2048, B=2, E=1024, H=16, D=64
#define T_DIM 2048
#define E_DIM 1024
#define NH    32            // B*H
#define M_DIM 4096          // T*B
#define HD    (T_DIM * 64)  // per-head plane elems

// ---------------------------------------------------------------------------
// Device-global scratch: bf16 hi/lo split planes.
// ---------------------------------------------------------------------------
__device__ __nv_bfloat16 g_xh[(size_t)M_DIM * E_DIM], g_xl[(size_t)M_DIM * E_DIM];
__device__ __nv_bfloat16 g_wqh[1024 * 1024], g_wql[1024 * 1024];
__device__ __nv_bfloat16 g_wkh[1024 * 1024], g_wkl[1024 * 1024];
__device__ __nv_bfloat16 g_wvh[1024 * 1024], g_wvl[1024 * 1024];
__device__ __nv_bfloat16 g_woh[1024 * 1024], g_wol[1024 * 1024];
__device__ __nv_bfloat16 g_qh[(size_t)NH * HD], g_ql[(size_t)NH * HD];
__device__ __nv_bfloat16 g_kh[(size_t)NH * HD], g_kl[(size_t)NH * HD];
__device__ __nv_bfloat16 g_vh[(size_t)NH * HD], g_vl[(size_t)NH * HD];
__device__ __nv_bfloat16 g_ah[(size_t)M_DIM * E_DIM], g_al[(size_t)M_DIM * E_DIM];

// ---------------------------------------------------------------------------
// Helpers
// ---------------------------------------------------------------------------
__device__ __forceinline__ unsigned smem_u32(const void* p) {
    return (unsigned)__cvta_generic_to_shared(p);
}
__device__ __forceinline__ void cp16(unsigned dst, const void* src) {
    asm volatile("cp.async.cg.shared.global [%0], [%1], 16;" :: "r"(dst), "l"(src));
}
__device__ __forceinline__ void cp_commit() {
    asm volatile("cp.async.commit_group;");
}
template <int N> __device__ __forceinline__ void cp_wait() {
    asm volatile("cp.async.wait_group %0;" :: "n"(N));
}
__device__ __forceinline__ void ldmA(unsigned addr, unsigned& r0, unsigned& r1,
                                     unsigned& r2, unsigned& r3) {
    asm volatile("ldmatrix.sync.aligned.m8n8.x4.shared.b16 {%0,%1,%2,%3}, [%4];"
                 : "=r"(r0), "=r"(r1), "=r"(r2), "=r"(r3) : "r"(addr));
}
__device__ __forceinline__ void ldmB(unsigned addr, unsigned& r0, unsigned& r1) {
    asm volatile("ldmatrix.sync.aligned.m8n8.x2.shared.b16 {%0,%1}, [%2];"
                 : "=r"(r0), "=r"(r1) : "r"(addr));
}
__device__ __forceinline__ void ldmBT(unsigned addr, unsigned& r0, unsigned& r1) {
    asm volatile("ldmatrix.sync.aligned.m8n8.x2.trans.shared.b16 {%0,%1}, [%2];"
                 : "=r"(r0), "=r"(r1) : "r"(addr));
}
__device__ __forceinline__ void mma16816(float* c, unsigned a0, unsigned a1,
                                         unsigned a2, unsigned a3,
                                         unsigned b0, unsigned b1) {
    asm volatile(
        "mma.sync.aligned.m16n8k16.row.col.f32.bf16.bf16.f32 "
        "{%0,%1,%2,%3}, {%4,%5,%6,%7}, {%8,%9}, {%0,%1,%2,%3};"
        : "+f"(c[0]), "+f"(c[1]), "+f"(c[2]), "+f"(c[3])
        : "r"(a0), "r"(a1), "r"(a2), "r"(a3), "r"(b0), "r"(b1));
}
__device__ __forceinline__ unsigned bpack(__nv_bfloat16 a, __nv_bfloat16 b) {
    unsigned short ua = *(unsigned short*)&a, ub = *(unsigned short*)&b;
    return (unsigned)ua | ((unsigned)ub << 16);
}
__device__ __forceinline__ void split_pair(float x, float y, unsigned& hi, unsigned& lo) {
    __nv_bfloat16 xh = __float2bfloat16(x), yh = __float2bfloat16(y);
    float xr = x - __bfloat162float(xh), yr = y - __bfloat162float(yh);
    hi = bpack(xh, yh);
    lo = bpack(__float2bfloat16(xr), __float2bfloat16(yr));
}
__device__ __forceinline__ void stg_cs_f2(float* p, float a, float b) {
    asm volatile("st.global.cs.v2.f32 [%0], {%1,%2};" :: "l"(p), "f"(a), "f"(b));
}

// ---------------------------------------------------------------------------
// Split all fp32 inputs into bf16 hi/lo planes.
// ---------------------------------------------------------------------------
__global__ __launch_bounds__(256) void split_all(
    const float* __restrict__ X, const float* __restrict__ wq,
    const float* __restrict__ wk, const float* __restrict__ wv,
    const float* __restrict__ wo)
{
    size_t i = (size_t)blockIdx.x * 256 + threadIdx.x;
    const float* src; __nv_bfloat16 *dh, *dl; size_t off;
    if (i < 1048576) { src = X; dh = g_xh; dl = g_xl; off = i; }
    else {
        size_t j = i - 1048576;
        int w = (int)(j >> 18);
        off = j & 262143;
        if      (w == 0) { src = wq; dh = g_wqh; dl = g_wql; }
        else if (w == 1) { src = wk; dh = g_wkh; dl = g_wkl; }
        else if (w == 2) { src = wv; dh = g_wvh; dl = g_wvl; }
        else             { src = wo; dh = g_woh; dl = g_wol; }
    }
    float4 v = ((const float4*)src)[off];
    unsigned h0, l0, h1, l1;
    split_pair(v.x, v.y, h0, l0); split_pair(v.z, v.w, h1, l1);
    ((unsigned*)dh)[off * 2] = h0; ((unsigned*)dh)[off * 2 + 1] = h1;
    ((unsigned*)dl)[off * 2] = l0; ((unsigned*)dl)[off * 2 + 1] = l1;
}

// ---------------------------------------------------------------------------
// GEMM tile constants
// ---------------------------------------------------------------------------
#define GSTR  40
#define GPL   (128 * GSTR)
#define GSTG  (4 * GPL)

// ---------------------------------------------------------------------------
// QKV projection GEMM (bf16x3, cp.async double-buffered, 2 CTAs/SM).
// ---------------------------------------------------------------------------
__global__ __launch_bounds__(256, 2) void gemm_qkv(
    const float* __restrict__ bq, const float* __restrict__ bk, const float* __restrict__ bv)
{
    extern __shared__ __nv_bfloat16 sb[];

    const int wsel = blockIdx.y >> 3;
    const int n0   = (blockIdx.y & 7) * 128;
    const int m0   = blockIdx.x * 128;

    const __nv_bfloat16* Wh = (wsel == 0) ? g_wqh : (wsel == 1) ? g_wkh : g_wvh;
    const __nv_bfloat16* Wl = (wsel == 0) ? g_wql : (wsel == 1) ? g_wkl : g_wvl;
    const float* bias = (wsel == 0) ? bq : (wsel == 1) ? bk : bv;
    __nv_bfloat16* dh = (wsel == 0) ? g_qh : (wsel == 1) ? g_kh : g_vh;
    __nv_bfloat16* dl = (wsel == 0) ? g_ql : (wsel == 1) ? g_kl : g_vl;
    const float scale = (wsel == 0) ? 0.125f : 1.0f;

    const int tid = threadIdx.x, lane = tid & 31, wid = tid >> 5;
    const int wm = (wid >> 2) * 64, wn = (wid & 3) * 32;
    const int lr = tid >> 2;
    const int lc = (tid & 3) * 8;

    float acc[4][4][4];
#pragma unroll
    for (int i = 0; i < 4; i++)
#pragma unroll
        for (int j = 0; j < 4; j++)
#pragma unroll
            for (int q = 0; q < 4; q++) acc[i][j][q] = 0.f;

    auto load_stage = [&](int s, int k0) {
        __nv_bfloat16* base = sb + s * GSTG;
#pragma unroll
        for (int rr = 0; rr < 128; rr += 64) {
            int row = rr + lr;
            size_t ga = (size_t)(m0 + row) * 1024 + k0 + lc;
            size_t gb = (size_t)(n0 + row) * 1024 + k0 + lc;
            unsigned d = smem_u32(base + row * GSTR + lc);
            cp16(d,           g_xh + ga);
            cp16(d + GPL * 2, g_xl + ga);
            cp16(d + GPL * 4, Wh + gb);
            cp16(d + GPL * 6, Wl + gb);
        }
    };

    load_stage(0, 0); cp_commit();

    for (int kt = 0; kt < 32; kt++) {
        const int buf = kt & 1;
        if (kt < 31) { load_stage(buf ^ 1, (kt + 1) * 32); cp_commit(); cp_wait<1>(); }
        else         { cp_wait<0>(); }
        __syncthreads();

        const __nv_bfloat16* Ah = sb + buf * GSTG;
        const __nv_bfloat16* Al = Ah + GPL;
        const __nv_bfloat16* Bh = Al + GPL;
        const __nv_bfloat16* Bl = Bh + GPL;

#pragma unroll
        for (int kf = 0; kf < 2; kf++) {
            unsigned ah[4][4], al[4][4];
#pragma unroll
            for (int i = 0; i < 4; i++) {
                int aoff = (wm + i * 16 + (lane & 15)) * GSTR + kf * 16 + (lane >> 4) * 8;
                ldmA(smem_u32(&Ah[aoff]), ah[i][0], ah[i][1], ah[i][2], ah[i][3]);
                ldmA(smem_u32(&Al[aoff]), al[i][0], al[i][1], al[i][2], al[i][3]);
            }
#pragma unroll
            for (int j = 0; j < 4; j++) {
                int boff = (wn + j * 8 + (lane & 7)) * GSTR + kf * 16 + ((lane >> 3) & 1) * 8;
                unsigned bh0, bh1, bl0, bl1;
                ldmB(smem_u32(&Bh[boff]), bh0, bh1);
                ldmB(smem_u32(&Bl[boff]), bl0, bl1);
#pragma unroll
                for (int i = 0; i < 4; i++) {
                    mma16816(acc[i][j], ah[i][0], ah[i][1], ah[i][2], ah[i][3], bh0, bh1);
                    mma16816(acc[i][j], ah[i][0], ah[i][1], ah[i][2], ah[i][3], bl0, bl1);
                    mma16816(acc[i][j], al[i][0], al[i][1], al[i][2], al[i][3], bh0, bh1);
                }
            }
        }
        __syncthreads();
    }

#pragma unroll
    for (int i = 0; i < 4; i++) {
#pragma unroll
        for (int j = 0; j < 4; j++) {
            int col = n0 + wn + j * 8 + (lane & 3) * 2;
            float b0 = bias[col], b1 = bias[col + 1];
            int h = col >> 6, d = col & 63;
#pragma unroll
            for (int hf = 0; hf < 2; hf++) {
                int r = m0 + wm + i * 16 + (lane >> 2) + hf * 8;
                float v0 = (acc[i][j][2 * hf + 0] + b0) * scale;
                float v1 = (acc[i][j][2 * hf + 1] + b1) * scale;
                unsigned hi, lo;
                split_pair(v0, v1, hi, lo);
                size_t off = (size_t)((r & 1) * 16 + h) * HD + (size_t)(r >> 1) * 64 + d;
                *(unsigned*)&dh[off] = hi;
                *(unsigned*)&dl[off] = lo;
            }
        }
    }
}

// ---------------------------------------------------------------------------
// Attention score half-tiles.
// Full precision (bf16x3): used in pass 2 (weights output).
// Single plane (1 MMA):    used in pass 1 (statistics only).
// ---------------------------------------------------------------------------
#define ASTR 72
#define APL  (128 * ASTR)

__device__ __forceinline__ void compute_scores8(
    const __nv_bfloat16* Qh, const __nv_bfloat16* Ql,
    const __nv_bfloat16* Kh, const __nv_bfloat16* Kl,
    int wr, int co, int lane, float acc[8][4])
{
#pragma unroll
    for (int j = 0; j < 8; j++)
#pragma unroll
        for (int q = 0; q < 4; q++) acc[j][q] = 0.f;

#pragma unroll
    for (int kf = 0; kf < 4; kf++) {
        unsigned ah[4], al[4];
        int qoff = (wr + (lane & 15)) * ASTR + kf * 16 + (lane >> 4) * 8;
        ldmA(smem_u32(&Qh[qoff]), ah[0], ah[1], ah[2], ah[3]);
        ldmA(smem_u32(&Ql[qoff]), al[0], al[1], al[2], al[3]);
#pragma unroll
        for (int j = 0; j < 8; j++) {
            int koff = (co + j * 8 + (lane & 7)) * ASTR + kf * 16 + ((lane >> 3) & 1) * 8;
            unsigned bh0, bh1, bl0, bl1;
            ldmB(smem_u32(&Kh[koff]), bh0, bh1);
            ldmB(smem_u32(&Kl[koff]), bl0, bl1);
            mma16816(acc[j], ah[0], ah[1], ah[2], ah[3], bh0, bh1);
            mma16816(acc[j], ah[0], ah[1], ah[2], ah[3], bl0, bl1);
            mma16816(acc[j], al[0], al[1], al[2], al[3], bh0, bh1);
        }
    }
}

__device__ __forceinline__ void compute_scores1(
    const __nv_bfloat16* Qh, const __nv_bfloat16* Kh,
    int wr, int co, int lane, float acc[8][4])
{
#pragma unroll
    for (int j = 0; j < 8; j++)
#pragma unroll
        for (int q = 0; q < 4; q++) acc[j][q] = 0.f;

#pragma unroll
    for (int kf = 0; kf < 4; kf++) {
        unsigned ah[4];
        int qoff = (wr + (lane & 15)) * ASTR + kf * 16 + (lane >> 4) * 8;
        ldmA(smem_u32(&Qh[qoff]), ah[0], ah[1], ah[2], ah[3]);
#pragma unroll
        for (int j = 0; j < 8; j++) {
            int koff = (co + j * 8 + (lane & 7)) * ASTR + kf * 16 + ((lane >> 3) & 1) * 8;
            unsigned bh0, bh1;
            ldmB(smem_u32(&Kh[koff]), bh0, bh1);
            mma16816(acc[j], ah[0], ah[1], ah[2], ah[3], bh0, bh1);
        }
    }
}

// ---------------------------------------------------------------------------
// Attention: per (head n, 128-row q-block). 512 threads / 16 warps.
// Row-group rowgrp = wid&7 (16 rows); column half hv = wid>>3 (64 of 128 cols).
// Pass 1 uses hi-plane-only scores (statistics tolerance); pass 2 full bf16x3.
// ---------------------------------------------------------------------------
__global__ __launch_bounds__(512, 1) void attn_kernel(float* __restrict__ w_out)
{
    extern __shared__ __nv_bfloat16 sm[];
    __nv_bfloat16* Qh = sm;
    __nv_bfloat16* Ql = sm + APL;
    // stage s: sm + 2*APL + s*4*APL -> Kh, Kl, Vh, Vl

    const int n   = blockIdx.y;
    const int qb  = blockIdx.x * 128;
    const int tid = threadIdx.x, lane = tid & 31, wid = tid >> 5;
    const int rowgrp = wid & 7, hv = wid >> 3;
    const int wr = rowgrp * 16, co = hv * 64;

    const __nv_bfloat16* qhg = g_qh + (size_t)n * HD + (size_t)qb * 64;
    const __nv_bfloat16* qlg = g_ql + (size_t)n * HD + (size_t)qb * 64;
    const __nv_bfloat16* khg = g_kh + (size_t)n * HD;
    const __nv_bfloat16* klg = g_kl + (size_t)n * HD;
    const __nv_bfloat16* vhg = g_vh + (size_t)n * HD;
    const __nv_bfloat16* vlg = g_vl + (size_t)n * HD;

    for (int idx = tid; idx < 128 * 8; idx += 512) {
        int row = idx >> 3, c = (idx & 7) * 8;
        *(uint4*)&Qh[row * ASTR + c] = *(const uint4*)(qhg + (size_t)row * 64 + c);
        *(uint4*)&Ql[row * ASTR + c] = *(const uint4*)(qlg + (size_t)row * 64 + c);
    }

    const int ar = tid >> 3, ac = (tid & 7) * 8;

    // pass-1 loads: Kh plane only
    auto load_k1 = [&](int s, int sc) {
        __nv_bfloat16* kh = sm + 2 * APL + s * 4 * APL;
#pragma unroll
        for (int rr = 0; rr < 128; rr += 64) {
            int row = rr + ar;
            size_t g = (size_t)(sc * 128 + row) * 64 + ac;
            cp16(smem_u32(&kh[row * ASTR + ac]), khg + g);
        }
    };
    auto load_kv = [&](int s, int sc) {
        __nv_bfloat16* kh = sm + 2 * APL + s * 4 * APL;
#pragma unroll
        for (int rr = 0; rr < 128; rr += 64) {
            int row = rr + ar;
            size_t g = (size_t)(sc * 128 + row) * 64 + ac;
            unsigned d = smem_u32(&kh[row * ASTR + ac]);
            cp16(d,           khg + g);
            cp16(d + APL * 2, klg + g);
            cp16(d + APL * 4, vhg + g);
            cp16(d + APL * 6, vlg + g);
        }
    };

    float mv[2] = {-1e30f, -1e30f}, lv[2] = {0.f, 0.f};

    // ---------------- pass 1: per-half softmax statistics (hi-plane only) ----
    load_k1(0, 0); cp_commit();
    for (int sc = 0; sc < 16; sc++) {
        const int buf = sc & 1;
        if (sc < 15) { load_k1(buf ^ 1, sc + 1); cp_commit(); cp_wait<1>(); }
        else         { cp_wait<0>(); }
        __syncthreads();

        const __nv_bfloat16* Kh = sm + 2 * APL + buf * 4 * APL;

        float acc[8][4];
        compute_scores1(Qh, Kh, wr, co, lane, acc);
        __syncthreads();

#pragma unroll
        for (int hf = 0; hf < 2; hf++) {
            float mx = -1e30f;
#pragma unroll
            for (int j = 0; j < 8; j++)
                mx = fmaxf(mx, fmaxf(acc[j][2 * hf], acc[j][2 * hf + 1]));
            mx = fmaxf(mx, __shfl_xor_sync(0xffffffffu, mx, 1));
            mx = fmaxf(mx, __shfl_xor_sync(0xffffffffu, mx, 2));
            float mn = fmaxf(mv[hf], mx);
            float s = 0.f;
#pragma unroll
            for (int j = 0; j < 8; j++)
                s += __expf(acc[j][2 * hf] - mn) + __expf(acc[j][2 * hf + 1] - mn);
            s += __shfl_xor_sync(0xffffffffu, s, 1);
            s += __shfl_xor_sync(0xffffffffu, s, 2);
            lv[hf] = lv[hf] * __expf(mv[hf] - mn) + s;
            mv[hf] = mn;
        }
    }

    // ---------------- merge the two column-halves' stats ----------------
    float* st = (float*)(sm + 2 * APL);
    __syncthreads();
    if ((lane & 3) == 0) {
        int r_ = lane >> 2;
        st[((hv * 8 + rowgrp) * 16 + r_) * 2 + 0]     = mv[0];
        st[((hv * 8 + rowgrp) * 16 + r_) * 2 + 1]     = lv[0];
        st[((hv * 8 + rowgrp) * 16 + r_ + 8) * 2 + 0] = mv[1];
        st[((hv * 8 + rowgrp) * 16 + r_ + 8) * 2 + 1] = lv[1];
    }
    __syncthreads();
    float mfin[2], invl[2];
#pragma unroll
    for (int hf = 0; hf < 2; hf++) {
        int r_ = (lane >> 2) + hf * 8;
        float ma = st[((0 + rowgrp) * 16 + r_) * 2 + 0];
        float la = st[((0 + rowgrp) * 16 + r_) * 2 + 1];
        float mb = st[((8 + rowgrp) * 16 + r_) * 2 + 0];
        float lb = st[((8 + rowgrp) * 16 + r_) * 2 + 1];
        float mm = fmaxf(ma, mb);
        float ll = la * __expf(ma - mm) + lb * __expf(mb - mm);
        mfin[hf] = mm; invl[hf] = 1.0f / ll;
    }
    __syncthreads();

    float o[8][4];
#pragma unroll
    for (int j = 0; j < 8; j++)
#pragma unroll
        for (int q = 0; q < 4; q++) o[j][q] = 0.f;

    // ---------------- pass 2: weights out + partial P@V (full precision) ----
    load_kv(0, 0); cp_commit();
    for (int sc = 0; sc < 16; sc++) {
        const int buf = sc & 1;
        if (sc < 15) { load_kv(buf ^ 1, sc + 1); cp_commit(); cp_wait<1>(); }
        else         { cp_wait<0>(); }
        __syncthreads();

        const __nv_bfloat16* Kh = sm + 2 * APL + buf * 4 * APL;
        const __nv_bfloat16* Kl = Kh + APL;
        const __nv_bfloat16* Vh = Kl + APL;
        const __nv_bfloat16* Vl = Vh + APL;

        float acc[8][4];
        compute_scores8(Qh, Ql, Kh, Kl, wr, co, lane, acc);

        float* wb = w_out + (size_t)n * ((size_t)T_DIM * T_DIM)
                  + (size_t)(qb + wr + (lane >> 2)) * T_DIM + sc * 128 + co + (lane & 3) * 2;
#pragma unroll
        for (int j = 0; j < 8; j++) {
            float p0 = __expf(acc[j][0] - mfin[0]) * invl[0];
            float p1 = __expf(acc[j][1] - mfin[0]) * invl[0];
            float p2 = __expf(acc[j][2] - mfin[1]) * invl[1];
            float p3 = __expf(acc[j][3] - mfin[1]) * invl[1];
            acc[j][0] = p0; acc[j][1] = p1; acc[j][2] = p2; acc[j][3] = p3;
            stg_cs_f2(wb + j * 8, p0, p1);
            stg_cs_f2(wb + 8 * (size_t)T_DIM + j * 8, p2, p3);
        }

#pragma unroll
        for (int g = 0; g < 4; g++) {
            unsigned a0h, a0l, a1h, a1l, a2h, a2l, a3h, a3l;
            split_pair(acc[2 * g][0],     acc[2 * g][1],     a0h, a0l);
            split_pair(acc[2 * g][2],     acc[2 * g][3],     a1h, a1l);
            split_pair(acc[2 * g + 1][0], acc[2 * g + 1][1], a2h, a2l);
            split_pair(acc[2 * g + 1][2], acc[2 * g + 1][3], a3h, a3l);
#pragma unroll
            for (int j = 0; j < 8; j++) {
                int voff = (co + g * 16 + (lane & 15)) * ASTR + j * 8;
                unsigned bh0, bh1, bl0, bl1;
                ldmBT(smem_u32(&Vh[voff]), bh0, bh1);
                ldmBT(smem_u32(&Vl[voff]), bl0, bl1);
                mma16816(o[j], a0h, a1h, a2h, a3h, bh0, bh1);
                mma16816(o[j], a0h, a1h, a2h, a3h, bl0, bl1);
                mma16816(o[j], a0l, a1l, a2l, a3l, bh0, bh1);
            }
        }
        __syncthreads();
    }

    // ---------------- merge partial O across the two halves ----------------
    float* os = (float*)sm;
    if (hv == 1) {
#pragma unroll
        for (int j = 0; j < 8; j++)
#pragma unroll
            for (int q = 0; q < 4; q++)
                os[(rowgrp * 32 + lane) * 32 + j * 4 + q] = o[j][q];
    }
    __syncthreads();
    if (hv == 0) {
#pragma unroll
        for (int j = 0; j < 8; j++)
#pragma unroll
            for (int q = 0; q < 4; q++)
                o[j][q] += os[(rowgrp * 32 + lane) * 32 + j * 4 + q];

        const int bsel = n >> 4, h = n & 15;
        const int t0   = qb + wr + (lane >> 2);
        const int dcol = (lane & 3) * 2;
#pragma unroll
        for (int j = 0; j < 8; j++) {
            int d = j * 8 + dcol;
            unsigned hi, lo;
            split_pair(o[j][0], o[j][1], hi, lo);
            size_t off = (size_t)(t0 * 2 + bsel) * E_DIM + h * 64 + d;
            *(unsigned*)&g_ah[off] = hi; *(unsigned*)&g_al[off] = lo;
            split_pair(o[j][2], o[j][3], hi, lo);
            off = (size_t)((t0 + 8) * 2 + bsel) * E_DIM + h * 64 + d;
            *(unsigned*)&g_ah[off] = hi; *(unsigned*)&g_al[off] = lo;
        }
    }
}

// ---------------------------------------------------------------------------
// Output projection (bf16x3, cp.async double-buffered, 2 CTAs/SM).
// ---------------------------------------------------------------------------
__global__ __launch_bounds__(256, 2) void gemm_out(
    const float* __restrict__ bo, float* __restrict__ out)
{
    extern __shared__ __nv_bfloat16 sb[];

    const int n0 = blockIdx.y * 128;
    const int m0 = blockIdx.x * 128;

    const int tid = threadIdx.x, lane = tid & 31, wid = tid >> 5;
    const int wm = (wid >> 2) * 64, wn = (wid & 3) * 32;
    const int lr = tid >> 2;
    const int lc = (tid & 3) * 8;

    float acc[4][4][4];
#pragma unroll
    for (int i = 0; i < 4; i++)
#pragma unroll
        for (int j = 0; j < 4; j++)
#pragma unroll
            for (int q = 0; q < 4; q++) acc[i][j][q] = 0.f;

    auto load_stage = [&](int s, int k0) {
        __nv_bfloat16* base = sb + s * GSTG;
#pragma unroll
        for (int rr = 0; rr < 128; rr += 64) {
            int row = rr + lr;
            size_t ga = (size_t)(m0 + row) * 1024 + k0 + lc;
            size_t gb = (size_t)(n0 + row) * 1024 + k0 + lc;
            unsigned d = smem_u32(base + row * GSTR + lc);
            cp16(d,           g_ah + ga);
            cp16(d + GPL * 2, g_al + ga);
            cp16(d + GPL * 4, g_woh + gb);
            cp16(d + GPL * 6, g_wol + gb);
        }
    };

    load_stage(0, 0); cp_commit();

    for (int kt = 0; kt < 32; kt++) {
        const int buf = kt & 1;
        if (kt < 31) { load_stage(buf ^ 1, (kt + 1) * 32); cp_commit(); cp_wait<1>(); }
        else         { cp_wait<0>(); }
        __syncthreads();

        const __nv_bfloat16* Ah = sb + buf * GSTG;
        const __nv_bfloat16* Al = Ah + GPL;
        const __nv_bfloat16* Bh = Al + GPL;
        const __nv_bfloat16* Bl = Bh + GPL;

#pragma unroll
        for (int kf = 0; kf < 2; kf++) {
            unsigned ah[4][4], al[4][4];
#pragma unroll
            for (int i = 0; i < 4; i++) {
                int aoff = (wm + i * 16 + (lane & 15)) * GSTR + kf * 16 + (lane >> 4) * 8;
                ldmA(smem_u32(&Ah[aoff]), ah[i][0], ah[i][1], ah[i][2], ah[i][3]);
                ldmA(smem_u32(&Al[aoff]), al[i][0], al[i][1], al[i][2], al[i][3]);
            }
#pragma unroll
            for (int j = 0; j < 4; j++) {
                int boff = (wn + j * 8 + (lane & 7)) * GSTR + kf * 16 + ((lane >> 3) & 1) * 8;
                unsigned bh0, bh1, bl0, bl1;
                ldmB(smem_u32(&Bh[boff]), bh0, bh1);
                ldmB(smem_u32(&Bl[boff]), bl0, bl1);
#pragma unroll
                for (int i = 0; i < 4; i++) {
                    mma16816(acc[i][j], ah[i][0], ah[i][1], ah[i][2], ah[i][3], bh0, bh1);
                    mma16816(acc[i][j], ah[i][0], ah[i][1], ah[i][2], ah[i][3], bl0, bl1);
                    mma16816(acc[i][j], al[i][0], al[i][1], al[i][2], al[i][3], bh0, bh1);
                }
            }
        }
        __syncthreads();
    }

#pragma unroll
    for (int i = 0; i < 4; i++) {
#pragma unroll
        for (int j = 0; j < 4; j++) {
            int col = n0 + wn + j * 8 + (lane & 3) * 2;
            float b0 = bo[col], b1 = bo[col + 1];
#pragma unroll
            for (int hf = 0; hf < 2; hf++) {
                int r = m0 + wm + i * 16 + (lane >> 2) + hf * 8;
                float2 v;
                v.x = acc[i][j][2 * hf + 0] + b0;
                v.y = acc[i][j][2 * hf + 1] + b1;
                *(float2*)(out + (size_t)r * 1024 + col) = v;
            }
        }
    }
}

// ---------------------------------------------------------------------------
// d_out = [ out (4096*1024 fp32) | attn_weights (32*2048*2048 fp32) ]
// ---------------------------------------------------------------------------
extern "C" void kernel_launch(void* const* d_in, const int* in_sizes, int n_in,
                              void* d_out, int out_size)
{
    const float* query = (const float*)d_in[0];
    const float* wq    = (const float*)d_in[1];
    const float* bq    = (const float*)d_in[2];
    const float* wk    = (const float*)d_in[3];
    const float* bk    = (const float*)d_in[4];
    const float* wv    = (const float*)d_in[5];
    const float* bv    = (const float*)d_in[6];
    const float* wo    = (const float*)d_in[7];
    const float* bo    = (const float*)d_in[8];

    float* out   = (float*)d_out;
    float* w_out = out + (size_t)M_DIM * E_DIM;

    const int gemm_smem = 2 * GSTG * (int)sizeof(__nv_bfloat16);   // 81,920 B
    const int attn_smem = 10 * APL * (int)sizeof(__nv_bfloat16);   // 184,320 B
    cudaFuncSetAttribute(gemm_qkv,    cudaFuncAttributeMaxDynamicSharedMemorySize, gemm_smem);
    cudaFuncSetAttribute(attn_kernel, cudaFuncAttributeMaxDynamicSharedMemorySize, attn_smem);
    cudaFuncSetAttribute(gemm_out,    cudaFuncAttributeMaxDynamicSharedMemorySize, gemm_smem);

    split_all<<<8192, 256>>>(query, wq, wk, wv, wo);
    gemm_qkv<<<dim3(32, 24), 256, gemm_smem>>>(bq, bk, bv);
    attn_kernel<<<dim3(16, 32), 512, attn_smem>>>(w_out);
    gemm_out<<<dim3(32, 8), 256, gemm_smem>>>(bo, out);
}

// round 11
// speedup vs baseline: 4.0397x; 1.2742x over previous
#include <cuda_runtime.h>
#include <cuda_bf16.h>
#include <cuda_fp16.h>

// T=2048, B=2, E=1024, H=16, D=64
#define T_DIM 2048
#define E_DIM 1024
#define NH    32            // B*H
#define M_DIM 4096          // T*B
#define HD    (T_DIM * 64)  // per-head plane elems

// ---------------------------------------------------------------------------
// Device-global scratch (fp16 planes). Weights stored pre-scaled by 64 so the
// lo plane stays in fp16 normal range; epilogues divide by 64.
// ---------------------------------------------------------------------------
__device__ __half g_xh[(size_t)M_DIM * E_DIM];
__device__ __half g_wqh[1024 * 1024], g_wql[1024 * 1024];
__device__ __half g_wkh[1024 * 1024], g_wkl[1024 * 1024];
__device__ __half g_wvh[1024 * 1024], g_wvl[1024 * 1024];
__device__ __half g_woh[1024 * 1024], g_wol[1024 * 1024];
__device__ __half g_qh[(size_t)NH * HD], g_ql[(size_t)NH * HD];   // q unscaled (no 0.125)
__device__ __half g_kh[(size_t)NH * HD];                          // k hi only
__device__ __half g_vh[(size_t)NH * HD], g_vl[(size_t)NH * HD];
__device__ __half g_ah[(size_t)M_DIM * E_DIM];                    // attn result hi only

// ---------------------------------------------------------------------------
// Helpers
// ---------------------------------------------------------------------------
__device__ __forceinline__ unsigned smem_u32(const void* p) {
    return (unsigned)__cvta_generic_to_shared(p);
}
__device__ __forceinline__ void cp16(unsigned dst, const void* src) {
    asm volatile("cp.async.cg.shared.global [%0], [%1], 16;" :: "r"(dst), "l"(src));
}
__device__ __forceinline__ void cp_commit() {
    asm volatile("cp.async.commit_group;");
}
template <int N> __device__ __forceinline__ void cp_wait() {
    asm volatile("cp.async.wait_group %0;" :: "n"(N));
}
__device__ __forceinline__ void ldmA(unsigned addr, unsigned& r0, unsigned& r1,
                                     unsigned& r2, unsigned& r3) {
    asm volatile("ldmatrix.sync.aligned.m8n8.x4.shared.b16 {%0,%1,%2,%3}, [%4];"
                 : "=r"(r0), "=r"(r1), "=r"(r2), "=r"(r3) : "r"(addr));
}
__device__ __forceinline__ void ldmB(unsigned addr, unsigned& r0, unsigned& r1) {
    asm volatile("ldmatrix.sync.aligned.m8n8.x2.shared.b16 {%0,%1}, [%2];"
                 : "=r"(r0), "=r"(r1) : "r"(addr));
}
__device__ __forceinline__ void ldmBT(unsigned addr, unsigned& r0, unsigned& r1) {
    asm volatile("ldmatrix.sync.aligned.m8n8.x2.trans.shared.b16 {%0,%1}, [%2];"
                 : "=r"(r0), "=r"(r1) : "r"(addr));
}
// fp16 MMA, fp32 accumulate
__device__ __forceinline__ void mma16816(float* c, unsigned a0, unsigned a1,
                                         unsigned a2, unsigned a3,
                                         unsigned b0, unsigned b1) {
    asm volatile(
        "mma.sync.aligned.m16n8k16.row.col.f32.f16.f16.f32 "
        "{%0,%1,%2,%3}, {%4,%5,%6,%7}, {%8,%9}, {%0,%1,%2,%3};"
        : "+f"(c[0]), "+f"(c[1]), "+f"(c[2]), "+f"(c[3])
        : "r"(a0), "r"(a1), "r"(a2), "r"(a3), "r"(b0), "r"(b1));
}
__device__ __forceinline__ unsigned packh(__half a, __half b) {
    unsigned short ua = *(unsigned short*)&a, ub = *(unsigned short*)&b;
    return (unsigned)ua | ((unsigned)ub << 16);
}
__device__ __forceinline__ unsigned packh_f(float x, float y) {
    return packh(__float2half_rn(x), __float2half_rn(y));
}
__device__ __forceinline__ void split_pair_h(float x, float y, unsigned& hi, unsigned& lo) {
    __half xh = __float2half_rn(x), yh = __float2half_rn(y);
    float xr = x - __half2float(xh), yr = y - __half2float(yh);
    hi = packh(xh, yh);
    lo = packh(__float2half_rn(xr), __float2half_rn(yr));
}
__device__ __forceinline__ void stg_cs_f2(float* p, float a, float b) {
    asm volatile("st.global.cs.v2.f32 [%0], {%1,%2};" :: "l"(p), "f"(a), "f"(b));
}

// ---------------------------------------------------------------------------
// Split fp32 inputs into fp16 planes. X: hi only. Weights (x64): hi + lo.
// ---------------------------------------------------------------------------
__global__ __launch_bounds__(256) void split_all(
    const float* __restrict__ X, const float* __restrict__ wq,
    const float* __restrict__ wk, const float* __restrict__ wv,
    const float* __restrict__ wo)
{
    size_t i = (size_t)blockIdx.x * 256 + threadIdx.x;
    if (i < 1048576) {
        float4 v = ((const float4*)X)[i];
        ((unsigned*)g_xh)[i * 2]     = packh_f(v.x, v.y);
        ((unsigned*)g_xh)[i * 2 + 1] = packh_f(v.z, v.w);
        return;
    }
    size_t j = i - 1048576;
    int w = (int)(j >> 18);
    size_t off = j & 262143;
    const float* src; __half *dh, *dl;
    if      (w == 0) { src = wq; dh = g_wqh; dl = g_wql; }
    else if (w == 1) { src = wk; dh = g_wkh; dl = g_wkl; }
    else if (w == 2) { src = wv; dh = g_wvh; dl = g_wvl; }
    else             { src = wo; dh = g_woh; dl = g_wol; }
    float4 v = ((const float4*)src)[off];
    unsigned h0, l0, h1, l1;
    split_pair_h(v.x * 64.f, v.y * 64.f, h0, l0);
    split_pair_h(v.z * 64.f, v.w * 64.f, h1, l1);
    ((unsigned*)dh)[off * 2] = h0; ((unsigned*)dh)[off * 2 + 1] = h1;
    ((unsigned*)dl)[off * 2] = l0; ((unsigned*)dl)[off * 2 + 1] = l1;
}

// ---------------------------------------------------------------------------
// GEMM tile constants: 3 planes per stage (Ah, Bh, Bl), K-chunk 32.
// ---------------------------------------------------------------------------
#define GSTR  40
#define GPL   (128 * GSTR)
#define GSTG  (3 * GPL)

// ---------------------------------------------------------------------------
// QKV projection GEMM (fp16x2: full-A-hi x (Bh,Bl)), cp.async double-buffered.
// Stored q/k/v are UNSCALED by 0.125 (applied at score stage).
// ---------------------------------------------------------------------------
__global__ __launch_bounds__(256, 2) void gemm_qkv(
    const float* __restrict__ bq, const float* __restrict__ bk, const float* __restrict__ bv)
{
    extern __shared__ __half sb[];

    const int wsel = blockIdx.y >> 3;
    const int n0   = (blockIdx.y & 7) * 128;
    const int m0   = blockIdx.x * 128;

    const __half* Wh = (wsel == 0) ? g_wqh : (wsel == 1) ? g_wkh : g_wvh;
    const __half* Wl = (wsel == 0) ? g_wql : (wsel == 1) ? g_wkl : g_wvl;
    const float* bias = (wsel == 0) ? bq : (wsel == 1) ? bk : bv;
    __half* dh = (wsel == 0) ? g_qh : (wsel == 1) ? g_kh : g_vh;
    __half* dl = (wsel == 0) ? g_ql : (wsel == 2) ? g_vl : g_ql;  // k: unused
    const bool write_lo = (wsel != 1);

    const int tid = threadIdx.x, lane = tid & 31, wid = tid >> 5;
    const int wm = (wid >> 2) * 64, wn = (wid & 3) * 32;
    const int lr = tid >> 2;
    const int lc = (tid & 3) * 8;

    float acc[4][4][4];
#pragma unroll
    for (int i = 0; i < 4; i++)
#pragma unroll
        for (int j = 0; j < 4; j++)
#pragma unroll
            for (int q = 0; q < 4; q++) acc[i][j][q] = 0.f;

    auto load_stage = [&](int s, int k0) {
        __half* base = sb + s * GSTG;
#pragma unroll
        for (int rr = 0; rr < 128; rr += 64) {
            int row = rr + lr;
            size_t ga = (size_t)(m0 + row) * 1024 + k0 + lc;
            size_t gb = (size_t)(n0 + row) * 1024 + k0 + lc;
            unsigned d = smem_u32(base + row * GSTR + lc);
            cp16(d,           g_xh + ga);
            cp16(d + GPL * 2, Wh + gb);
            cp16(d + GPL * 4, Wl + gb);
        }
    };

    load_stage(0, 0); cp_commit();

    for (int kt = 0; kt < 32; kt++) {
        const int buf = kt & 1;
        if (kt < 31) { load_stage(buf ^ 1, (kt + 1) * 32); cp_commit(); cp_wait<1>(); }
        else         { cp_wait<0>(); }
        __syncthreads();

        const __half* Ah = sb + buf * GSTG;
        const __half* Bh = Ah + GPL;
        const __half* Bl = Bh + GPL;

#pragma unroll
        for (int kf = 0; kf < 2; kf++) {
            unsigned ah[4][4];
#pragma unroll
            for (int i = 0; i < 4; i++) {
                int aoff = (wm + i * 16 + (lane & 15)) * GSTR + kf * 16 + (lane >> 4) * 8;
                ldmA(smem_u32(&Ah[aoff]), ah[i][0], ah[i][1], ah[i][2], ah[i][3]);
            }
#pragma unroll
            for (int j = 0; j < 4; j++) {
                int boff = (wn + j * 8 + (lane & 7)) * GSTR + kf * 16 + ((lane >> 3) & 1) * 8;
                unsigned bh0, bh1, bl0, bl1;
                ldmB(smem_u32(&Bh[boff]), bh0, bh1);
                ldmB(smem_u32(&Bl[boff]), bl0, bl1);
#pragma unroll
                for (int i = 0; i < 4; i++) {
                    mma16816(acc[i][j], ah[i][0], ah[i][1], ah[i][2], ah[i][3], bh0, bh1);
                    mma16816(acc[i][j], ah[i][0], ah[i][1], ah[i][2], ah[i][3], bl0, bl1);
                }
            }
        }
        __syncthreads();
    }

    const float inv64 = 0.015625f;
#pragma unroll
    for (int i = 0; i < 4; i++) {
#pragma unroll
        for (int j = 0; j < 4; j++) {
            int col = n0 + wn + j * 8 + (lane & 3) * 2;
            float b0 = bias[col], b1 = bias[col + 1];
            int h = col >> 6, d = col & 63;
#pragma unroll
            for (int hf = 0; hf < 2; hf++) {
                int r = m0 + wm + i * 16 + (lane >> 2) + hf * 8;
                float v0 = acc[i][j][2 * hf + 0] * inv64 + b0;
                float v1 = acc[i][j][2 * hf + 1] * inv64 + b1;
                unsigned hi, lo;
                split_pair_h(v0, v1, hi, lo);
                size_t off = (size_t)((r & 1) * 16 + h) * HD + (size_t)(r >> 1) * 64 + d;
                *(unsigned*)&dh[off] = hi;
                if (write_lo) *(unsigned*)&dl[off] = lo;
            }
        }
    }
}

// ---------------------------------------------------------------------------
// Attention score half-tiles (fp16). Pass 2: (qh+ql)*kh = 2 MMA. Pass 1: qh*kh.
// ---------------------------------------------------------------------------
#define ASTR 72
#define APL  (128 * ASTR)

__device__ __forceinline__ void compute_scores2(
    const __half* Qh, const __half* Ql, const __half* Kh,
    int wr, int co, int lane, float acc[8][4])
{
#pragma unroll
    for (int j = 0; j < 8; j++)
#pragma unroll
        for (int q = 0; q < 4; q++) acc[j][q] = 0.f;

#pragma unroll
    for (int kf = 0; kf < 4; kf++) {
        unsigned ah[4], al[4];
        int qoff = (wr + (lane & 15)) * ASTR + kf * 16 + (lane >> 4) * 8;
        ldmA(smem_u32(&Qh[qoff]), ah[0], ah[1], ah[2], ah[3]);
        ldmA(smem_u32(&Ql[qoff]), al[0], al[1], al[2], al[3]);
#pragma unroll
        for (int j = 0; j < 8; j++) {
            int koff = (co + j * 8 + (lane & 7)) * ASTR + kf * 16 + ((lane >> 3) & 1) * 8;
            unsigned bh0, bh1;
            ldmB(smem_u32(&Kh[koff]), bh0, bh1);
            mma16816(acc[j], ah[0], ah[1], ah[2], ah[3], bh0, bh1);
            mma16816(acc[j], al[0], al[1], al[2], al[3], bh0, bh1);
        }
    }
}

__device__ __forceinline__ void compute_scores1(
    const __half* Qh, const __half* Kh,
    int wr, int co, int lane, float acc[8][4])
{
#pragma unroll
    for (int j = 0; j < 8; j++)
#pragma unroll
        for (int q = 0; q < 4; q++) acc[j][q] = 0.f;

#pragma unroll
    for (int kf = 0; kf < 4; kf++) {
        unsigned ah[4];
        int qoff = (wr + (lane & 15)) * ASTR + kf * 16 + (lane >> 4) * 8;
        ldmA(smem_u32(&Qh[qoff]), ah[0], ah[1], ah[2], ah[3]);
#pragma unroll
        for (int j = 0; j < 8; j++) {
            int koff = (co + j * 8 + (lane & 7)) * ASTR + kf * 16 + ((lane >> 3) & 1) * 8;
            unsigned bh0, bh1;
            ldmB(smem_u32(&Kh[koff]), bh0, bh1);
            mma16816(acc[j], ah[0], ah[1], ah[2], ah[3], bh0, bh1);
        }
    }
}

// ---------------------------------------------------------------------------
// Attention: per (head n, 128-row q-block). 512 threads / 16 warps.
// rowgrp = wid&7 (16 rows); column half hv = wid>>3 (64 of 128 cols).
// Stage planes: Kh, Vh, Vl (3). Scores scaled by 0.125 in fp32.
// ---------------------------------------------------------------------------
__global__ __launch_bounds__(512, 1) void attn_kernel(float* __restrict__ w_out)
{
    extern __shared__ __half sm[];
    __half* Qh = sm;
    __half* Ql = sm + APL;
    // stage s: sm + 2*APL + s*3*APL -> Kh, Vh, Vl

    const int n   = blockIdx.y;
    const int qb  = blockIdx.x * 128;
    const int tid = threadIdx.x, lane = tid & 31, wid = tid >> 5;
    const int rowgrp = wid & 7, hv = wid >> 3;
    const int wr = rowgrp * 16, co = hv * 64;

    const __half* qhg = g_qh + (size_t)n * HD + (size_t)qb * 64;
    const __half* qlg = g_ql + (size_t)n * HD + (size_t)qb * 64;
    const __half* khg = g_kh + (size_t)n * HD;
    const __half* vhg = g_vh + (size_t)n * HD;
    const __half* vlg = g_vl + (size_t)n * HD;

    for (int idx = tid; idx < 128 * 8; idx += 512) {
        int row = idx >> 3, c = (idx & 7) * 8;
        *(uint4*)&Qh[row * ASTR + c] = *(const uint4*)(qhg + (size_t)row * 64 + c);
        *(uint4*)&Ql[row * ASTR + c] = *(const uint4*)(qlg + (size_t)row * 64 + c);
    }

    const int ar = tid >> 3, ac = (tid & 7) * 8;

    auto load_k1 = [&](int s, int sc) {
        __half* kh = sm + 2 * APL + s * 3 * APL;
#pragma unroll
        for (int rr = 0; rr < 128; rr += 64) {
            int row = rr + ar;
            size_t g = (size_t)(sc * 128 + row) * 64 + ac;
            cp16(smem_u32(&kh[row * ASTR + ac]), khg + g);
        }
    };
    auto load_kv = [&](int s, int sc) {
        __half* kh = sm + 2 * APL + s * 3 * APL;
#pragma unroll
        for (int rr = 0; rr < 128; rr += 64) {
            int row = rr + ar;
            size_t g = (size_t)(sc * 128 + row) * 64 + ac;
            unsigned d = smem_u32(&kh[row * ASTR + ac]);
            cp16(d,           khg + g);
            cp16(d + APL * 2, vhg + g);
            cp16(d + APL * 4, vlg + g);
        }
    };

    float mv[2] = {-1e30f, -1e30f}, lv[2] = {0.f, 0.f};

    // ---------------- pass 1: per-half softmax statistics (qh*kh) ----------
    load_k1(0, 0); cp_commit();
    for (int sc = 0; sc < 16; sc++) {
        const int buf = sc & 1;
        if (sc < 15) { load_k1(buf ^ 1, sc + 1); cp_commit(); cp_wait<1>(); }
        else         { cp_wait<0>(); }
        __syncthreads();

        const __half* Kh = sm + 2 * APL + buf * 3 * APL;

        float acc[8][4];
        compute_scores1(Qh, Kh, wr, co, lane, acc);
        __syncthreads();

#pragma unroll
        for (int j = 0; j < 8; j++)
#pragma unroll
            for (int q = 0; q < 4; q++) acc[j][q] *= 0.125f;

#pragma unroll
        for (int hf = 0; hf < 2; hf++) {
            float mx = -1e30f;
#pragma unroll
            for (int j = 0; j < 8; j++)
                mx = fmaxf(mx, fmaxf(acc[j][2 * hf], acc[j][2 * hf + 1]));
            mx = fmaxf(mx, __shfl_xor_sync(0xffffffffu, mx, 1));
            mx = fmaxf(mx, __shfl_xor_sync(0xffffffffu, mx, 2));
            float mn = fmaxf(mv[hf], mx);
            float s = 0.f;
#pragma unroll
            for (int j = 0; j < 8; j++)
                s += __expf(acc[j][2 * hf] - mn) + __expf(acc[j][2 * hf + 1] - mn);
            s += __shfl_xor_sync(0xffffffffu, s, 1);
            s += __shfl_xor_sync(0xffffffffu, s, 2);
            lv[hf] = lv[hf] * __expf(mv[hf] - mn) + s;
            mv[hf] = mn;
        }
    }

    // ---------------- merge the two column-halves' stats ----------------
    float* st = (float*)(sm + 2 * APL);
    __syncthreads();
    if ((lane & 3) == 0) {
        int r_ = lane >> 2;
        st[((hv * 8 + rowgrp) * 16 + r_) * 2 + 0]     = mv[0];
        st[((hv * 8 + rowgrp) * 16 + r_) * 2 + 1]     = lv[0];
        st[((hv * 8 + rowgrp) * 16 + r_ + 8) * 2 + 0] = mv[1];
        st[((hv * 8 + rowgrp) * 16 + r_ + 8) * 2 + 1] = lv[1];
    }
    __syncthreads();
    float mfin[2], invl[2];
#pragma unroll
    for (int hf = 0; hf < 2; hf++) {
        int r_ = (lane >> 2) + hf * 8;
        float ma = st[((0 + rowgrp) * 16 + r_) * 2 + 0];
        float la = st[((0 + rowgrp) * 16 + r_) * 2 + 1];
        float mb = st[((8 + rowgrp) * 16 + r_) * 2 + 0];
        float lb = st[((8 + rowgrp) * 16 + r_) * 2 + 1];
        float mm = fmaxf(ma, mb);
        float ll = la * __expf(ma - mm) + lb * __expf(mb - mm);
        mfin[hf] = mm; invl[hf] = 1.0f / ll;
    }
    __syncthreads();

    float o[8][4];
#pragma unroll
    for (int j = 0; j < 8; j++)
#pragma unroll
        for (int q = 0; q < 4; q++) o[j][q] = 0.f;

    // ---------------- pass 2: weights out + partial P@V ----------------
    load_kv(0, 0); cp_commit();
    for (int sc = 0; sc < 16; sc++) {
        const int buf = sc & 1;
        if (sc < 15) { load_kv(buf ^ 1, sc + 1); cp_commit(); cp_wait<1>(); }
        else         { cp_wait<0>(); }
        __syncthreads();

        const __half* Kh = sm + 2 * APL + buf * 3 * APL;
        const __half* Vh = Kh + APL;
        const __half* Vl = Vh + APL;

        float acc[8][4];
        compute_scores2(Qh, Ql, Kh, wr, co, lane, acc);

        float* wb = w_out + (size_t)n * ((size_t)T_DIM * T_DIM)
                  + (size_t)(qb + wr + (lane >> 2)) * T_DIM + sc * 128 + co + (lane & 3) * 2;
#pragma unroll
        for (int j = 0; j < 8; j++) {
            float p0 = __expf(acc[j][0] * 0.125f - mfin[0]) * invl[0];
            float p1 = __expf(acc[j][1] * 0.125f - mfin[0]) * invl[0];
            float p2 = __expf(acc[j][2] * 0.125f - mfin[1]) * invl[1];
            float p3 = __expf(acc[j][3] * 0.125f - mfin[1]) * invl[1];
            acc[j][0] = p0; acc[j][1] = p1; acc[j][2] = p2; acc[j][3] = p3;
            stg_cs_f2(wb + j * 8, p0, p1);
            stg_cs_f2(wb + 8 * (size_t)T_DIM + j * 8, p2, p3);
        }

        // PV: p hi-only x (Vh + Vl)
#pragma unroll
        for (int g = 0; g < 4; g++) {
            unsigned a0 = packh_f(acc[2 * g][0],     acc[2 * g][1]);
            unsigned a1 = packh_f(acc[2 * g][2],     acc[2 * g][3]);
            unsigned a2 = packh_f(acc[2 * g + 1][0], acc[2 * g + 1][1]);
            unsigned a3 = packh_f(acc[2 * g + 1][2], acc[2 * g + 1][3]);
#pragma unroll
            for (int j = 0; j < 8; j++) {
                int voff = (co + g * 16 + (lane & 15)) * ASTR + j * 8;
                unsigned bh0, bh1, bl0, bl1;
                ldmBT(smem_u32(&Vh[voff]), bh0, bh1);
                ldmBT(smem_u32(&Vl[voff]), bl0, bl1);
                mma16816(o[j], a0, a1, a2, a3, bh0, bh1);
                mma16816(o[j], a0, a1, a2, a3, bl0, bl1);
            }
        }
        __syncthreads();
    }

    // ---------------- merge partial O across the two halves ----------------
    float* os = (float*)sm;
    if (hv == 1) {
#pragma unroll
        for (int j = 0; j < 8; j++)
#pragma unroll
            for (int q = 0; q < 4; q++)
                os[(rowgrp * 32 + lane) * 32 + j * 4 + q] = o[j][q];
    }
    __syncthreads();
    if (hv == 0) {
#pragma unroll
        for (int j = 0; j < 8; j++)
#pragma unroll
            for (int q = 0; q < 4; q++)
                o[j][q] += os[(rowgrp * 32 + lane) * 32 + j * 4 + q];

        const int bsel = n >> 4, h = n & 15;
        const int t0   = qb + wr + (lane >> 2);
        const int dcol = (lane & 3) * 2;
#pragma unroll
        for (int j = 0; j < 8; j++) {
            int d = j * 8 + dcol;
            size_t off = (size_t)(t0 * 2 + bsel) * E_DIM + h * 64 + d;
            *(unsigned*)&g_ah[off] = packh_f(o[j][0], o[j][1]);
            off = (size_t)((t0 + 8) * 2 + bsel) * E_DIM + h * 64 + d;
            *(unsigned*)&g_ah[off] = packh_f(o[j][2], o[j][3]);
        }
    }
}

// ---------------------------------------------------------------------------
// Output projection (fp16x2): out = attnx(hi) @ (woh+wol)^T / 64 + bo.
// ---------------------------------------------------------------------------
__global__ __launch_bounds__(256, 2) void gemm_out(
    const float* __restrict__ bo, float* __restrict__ out)
{
    extern __shared__ __half sb[];

    const int n0 = blockIdx.y * 128;
    const int m0 = blockIdx.x * 128;

    const int tid = threadIdx.x, lane = tid & 31, wid = tid >> 5;
    const int wm = (wid >> 2) * 64, wn = (wid & 3) * 32;
    const int lr = tid >> 2;
    const int lc = (tid & 3) * 8;

    float acc[4][4][4];
#pragma unroll
    for (int i = 0; i < 4; i++)
#pragma unroll
        for (int j = 0; j < 4; j++)
#pragma unroll
            for (int q = 0; q < 4; q++) acc[i][j][q] = 0.f;

    auto load_stage = [&](int s, int k0) {
        __half* base = sb + s * GSTG;
#pragma unroll
        for (int rr = 0; rr < 128; rr += 64) {
            int row = rr + lr;
            size_t ga = (size_t)(m0 + row) * 1024 + k0 + lc;
            size_t gb = (size_t)(n0 + row) * 1024 + k0 + lc;
            unsigned d = smem_u32(base + row * GSTR + lc);
            cp16(d,           g_ah + ga);
            cp16(d + GPL * 2, g_woh + gb);
            cp16(d + GPL * 4, g_wol + gb);
        }
    };

    load_stage(0, 0); cp_commit();

    for (int kt = 0; kt < 32; kt++) {
        const int buf = kt & 1;
        if (kt < 31) { load_stage(buf ^ 1, (kt + 1) * 32); cp_commit(); cp_wait<1>(); }
        else         { cp_wait<0>(); }
        __syncthreads();

        const __half* Ah = sb + buf * GSTG;
        const __half* Bh = Ah + GPL;
        const __half* Bl = Bh + GPL;

#pragma unroll
        for (int kf = 0; kf < 2; kf++) {
            unsigned ah[4][4];
#pragma unroll
            for (int i = 0; i < 4; i++) {
                int aoff = (wm + i * 16 + (lane & 15)) * GSTR + kf * 16 + (lane >> 4) * 8;
                ldmA(smem_u32(&Ah[aoff]), ah[i][0], ah[i][1], ah[i][2], ah[i][3]);
            }
#pragma unroll
            for (int j = 0; j < 4; j++) {
                int boff = (wn + j * 8 + (lane & 7)) * GSTR + kf * 16 + ((lane >> 3) & 1) * 8;
                unsigned bh0, bh1, bl0, bl1;
                ldmB(smem_u32(&Bh[boff]), bh0, bh1);
                ldmB(smem_u32(&Bl[boff]), bl0, bl1);
#pragma unroll
                for (int i = 0; i < 4; i++) {
                    mma16816(acc[i][j], ah[i][0], ah[i][1], ah[i][2], ah[i][3], bh0, bh1);
                    mma16816(acc[i][j], ah[i][0], ah[i][1], ah[i][2], ah[i][3], bl0, bl1);
                }
            }
        }
        __syncthreads();
    }

    const float inv64 = 0.015625f;
#pragma unroll
    for (int i = 0; i < 4; i++) {
#pragma unroll
        for (int j = 0; j < 4; j++) {
            int col = n0 + wn + j * 8 + (lane & 3) * 2;
            float b0 = bo[col], b1 = bo[col + 1];
#pragma unroll
            for (int hf = 0; hf < 2; hf++) {
                int r = m0 + wm + i * 16 + (lane >> 2) + hf * 8;
                float2 v;
                v.x = acc[i][j][2 * hf + 0] * inv64 + b0;
                v.y = acc[i][j][2 * hf + 1] * inv64 + b1;
                *(float2*)(out + (size_t)r * 1024 + col) = v;
            }
        }
    }
}

// ---------------------------------------------------------------------------
// d_out = [ out (4096*1024 fp32) | attn_weights (32*2048*2048 fp32) ]
// ---------------------------------------------------------------------------
extern "C" void kernel_launch(void* const* d_in, const int* in_sizes, int n_in,
                              void* d_out, int out_size)
{
    const float* query = (const float*)d_in[0];
    const float* wq    = (const float*)d_in[1];
    const float* bq    = (const float*)d_in[2];
    const float* wk    = (const float*)d_in[3];
    const float* bk    = (const float*)d_in[4];
    const float* wv    = (const float*)d_in[5];
    const float* bv    = (const float*)d_in[6];
    const float* wo    = (const float*)d_in[7];
    const float* bo    = (const float*)d_in[8];

    float* out   = (float*)d_out;
    float* w_out = out + (size_t)M_DIM * E_DIM;

    const int gemm_smem = 2 * GSTG * (int)sizeof(__half);   // 61,440 B
    const int attn_smem = 8 * APL * (int)sizeof(__half);    // 147,456 B
    cudaFuncSetAttribute(gemm_qkv,    cudaFuncAttributeMaxDynamicSharedMemorySize, gemm_smem);
    cudaFuncSetAttribute(attn_kernel, cudaFuncAttributeMaxDynamicSharedMemorySize, attn_smem);
    cudaFuncSetAttribute(gemm_out,    cudaFuncAttributeMaxDynamicSharedMemorySize, gemm_smem);

    split_all<<<8192, 256>>>(query, wq, wk, wv, wo);
    gemm_qkv<<<dim3(32, 24), 256, gemm_smem>>>(bq, bk, bv);
    attn_kernel<<<dim3(16, 32), 512, attn_smem>>>(w_out);
    gemm_out<<<dim3(32, 8), 256, gemm_smem>>>(bo, out);
}

// round 12
// speedup vs baseline: 4.2842x; 1.0605x over previous
#include <cuda_runtime.h>
#include <cuda_bf16.h>
#include <cuda_fp16.h>

// T=2048, B=2, E=1024, H=16, D=64
#define T_DIM 2048
#define E_DIM 1024
#define NH    32            // B*H
#define M_DIM 4096          // T*B
#define HD    (T_DIM * 64)  // per-head plane elems

// ---------------------------------------------------------------------------
// Device-global scratch (fp16 planes). Weights stored pre-scaled by 64 so the
// lo plane stays in fp16 normal range; epilogues divide by 64.
// ---------------------------------------------------------------------------
__device__ __half g_xh[(size_t)M_DIM * E_DIM];
__device__ __half g_wqh[1024 * 1024], g_wql[1024 * 1024];
__device__ __half g_wkh[1024 * 1024], g_wkl[1024 * 1024];
__device__ __half g_wvh[1024 * 1024], g_wvl[1024 * 1024];
__device__ __half g_woh[1024 * 1024], g_wol[1024 * 1024];
__device__ __half g_qh[(size_t)NH * HD], g_ql[(size_t)NH * HD];   // q unscaled (no 0.125)
__device__ __half g_kh[(size_t)NH * HD];                          // k hi only
__device__ __half g_vh[(size_t)NH * HD];                          // v hi only
__device__ __half g_ah[(size_t)M_DIM * E_DIM];                    // attn result hi only

// ---------------------------------------------------------------------------
// Helpers
// ---------------------------------------------------------------------------
__device__ __forceinline__ unsigned smem_u32(const void* p) {
    return (unsigned)__cvta_generic_to_shared(p);
}
__device__ __forceinline__ void cp16(unsigned dst, const void* src) {
    asm volatile("cp.async.cg.shared.global [%0], [%1], 16;" :: "r"(dst), "l"(src));
}
__device__ __forceinline__ void cp_commit() {
    asm volatile("cp.async.commit_group;");
}
template <int N> __device__ __forceinline__ void cp_wait() {
    asm volatile("cp.async.wait_group %0;" :: "n"(N));
}
__device__ __forceinline__ void ldmA(unsigned addr, unsigned& r0, unsigned& r1,
                                     unsigned& r2, unsigned& r3) {
    asm volatile("ldmatrix.sync.aligned.m8n8.x4.shared.b16 {%0,%1,%2,%3}, [%4];"
                 : "=r"(r0), "=r"(r1), "=r"(r2), "=r"(r3) : "r"(addr));
}
__device__ __forceinline__ void ldmB(unsigned addr, unsigned& r0, unsigned& r1) {
    asm volatile("ldmatrix.sync.aligned.m8n8.x2.shared.b16 {%0,%1}, [%2];"
                 : "=r"(r0), "=r"(r1) : "r"(addr));
}
__device__ __forceinline__ void ldmBT(unsigned addr, unsigned& r0, unsigned& r1) {
    asm volatile("ldmatrix.sync.aligned.m8n8.x2.trans.shared.b16 {%0,%1}, [%2];"
                 : "=r"(r0), "=r"(r1) : "r"(addr));
}
// fp16 MMA, fp32 accumulate
__device__ __forceinline__ void mma16816(float* c, unsigned a0, unsigned a1,
                                         unsigned a2, unsigned a3,
                                         unsigned b0, unsigned b1) {
    asm volatile(
        "mma.sync.aligned.m16n8k16.row.col.f32.f16.f16.f32 "
        "{%0,%1,%2,%3}, {%4,%5,%6,%7}, {%8,%9}, {%0,%1,%2,%3};"
        : "+f"(c[0]), "+f"(c[1]), "+f"(c[2]), "+f"(c[3])
        : "r"(a0), "r"(a1), "r"(a2), "r"(a3), "r"(b0), "r"(b1));
}
__device__ __forceinline__ unsigned packh(__half a, __half b) {
    unsigned short ua = *(unsigned short*)&a, ub = *(unsigned short*)&b;
    return (unsigned)ua | ((unsigned)ub << 16);
}
__device__ __forceinline__ unsigned packh_f(float x, float y) {
    return packh(__float2half_rn(x), __float2half_rn(y));
}
__device__ __forceinline__ void split_pair_h(float x, float y, unsigned& hi, unsigned& lo) {
    __half xh = __float2half_rn(x), yh = __float2half_rn(y);
    float xr = x - __half2float(xh), yr = y - __half2float(yh);
    hi = packh(xh, yh);
    lo = packh(__float2half_rn(xr), __float2half_rn(yr));
}
__device__ __forceinline__ void stg_cs_f2(float* p, float a, float b) {
    asm volatile("st.global.cs.v2.f32 [%0], {%1,%2};" :: "l"(p), "f"(a), "f"(b));
}

// ---------------------------------------------------------------------------
// Split fp32 inputs into fp16 planes. X: hi only. Weights (x64): hi + lo.
// ---------------------------------------------------------------------------
__global__ __launch_bounds__(256) void split_all(
    const float* __restrict__ X, const float* __restrict__ wq,
    const float* __restrict__ wk, const float* __restrict__ wv,
    const float* __restrict__ wo)
{
    size_t i = (size_t)blockIdx.x * 256 + threadIdx.x;
    if (i < 1048576) {
        float4 v = ((const float4*)X)[i];
        ((unsigned*)g_xh)[i * 2]     = packh_f(v.x, v.y);
        ((unsigned*)g_xh)[i * 2 + 1] = packh_f(v.z, v.w);
        return;
    }
    size_t j = i - 1048576;
    int w = (int)(j >> 18);
    size_t off = j & 262143;
    const float* src; __half *dh, *dl;
    if      (w == 0) { src = wq; dh = g_wqh; dl = g_wql; }
    else if (w == 1) { src = wk; dh = g_wkh; dl = g_wkl; }
    else if (w == 2) { src = wv; dh = g_wvh; dl = g_wvl; }
    else             { src = wo; dh = g_woh; dl = g_wol; }
    float4 v = ((const float4*)src)[off];
    unsigned h0, l0, h1, l1;
    split_pair_h(v.x * 64.f, v.y * 64.f, h0, l0);
    split_pair_h(v.z * 64.f, v.w * 64.f, h1, l1);
    ((unsigned*)dh)[off * 2] = h0; ((unsigned*)dh)[off * 2 + 1] = h1;
    ((unsigned*)dl)[off * 2] = l0; ((unsigned*)dl)[off * 2 + 1] = l1;
}

// ---------------------------------------------------------------------------
// GEMM tile constants: 3 planes per stage (Ah, Bh, Bl), K-chunk 32.
// ---------------------------------------------------------------------------
#define GSTR  40
#define GPL   (128 * GSTR)
#define GSTG  (3 * GPL)

// ---------------------------------------------------------------------------
// QKV projection GEMM (fp16x2: full-A-hi x (Bh,Bl)), cp.async double-buffered.
// Stored q/k/v are UNSCALED by 0.125 (applied at score stage).
// q keeps a lo plane (needed for score precision); k, v are hi-only.
// ---------------------------------------------------------------------------
__global__ __launch_bounds__(256, 2) void gemm_qkv(
    const float* __restrict__ bq, const float* __restrict__ bk, const float* __restrict__ bv)
{
    extern __shared__ __half sb[];

    const int wsel = blockIdx.y >> 3;
    const int n0   = (blockIdx.y & 7) * 128;
    const int m0   = blockIdx.x * 128;

    const __half* Wh = (wsel == 0) ? g_wqh : (wsel == 1) ? g_wkh : g_wvh;
    const __half* Wl = (wsel == 0) ? g_wql : (wsel == 1) ? g_wkl : g_wvl;
    const float* bias = (wsel == 0) ? bq : (wsel == 1) ? bk : bv;
    __half* dh = (wsel == 0) ? g_qh : (wsel == 1) ? g_kh : g_vh;
    const bool write_lo = (wsel == 0);

    const int tid = threadIdx.x, lane = tid & 31, wid = tid >> 5;
    const int wm = (wid >> 2) * 64, wn = (wid & 3) * 32;
    const int lr = tid >> 2;
    const int lc = (tid & 3) * 8;

    float acc[4][4][4];
#pragma unroll
    for (int i = 0; i < 4; i++)
#pragma unroll
        for (int j = 0; j < 4; j++)
#pragma unroll
            for (int q = 0; q < 4; q++) acc[i][j][q] = 0.f;

    auto load_stage = [&](int s, int k0) {
        __half* base = sb + s * GSTG;
#pragma unroll
        for (int rr = 0; rr < 128; rr += 64) {
            int row = rr + lr;
            size_t ga = (size_t)(m0 + row) * 1024 + k0 + lc;
            size_t gb = (size_t)(n0 + row) * 1024 + k0 + lc;
            unsigned d = smem_u32(base + row * GSTR + lc);
            cp16(d,           g_xh + ga);
            cp16(d + GPL * 2, Wh + gb);
            cp16(d + GPL * 4, Wl + gb);
        }
    };

    load_stage(0, 0); cp_commit();

    for (int kt = 0; kt < 32; kt++) {
        const int buf = kt & 1;
        if (kt < 31) { load_stage(buf ^ 1, (kt + 1) * 32); cp_commit(); cp_wait<1>(); }
        else         { cp_wait<0>(); }
        __syncthreads();

        const __half* Ah = sb + buf * GSTG;
        const __half* Bh = Ah + GPL;
        const __half* Bl = Bh + GPL;

#pragma unroll
        for (int kf = 0; kf < 2; kf++) {
            unsigned ah[4][4];
#pragma unroll
            for (int i = 0; i < 4; i++) {
                int aoff = (wm + i * 16 + (lane & 15)) * GSTR + kf * 16 + (lane >> 4) * 8;
                ldmA(smem_u32(&Ah[aoff]), ah[i][0], ah[i][1], ah[i][2], ah[i][3]);
            }
#pragma unroll
            for (int j = 0; j < 4; j++) {
                int boff = (wn + j * 8 + (lane & 7)) * GSTR + kf * 16 + ((lane >> 3) & 1) * 8;
                unsigned bh0, bh1, bl0, bl1;
                ldmB(smem_u32(&Bh[boff]), bh0, bh1);
                ldmB(smem_u32(&Bl[boff]), bl0, bl1);
#pragma unroll
                for (int i = 0; i < 4; i++) {
                    mma16816(acc[i][j], ah[i][0], ah[i][1], ah[i][2], ah[i][3], bh0, bh1);
                    mma16816(acc[i][j], ah[i][0], ah[i][1], ah[i][2], ah[i][3], bl0, bl1);
                }
            }
        }
        __syncthreads();
    }

    const float inv64 = 0.015625f;
#pragma unroll
    for (int i = 0; i < 4; i++) {
#pragma unroll
        for (int j = 0; j < 4; j++) {
            int col = n0 + wn + j * 8 + (lane & 3) * 2;
            float b0 = bias[col], b1 = bias[col + 1];
            int h = col >> 6, d = col & 63;
#pragma unroll
            for (int hf = 0; hf < 2; hf++) {
                int r = m0 + wm + i * 16 + (lane >> 2) + hf * 8;
                float v0 = acc[i][j][2 * hf + 0] * inv64 + b0;
                float v1 = acc[i][j][2 * hf + 1] * inv64 + b1;
                unsigned hi, lo;
                split_pair_h(v0, v1, hi, lo);
                size_t off = (size_t)((r & 1) * 16 + h) * HD + (size_t)(r >> 1) * 64 + d;
                *(unsigned*)&dh[off] = hi;
                if (write_lo) *(unsigned*)&g_ql[off] = lo;
            }
        }
    }
}

// ---------------------------------------------------------------------------
// Attention score half-tiles (fp16). Pass 2: (qh+ql)*kh = 2 MMA. Pass 1: qh*kh.
// ---------------------------------------------------------------------------
#define ASTR 72
#define APL  (128 * ASTR)

__device__ __forceinline__ void compute_scores2(
    const __half* Qh, const __half* Ql, const __half* Kh,
    int wr, int co, int lane, float acc[8][4])
{
#pragma unroll
    for (int j = 0; j < 8; j++)
#pragma unroll
        for (int q = 0; q < 4; q++) acc[j][q] = 0.f;

#pragma unroll
    for (int kf = 0; kf < 4; kf++) {
        unsigned ah[4], al[4];
        int qoff = (wr + (lane & 15)) * ASTR + kf * 16 + (lane >> 4) * 8;
        ldmA(smem_u32(&Qh[qoff]), ah[0], ah[1], ah[2], ah[3]);
        ldmA(smem_u32(&Ql[qoff]), al[0], al[1], al[2], al[3]);
#pragma unroll
        for (int j = 0; j < 8; j++) {
            int koff = (co + j * 8 + (lane & 7)) * ASTR + kf * 16 + ((lane >> 3) & 1) * 8;
            unsigned bh0, bh1;
            ldmB(smem_u32(&Kh[koff]), bh0, bh1);
            mma16816(acc[j], ah[0], ah[1], ah[2], ah[3], bh0, bh1);
            mma16816(acc[j], al[0], al[1], al[2], al[3], bh0, bh1);
        }
    }
}

__device__ __forceinline__ void compute_scores1(
    const __half* Qh, const __half* Kh,
    int wr, int co, int lane, float acc[8][4])
{
#pragma unroll
    for (int j = 0; j < 8; j++)
#pragma unroll
        for (int q = 0; q < 4; q++) acc[j][q] = 0.f;

#pragma unroll
    for (int kf = 0; kf < 4; kf++) {
        unsigned ah[4];
        int qoff = (wr + (lane & 15)) * ASTR + kf * 16 + (lane >> 4) * 8;
        ldmA(smem_u32(&Qh[qoff]), ah[0], ah[1], ah[2], ah[3]);
#pragma unroll
        for (int j = 0; j < 8; j++) {
            int koff = (co + j * 8 + (lane & 7)) * ASTR + kf * 16 + ((lane >> 3) & 1) * 8;
            unsigned bh0, bh1;
            ldmB(smem_u32(&Kh[koff]), bh0, bh1);
            mma16816(acc[j], ah[0], ah[1], ah[2], ah[3], bh0, bh1);
        }
    }
}

// ---------------------------------------------------------------------------
// Attention: per (head n, 128-row q-block). 512 threads / 16 warps.
// rowgrp = wid&7 (16 rows); column half hv = wid>>3 (64 of 128 cols).
// Stage planes: Kh, Vh (2). Scores scaled by 0.125 in fp32. PV: p x Vh (1 MMA).
// ---------------------------------------------------------------------------
__global__ __launch_bounds__(512, 1) void attn_kernel(float* __restrict__ w_out)
{
    extern __shared__ __half sm[];
    __half* Qh = sm;
    __half* Ql = sm + APL;
    // stage s: sm + 2*APL + s*2*APL -> Kh, Vh

    const int n   = blockIdx.y;
    const int qb  = blockIdx.x * 128;
    const int tid = threadIdx.x, lane = tid & 31, wid = tid >> 5;
    const int rowgrp = wid & 7, hv = wid >> 3;
    const int wr = rowgrp * 16, co = hv * 64;

    const __half* qhg = g_qh + (size_t)n * HD + (size_t)qb * 64;
    const __half* qlg = g_ql + (size_t)n * HD + (size_t)qb * 64;
    const __half* khg = g_kh + (size_t)n * HD;
    const __half* vhg = g_vh + (size_t)n * HD;

    for (int idx = tid; idx < 128 * 8; idx += 512) {
        int row = idx >> 3, c = (idx & 7) * 8;
        *(uint4*)&Qh[row * ASTR + c] = *(const uint4*)(qhg + (size_t)row * 64 + c);
        *(uint4*)&Ql[row * ASTR + c] = *(const uint4*)(qlg + (size_t)row * 64 + c);
    }

    const int ar = tid >> 3, ac = (tid & 7) * 8;

    auto load_k1 = [&](int s, int sc) {
        __half* kh = sm + 2 * APL + s * 2 * APL;
#pragma unroll
        for (int rr = 0; rr < 128; rr += 64) {
            int row = rr + ar;
            size_t g = (size_t)(sc * 128 + row) * 64 + ac;
            cp16(smem_u32(&kh[row * ASTR + ac]), khg + g);
        }
    };
    auto load_kv = [&](int s, int sc) {
        __half* kh = sm + 2 * APL + s * 2 * APL;
#pragma unroll
        for (int rr = 0; rr < 128; rr += 64) {
            int row = rr + ar;
            size_t g = (size_t)(sc * 128 + row) * 64 + ac;
            unsigned d = smem_u32(&kh[row * ASTR + ac]);
            cp16(d,           khg + g);
            cp16(d + APL * 2, vhg + g);
        }
    };

    float mv[2] = {-1e30f, -1e30f}, lv[2] = {0.f, 0.f};

    // ---------------- pass 1: per-half softmax statistics (qh*kh) ----------
    load_k1(0, 0); cp_commit();
    for (int sc = 0; sc < 16; sc++) {
        const int buf = sc & 1;
        if (sc < 15) { load_k1(buf ^ 1, sc + 1); cp_commit(); cp_wait<1>(); }
        else         { cp_wait<0>(); }
        __syncthreads();

        const __half* Kh = sm + 2 * APL + buf * 2 * APL;

        float acc[8][4];
        compute_scores1(Qh, Kh, wr, co, lane, acc);
        __syncthreads();

#pragma unroll
        for (int j = 0; j < 8; j++)
#pragma unroll
            for (int q = 0; q < 4; q++) acc[j][q] *= 0.125f;

#pragma unroll
        for (int hf = 0; hf < 2; hf++) {
            float mx = -1e30f;
#pragma unroll
            for (int j = 0; j < 8; j++)
                mx = fmaxf(mx, fmaxf(acc[j][2 * hf], acc[j][2 * hf + 1]));
            mx = fmaxf(mx, __shfl_xor_sync(0xffffffffu, mx, 1));
            mx = fmaxf(mx, __shfl_xor_sync(0xffffffffu, mx, 2));
            float mn = fmaxf(mv[hf], mx);
            float s = 0.f;
#pragma unroll
            for (int j = 0; j < 8; j++)
                s += __expf(acc[j][2 * hf] - mn) + __expf(acc[j][2 * hf + 1] - mn);
            s += __shfl_xor_sync(0xffffffffu, s, 1);
            s += __shfl_xor_sync(0xffffffffu, s, 2);
            lv[hf] = lv[hf] * __expf(mv[hf] - mn) + s;
            mv[hf] = mn;
        }
    }

    // ---------------- merge the two column-halves' stats ----------------
    float* st = (float*)(sm + 2 * APL);
    __syncthreads();
    if ((lane & 3) == 0) {
        int r_ = lane >> 2;
        st[((hv * 8 + rowgrp) * 16 + r_) * 2 + 0]     = mv[0];
        st[((hv * 8 + rowgrp) * 16 + r_) * 2 + 1]     = lv[0];
        st[((hv * 8 + rowgrp) * 16 + r_ + 8) * 2 + 0] = mv[1];
        st[((hv * 8 + rowgrp) * 16 + r_ + 8) * 2 + 1] = lv[1];
    }
    __syncthreads();
    float mfin[2], invl[2];
#pragma unroll
    for (int hf = 0; hf < 2; hf++) {
        int r_ = (lane >> 2) + hf * 8;
        float ma = st[((0 + rowgrp) * 16 + r_) * 2 + 0];
        float la = st[((0 + rowgrp) * 16 + r_) * 2 + 1];
        float mb = st[((8 + rowgrp) * 16 + r_) * 2 + 0];
        float lb = st[((8 + rowgrp) * 16 + r_) * 2 + 1];
        float mm = fmaxf(ma, mb);
        float ll = la * __expf(ma - mm) + lb * __expf(mb - mm);
        mfin[hf] = mm; invl[hf] = 1.0f / ll;
    }
    __syncthreads();

    float o[8][4];
#pragma unroll
    for (int j = 0; j < 8; j++)
#pragma unroll
        for (int q = 0; q < 4; q++) o[j][q] = 0.f;

    // ---------------- pass 2: weights out + partial P@V ----------------
    load_kv(0, 0); cp_commit();
    for (int sc = 0; sc < 16; sc++) {
        const int buf = sc & 1;
        if (sc < 15) { load_kv(buf ^ 1, sc + 1); cp_commit(); cp_wait<1>(); }
        else         { cp_wait<0>(); }
        __syncthreads();

        const __half* Kh = sm + 2 * APL + buf * 2 * APL;
        const __half* Vh = Kh + APL;

        float acc[8][4];
        compute_scores2(Qh, Ql, Kh, wr, co, lane, acc);

        float* wb = w_out + (size_t)n * ((size_t)T_DIM * T_DIM)
                  + (size_t)(qb + wr + (lane >> 2)) * T_DIM + sc * 128 + co + (lane & 3) * 2;
#pragma unroll
        for (int j = 0; j < 8; j++) {
            float p0 = __expf(acc[j][0] * 0.125f - mfin[0]) * invl[0];
            float p1 = __expf(acc[j][1] * 0.125f - mfin[0]) * invl[0];
            float p2 = __expf(acc[j][2] * 0.125f - mfin[1]) * invl[1];
            float p3 = __expf(acc[j][3] * 0.125f - mfin[1]) * invl[1];
            acc[j][0] = p0; acc[j][1] = p1; acc[j][2] = p2; acc[j][3] = p3;
            stg_cs_f2(wb + j * 8, p0, p1);
            stg_cs_f2(wb + 8 * (size_t)T_DIM + j * 8, p2, p3);
        }

        // PV: p hi-only x Vh (single MMA)
#pragma unroll
        for (int g = 0; g < 4; g++) {
            unsigned a0 = packh_f(acc[2 * g][0],     acc[2 * g][1]);
            unsigned a1 = packh_f(acc[2 * g][2],     acc[2 * g][3]);
            unsigned a2 = packh_f(acc[2 * g + 1][0], acc[2 * g + 1][1]);
            unsigned a3 = packh_f(acc[2 * g + 1][2], acc[2 * g + 1][3]);
#pragma unroll
            for (int j = 0; j < 8; j++) {
                int voff = (co + g * 16 + (lane & 15)) * ASTR + j * 8;
                unsigned bh0, bh1;
                ldmBT(smem_u32(&Vh[voff]), bh0, bh1);
                mma16816(o[j], a0, a1, a2, a3, bh0, bh1);
            }
        }
        __syncthreads();
    }

    // ---------------- merge partial O across the two halves ----------------
    float* os = (float*)sm;
    if (hv == 1) {
#pragma unroll
        for (int j = 0; j < 8; j++)
#pragma unroll
            for (int q = 0; q < 4; q++)
                os[(rowgrp * 32 + lane) * 32 + j * 4 + q] = o[j][q];
    }
    __syncthreads();
    if (hv == 0) {
#pragma unroll
        for (int j = 0; j < 8; j++)
#pragma unroll
            for (int q = 0; q < 4; q++)
                o[j][q] += os[(rowgrp * 32 + lane) * 32 + j * 4 + q];

        const int bsel = n >> 4, h = n & 15;
        const int t0   = qb + wr + (lane >> 2);
        const int dcol = (lane & 3) * 2;
#pragma unroll
        for (int j = 0; j < 8; j++) {
            int d = j * 8 + dcol;
            size_t off = (size_t)(t0 * 2 + bsel) * E_DIM + h * 64 + d;
            *(unsigned*)&g_ah[off] = packh_f(o[j][0], o[j][1]);
            off = (size_t)((t0 + 8) * 2 + bsel) * E_DIM + h * 64 + d;
            *(unsigned*)&g_ah[off] = packh_f(o[j][2], o[j][3]);
        }
    }
}

// ---------------------------------------------------------------------------
// Output projection (fp16x2): out = attnx(hi) @ (woh+wol)^T / 64 + bo.
// ---------------------------------------------------------------------------
__global__ __launch_bounds__(256, 2) void gemm_out(
    const float* __restrict__ bo, float* __restrict__ out)
{
    extern __shared__ __half sb[];

    const int n0 = blockIdx.y * 128;
    const int m0 = blockIdx.x * 128;

    const int tid = threadIdx.x, lane = tid & 31, wid = tid >> 5;
    const int wm = (wid >> 2) * 64, wn = (wid & 3) * 32;
    const int lr = tid >> 2;
    const int lc = (tid & 3) * 8;

    float acc[4][4][4];
#pragma unroll
    for (int i = 0; i < 4; i++)
#pragma unroll
        for (int j = 0; j < 4; j++)
#pragma unroll
            for (int q = 0; q < 4; q++) acc[i][j][q] = 0.f;

    auto load_stage = [&](int s, int k0) {
        __half* base = sb + s * GSTG;
#pragma unroll
        for (int rr = 0; rr < 128; rr += 64) {
            int row = rr + lr;
            size_t ga = (size_t)(m0 + row) * 1024 + k0 + lc;
            size_t gb = (size_t)(n0 + row) * 1024 + k0 + lc;
            unsigned d = smem_u32(base + row * GSTR + lc);
            cp16(d,           g_ah + ga);
            cp16(d + GPL * 2, g_woh + gb);
            cp16(d + GPL * 4, g_wol + gb);
        }
    };

    load_stage(0, 0); cp_commit();

    for (int kt = 0; kt < 32; kt++) {
        const int buf = kt & 1;
        if (kt < 31) { load_stage(buf ^ 1, (kt + 1) * 32); cp_commit(); cp_wait<1>(); }
        else         { cp_wait<0>(); }
        __syncthreads();

        const __half* Ah = sb + buf * GSTG;
        const __half* Bh = Ah + GPL;
        const __half* Bl = Bh + GPL;

#pragma unroll
        for (int kf = 0; kf < 2; kf++) {
            unsigned ah[4][4];
#pragma unroll
            for (int i = 0; i < 4; i++) {
                int aoff = (wm + i * 16 + (lane & 15)) * GSTR + kf * 16 + (lane >> 4) * 8;
                ldmA(smem_u32(&Ah[aoff]), ah[i][0], ah[i][1], ah[i][2], ah[i][3]);
            }
#pragma unroll
            for (int j = 0; j < 4; j++) {
                int boff = (wn + j * 8 + (lane & 7)) * GSTR + kf * 16 + ((lane >> 3) & 1) * 8;
                unsigned bh0, bh1, bl0, bl1;
                ldmB(smem_u32(&Bh[boff]), bh0, bh1);
                ldmB(smem_u32(&Bl[boff]), bl0, bl1);
#pragma unroll
                for (int i = 0; i < 4; i++) {
                    mma16816(acc[i][j], ah[i][0], ah[i][1], ah[i][2], ah[i][3], bh0, bh1);
                    mma16816(acc[i][j], ah[i][0], ah[i][1], ah[i][2], ah[i][3], bl0, bl1);
                }
            }
        }
        __syncthreads();
    }

    const float inv64 = 0.015625f;
#pragma unroll
    for (int i = 0; i < 4; i++) {
#pragma unroll
        for (int j = 0; j < 4; j++) {
            int col = n0 + wn + j * 8 + (lane & 3) * 2;
            float b0 = bo[col], b1 = bo[col + 1];
#pragma unroll
            for (int hf = 0; hf < 2; hf++) {
                int r = m0 + wm + i * 16 + (lane >> 2) + hf * 8;
                float2 v;
                v.x = acc[i][j][2 * hf + 0] * inv64 + b0;
                v.y = acc[i][j][2 * hf + 1] * inv64 + b1;
                *(float2*)(out + (size_t)r * 1024 + col) = v;
            }
        }
    }
}

// ---------------------------------------------------------------------------
// d_out = [ out (4096*1024 fp32) | attn_weights (32*2048*2048 fp32) ]
// ---------------------------------------------------------------------------
extern "C" void kernel_launch(void* const* d_in, const int* in_sizes, int n_in,
                              void* d_out, int out_size)
{
    const float* query = (const float*)d_in[0];
    const float* wq    = (const float*)d_in[1];
    const float* bq    = (const float*)d_in[2];
    const float* wk    = (const float*)d_in[3];
    const float* bk    = (const float*)d_in[4];
    const float* wv    = (const float*)d_in[5];
    const float* bv    = (const float*)d_in[6];
    const float* wo    = (const float*)d_in[7];
    const float* bo    = (const float*)d_in[8];

    float* out   = (float*)d_out;
    float* w_out = out + (size_t)M_DIM * E_DIM;

    const int gemm_smem = 2 * GSTG * (int)sizeof(__half);   // 61,440 B
    const int attn_smem = 6 * APL * (int)sizeof(__half);    // 110,592 B
    cudaFuncSetAttribute(gemm_qkv,    cudaFuncAttributeMaxDynamicSharedMemorySize, gemm_smem);
    cudaFuncSetAttribute(attn_kernel, cudaFuncAttributeMaxDynamicSharedMemorySize, attn_smem);
    cudaFuncSetAttribute(gemm_out,    cudaFuncAttributeMaxDynamicSharedMemorySize, gemm_smem);

    split_all<<<8192, 256>>>(query, wq, wk, wv, wo);
    gemm_qkv<<<dim3(32, 24), 256, gemm_smem>>>(bq, bk, bv);
    attn_kernel<<<dim3(16, 32), 512, attn_smem>>>(w_out);
    gemm_out<<<dim3(32, 8), 256, gemm_smem>>>(bo, out);
}

// round 13
// speedup vs baseline: 4.5574x; 1.0638x over previous
#include <cuda_runtime.h>
#include <cuda_bf16.h>
#include <cuda_fp16.h>

// T=2048, B=2, E=1024, H=16, D=64
#define T_DIM 2048
#define E_DIM 1024
#define NH    32            // B*H
#define M_DIM 4096          // T*B
#define HD    (T_DIM * 64)  // per-head plane elems

// 0.125 * log2(e): score scaling folded into exp2
#define EC 0.18033688011112042f

// ---------------------------------------------------------------------------
// Device-global scratch (fp16 planes). Weights stored pre-scaled by 64 so the
// lo plane stays in fp16 normal range; epilogues divide by 64.
// ---------------------------------------------------------------------------
__device__ __half g_xh[(size_t)M_DIM * E_DIM];
__device__ __half g_wqh[1024 * 1024], g_wql[1024 * 1024];
__device__ __half g_wkh[1024 * 1024], g_wkl[1024 * 1024];
__device__ __half g_wvh[1024 * 1024], g_wvl[1024 * 1024];
__device__ __half g_woh[1024 * 1024], g_wol[1024 * 1024];
__device__ __half g_qh[(size_t)NH * HD], g_ql[(size_t)NH * HD];   // q unscaled
__device__ __half g_kh[(size_t)NH * HD];                          // k hi only
__device__ __half g_vh[(size_t)NH * HD];                          // v hi only
__device__ __half g_ah[(size_t)M_DIM * E_DIM];                    // attn result hi only

// ---------------------------------------------------------------------------
// Helpers
// ---------------------------------------------------------------------------
__device__ __forceinline__ unsigned smem_u32(const void* p) {
    return (unsigned)__cvta_generic_to_shared(p);
}
__device__ __forceinline__ void cp16(unsigned dst, const void* src) {
    asm volatile("cp.async.cg.shared.global [%0], [%1], 16;" :: "r"(dst), "l"(src));
}
__device__ __forceinline__ void cp_commit() {
    asm volatile("cp.async.commit_group;");
}
template <int N> __device__ __forceinline__ void cp_wait() {
    asm volatile("cp.async.wait_group %0;" :: "n"(N));
}
__device__ __forceinline__ void ldmA(unsigned addr, unsigned& r0, unsigned& r1,
                                     unsigned& r2, unsigned& r3) {
    asm volatile("ldmatrix.sync.aligned.m8n8.x4.shared.b16 {%0,%1,%2,%3}, [%4];"
                 : "=r"(r0), "=r"(r1), "=r"(r2), "=r"(r3) : "r"(addr));
}
__device__ __forceinline__ void ldmB(unsigned addr, unsigned& r0, unsigned& r1) {
    asm volatile("ldmatrix.sync.aligned.m8n8.x2.shared.b16 {%0,%1}, [%2];"
                 : "=r"(r0), "=r"(r1) : "r"(addr));
}
__device__ __forceinline__ void ldmBT(unsigned addr, unsigned& r0, unsigned& r1) {
    asm volatile("ldmatrix.sync.aligned.m8n8.x2.trans.shared.b16 {%0,%1}, [%2];"
                 : "=r"(r0), "=r"(r1) : "r"(addr));
}
// fp16 MMA, fp32 accumulate
__device__ __forceinline__ void mma16816(float* c, unsigned a0, unsigned a1,
                                         unsigned a2, unsigned a3,
                                         unsigned b0, unsigned b1) {
    asm volatile(
        "mma.sync.aligned.m16n8k16.row.col.f32.f16.f16.f32 "
        "{%0,%1,%2,%3}, {%4,%5,%6,%7}, {%8,%9}, {%0,%1,%2,%3};"
        : "+f"(c[0]), "+f"(c[1]), "+f"(c[2]), "+f"(c[3])
        : "r"(a0), "r"(a1), "r"(a2), "r"(a3), "r"(b0), "r"(b1));
}
__device__ __forceinline__ unsigned packh(__half a, __half b) {
    unsigned short ua = *(unsigned short*)&a, ub = *(unsigned short*)&b;
    return (unsigned)ua | ((unsigned)ub << 16);
}
__device__ __forceinline__ unsigned packh_f(float x, float y) {
    return packh(__float2half_rn(x), __float2half_rn(y));
}
__device__ __forceinline__ void split_pair_h(float x, float y, unsigned& hi, unsigned& lo) {
    __half xh = __float2half_rn(x), yh = __float2half_rn(y);
    float xr = x - __half2float(xh), yr = y - __half2float(yh);
    hi = packh(xh, yh);
    lo = packh(__float2half_rn(xr), __float2half_rn(yr));
}
__device__ __forceinline__ void stg_cs_f2(float* p, float a, float b) {
    asm volatile("st.global.cs.v2.f32 [%0], {%1,%2};" :: "l"(p), "f"(a), "f"(b));
}

// ---------------------------------------------------------------------------
// Split fp32 inputs into fp16 planes. X: hi only. Weights (x64): hi + lo.
// ---------------------------------------------------------------------------
__global__ __launch_bounds__(256) void split_all(
    const float* __restrict__ X, const float* __restrict__ wq,
    const float* __restrict__ wk, const float* __restrict__ wv,
    const float* __restrict__ wo)
{
    size_t i = (size_t)blockIdx.x * 256 + threadIdx.x;
    if (i < 1048576) {
        float4 v = ((const float4*)X)[i];
        ((unsigned*)g_xh)[i * 2]     = packh_f(v.x, v.y);
        ((unsigned*)g_xh)[i * 2 + 1] = packh_f(v.z, v.w);
        return;
    }
    size_t j = i - 1048576;
    int w = (int)(j >> 18);
    size_t off = j & 262143;
    const float* src; __half *dh, *dl;
    if      (w == 0) { src = wq; dh = g_wqh; dl = g_wql; }
    else if (w == 1) { src = wk; dh = g_wkh; dl = g_wkl; }
    else if (w == 2) { src = wv; dh = g_wvh; dl = g_wvl; }
    else             { src = wo; dh = g_woh; dl = g_wol; }
    float4 v = ((const float4*)src)[off];
    unsigned h0, l0, h1, l1;
    split_pair_h(v.x * 64.f, v.y * 64.f, h0, l0);
    split_pair_h(v.z * 64.f, v.w * 64.f, h1, l1);
    ((unsigned*)dh)[off * 2] = h0; ((unsigned*)dh)[off * 2 + 1] = h1;
    ((unsigned*)dl)[off * 2] = l0; ((unsigned*)dl)[off * 2 + 1] = l1;
}

// ---------------------------------------------------------------------------
// GEMM tile constants: 3 planes per stage (Ah, Bh, Bl), K-chunk 32, 3 stages.
// ---------------------------------------------------------------------------
#define GSTR  40
#define GPL   (128 * GSTR)
#define GSTG  (3 * GPL)

// ---------------------------------------------------------------------------
// QKV projection GEMM (fp16x2), cp.async 3-stage, single sync per k-tile.
// ---------------------------------------------------------------------------
__global__ __launch_bounds__(256, 2) void gemm_qkv(
    const float* __restrict__ bq, const float* __restrict__ bk, const float* __restrict__ bv)
{
    extern __shared__ __half sb[];

    const int wsel = blockIdx.y >> 3;
    const int n0   = (blockIdx.y & 7) * 128;
    const int m0   = blockIdx.x * 128;

    const __half* Wh = (wsel == 0) ? g_wqh : (wsel == 1) ? g_wkh : g_wvh;
    const __half* Wl = (wsel == 0) ? g_wql : (wsel == 1) ? g_wkl : g_wvl;
    const float* bias = (wsel == 0) ? bq : (wsel == 1) ? bk : bv;
    __half* dh = (wsel == 0) ? g_qh : (wsel == 1) ? g_kh : g_vh;
    const bool write_lo = (wsel == 0);

    const int tid = threadIdx.x, lane = tid & 31, wid = tid >> 5;
    const int wm = (wid >> 2) * 64, wn = (wid & 3) * 32;
    const int lr = tid >> 2;
    const int lc = (tid & 3) * 8;

    float acc[4][4][4];
#pragma unroll
    for (int i = 0; i < 4; i++)
#pragma unroll
        for (int j = 0; j < 4; j++)
#pragma unroll
            for (int q = 0; q < 4; q++) acc[i][j][q] = 0.f;

    auto load_stage = [&](int s, int k0) {
        __half* base = sb + s * GSTG;
#pragma unroll
        for (int rr = 0; rr < 128; rr += 64) {
            int row = rr + lr;
            size_t ga = (size_t)(m0 + row) * 1024 + k0 + lc;
            size_t gb = (size_t)(n0 + row) * 1024 + k0 + lc;
            unsigned d = smem_u32(base + row * GSTR + lc);
            cp16(d,           g_xh + ga);
            cp16(d + GPL * 2, Wh + gb);
            cp16(d + GPL * 4, Wl + gb);
        }
    };

    load_stage(0, 0);  cp_commit();
    load_stage(1, 32); cp_commit();

    for (int kt = 0; kt < 32; kt++) {
        if (kt < 31) cp_wait<1>(); else cp_wait<0>();
        __syncthreads();
        if (kt + 2 < 32) { load_stage((kt + 2) % 3, (kt + 2) * 32); cp_commit(); }

        const __half* Ah = sb + (kt % 3) * GSTG;
        const __half* Bh = Ah + GPL;
        const __half* Bl = Bh + GPL;

#pragma unroll
        for (int kf = 0; kf < 2; kf++) {
            unsigned ah[4][4];
#pragma unroll
            for (int i = 0; i < 4; i++) {
                int aoff = (wm + i * 16 + (lane & 15)) * GSTR + kf * 16 + (lane >> 4) * 8;
                ldmA(smem_u32(&Ah[aoff]), ah[i][0], ah[i][1], ah[i][2], ah[i][3]);
            }
#pragma unroll
            for (int j = 0; j < 4; j++) {
                int boff = (wn + j * 8 + (lane & 7)) * GSTR + kf * 16 + ((lane >> 3) & 1) * 8;
                unsigned bh0, bh1, bl0, bl1;
                ldmB(smem_u32(&Bh[boff]), bh0, bh1);
                ldmB(smem_u32(&Bl[boff]), bl0, bl1);
#pragma unroll
                for (int i = 0; i < 4; i++) {
                    mma16816(acc[i][j], ah[i][0], ah[i][1], ah[i][2], ah[i][3], bh0, bh1);
                    mma16816(acc[i][j], ah[i][0], ah[i][1], ah[i][2], ah[i][3], bl0, bl1);
                }
            }
        }
    }

    const float inv64 = 0.015625f;
#pragma unroll
    for (int i = 0; i < 4; i++) {
#pragma unroll
        for (int j = 0; j < 4; j++) {
            int col = n0 + wn + j * 8 + (lane & 3) * 2;
            float b0 = bias[col], b1 = bias[col + 1];
            int h = col >> 6, d = col & 63;
#pragma unroll
            for (int hf = 0; hf < 2; hf++) {
                int r = m0 + wm + i * 16 + (lane >> 2) + hf * 8;
                float v0 = acc[i][j][2 * hf + 0] * inv64 + b0;
                float v1 = acc[i][j][2 * hf + 1] * inv64 + b1;
                unsigned hi, lo;
                split_pair_h(v0, v1, hi, lo);
                size_t off = (size_t)((r & 1) * 16 + h) * HD + (size_t)(r >> 1) * 64 + d;
                *(unsigned*)&dh[off] = hi;
                if (write_lo) *(unsigned*)&g_ql[off] = lo;
            }
        }
    }
}

// ---------------------------------------------------------------------------
// Attention score half-tiles (fp16).
// ---------------------------------------------------------------------------
#define ASTR 72
#define APL  (128 * ASTR)

__device__ __forceinline__ void compute_scores2(
    const __half* Qh, const __half* Ql, const __half* Kh,
    int wr, int co, int lane, float acc[8][4])
{
#pragma unroll
    for (int j = 0; j < 8; j++)
#pragma unroll
        for (int q = 0; q < 4; q++) acc[j][q] = 0.f;

#pragma unroll
    for (int kf = 0; kf < 4; kf++) {
        unsigned ah[4], al[4];
        int qoff = (wr + (lane & 15)) * ASTR + kf * 16 + (lane >> 4) * 8;
        ldmA(smem_u32(&Qh[qoff]), ah[0], ah[1], ah[2], ah[3]);
        ldmA(smem_u32(&Ql[qoff]), al[0], al[1], al[2], al[3]);
#pragma unroll
        for (int j = 0; j < 8; j++) {
            int koff = (co + j * 8 + (lane & 7)) * ASTR + kf * 16 + ((lane >> 3) & 1) * 8;
            unsigned bh0, bh1;
            ldmB(smem_u32(&Kh[koff]), bh0, bh1);
            mma16816(acc[j], ah[0], ah[1], ah[2], ah[3], bh0, bh1);
            mma16816(acc[j], al[0], al[1], al[2], al[3], bh0, bh1);
        }
    }
}

__device__ __forceinline__ void compute_scores1(
    const __half* Qh, const __half* Kh,
    int wr, int co, int lane, float acc[8][4])
{
#pragma unroll
    for (int j = 0; j < 8; j++)
#pragma unroll
        for (int q = 0; q < 4; q++) acc[j][q] = 0.f;

#pragma unroll
    for (int kf = 0; kf < 4; kf++) {
        unsigned ah[4];
        int qoff = (wr + (lane & 15)) * ASTR + kf * 16 + (lane >> 4) * 8;
        ldmA(smem_u32(&Qh[qoff]), ah[0], ah[1], ah[2], ah[3]);
#pragma unroll
        for (int j = 0; j < 8; j++) {
            int koff = (co + j * 8 + (lane & 7)) * ASTR + kf * 16 + ((lane >> 3) & 1) * 8;
            unsigned bh0, bh1;
            ldmB(smem_u32(&Kh[koff]), bh0, bh1);
            mma16816(acc[j], ah[0], ah[1], ah[2], ah[3], bh0, bh1);
        }
    }
}

// ---------------------------------------------------------------------------
// Attention: per (head n, 128-row q-block). 512 threads / 16 warps.
// rowgrp = wid&7 (16 rows); column half hv = wid>>3 (64 of 128 cols).
// NO softmax max (scores bounded; exp safe in fp32):
//   pass 1 accumulates per-thread l partials, ONE reduction at the end.
//   pass 2: p = exp2(s*EC) * invl.
// 3-stage cp.async pipeline (lookahead 2), single sync per tile.
// ---------------------------------------------------------------------------
__global__ __launch_bounds__(512, 1) void attn_kernel(float* __restrict__ w_out)
{
    extern __shared__ __half sm[];
    __half* Qh = sm;
    __half* Ql = sm + APL;
    // stage s (s=0..2): sm + 2*APL + s*2*APL -> Kh, Vh

    const int n   = blockIdx.y;
    const int qb  = blockIdx.x * 128;
    const int tid = threadIdx.x, lane = tid & 31, wid = tid >> 5;
    const int rowgrp = wid & 7, hv = wid >> 3;
    const int wr = rowgrp * 16, co = hv * 64;

    const __half* qhg = g_qh + (size_t)n * HD + (size_t)qb * 64;
    const __half* qlg = g_ql + (size_t)n * HD + (size_t)qb * 64;
    const __half* khg = g_kh + (size_t)n * HD;
    const __half* vhg = g_vh + (size_t)n * HD;

    for (int idx = tid; idx < 128 * 8; idx += 512) {
        int row = idx >> 3, c = (idx & 7) * 8;
        *(uint4*)&Qh[row * ASTR + c] = *(const uint4*)(qhg + (size_t)row * 64 + c);
        *(uint4*)&Ql[row * ASTR + c] = *(const uint4*)(qlg + (size_t)row * 64 + c);
    }

    const int ar = tid >> 3, ac = (tid & 7) * 8;

    auto load_k1 = [&](int s, int sc) {
        __half* kh = sm + 2 * APL + s * 2 * APL;
#pragma unroll
        for (int rr = 0; rr < 128; rr += 64) {
            int row = rr + ar;
            size_t g = (size_t)(sc * 128 + row) * 64 + ac;
            cp16(smem_u32(&kh[row * ASTR + ac]), khg + g);
        }
    };
    auto load_kv = [&](int s, int sc) {
        __half* kh = sm + 2 * APL + s * 2 * APL;
#pragma unroll
        for (int rr = 0; rr < 128; rr += 64) {
            int row = rr + ar;
            size_t g = (size_t)(sc * 128 + row) * 64 + ac;
            unsigned d = smem_u32(&kh[row * ASTR + ac]);
            cp16(d,           khg + g);
            cp16(d + APL * 2, vhg + g);
        }
    };

    float lv[2] = {0.f, 0.f};

    // ---------------- pass 1: l partials (qh*kh scores, no max) ------------
    load_k1(0, 0); cp_commit();
    load_k1(1, 1); cp_commit();
    for (int sc = 0; sc < 16; sc++) {
        if (sc < 15) cp_wait<1>(); else cp_wait<0>();
        __syncthreads();
        if (sc + 2 < 16) { load_k1((sc + 2) % 3, sc + 2); cp_commit(); }

        const __half* Kh = sm + 2 * APL + (sc % 3) * 2 * APL;

        float acc[8][4];
        compute_scores1(Qh, Kh, wr, co, lane, acc);

#pragma unroll
        for (int j = 0; j < 8; j++) {
            lv[0] += exp2f(acc[j][0] * EC) + exp2f(acc[j][1] * EC);
            lv[1] += exp2f(acc[j][2] * EC) + exp2f(acc[j][3] * EC);
        }
    }

    // single reduction: across lane quad, then across column halves via smem
#pragma unroll
    for (int hf = 0; hf < 2; hf++) {
        lv[hf] += __shfl_xor_sync(0xffffffffu, lv[hf], 1);
        lv[hf] += __shfl_xor_sync(0xffffffffu, lv[hf], 2);
    }
    float* st = (float*)(sm + 2 * APL);   // overlaps stage bufs; sync first
    __syncthreads();
    if ((lane & 3) == 0) {
        int r_ = lane >> 2;
        st[hv * 128 + rowgrp * 16 + r_]     = lv[0];
        st[hv * 128 + rowgrp * 16 + r_ + 8] = lv[1];
    }
    __syncthreads();
    float invl[2];
#pragma unroll
    for (int hf = 0; hf < 2; hf++) {
        int r_ = (lane >> 2) + hf * 8;
        invl[hf] = 1.0f / (st[rowgrp * 16 + r_] + st[128 + rowgrp * 16 + r_]);
    }
    __syncthreads();   // st reads done before pass-2 loads overwrite

    float o[8][4];
#pragma unroll
    for (int j = 0; j < 8; j++)
#pragma unroll
        for (int q = 0; q < 4; q++) o[j][q] = 0.f;

    // ---------------- pass 2: weights out + partial P@V ----------------
    load_kv(0, 0); cp_commit();
    load_kv(1, 1); cp_commit();
    for (int sc = 0; sc < 16; sc++) {
        if (sc < 15) cp_wait<1>(); else cp_wait<0>();
        __syncthreads();
        if (sc + 2 < 16) { load_kv((sc + 2) % 3, sc + 2); cp_commit(); }

        const __half* Kh = sm + 2 * APL + (sc % 3) * 2 * APL;
        const __half* Vh = Kh + APL;

        float acc[8][4];
        compute_scores2(Qh, Ql, Kh, wr, co, lane, acc);

        float* wb = w_out + (size_t)n * ((size_t)T_DIM * T_DIM)
                  + (size_t)(qb + wr + (lane >> 2)) * T_DIM + sc * 128 + co + (lane & 3) * 2;
#pragma unroll
        for (int j = 0; j < 8; j++) {
            float p0 = exp2f(acc[j][0] * EC) * invl[0];
            float p1 = exp2f(acc[j][1] * EC) * invl[0];
            float p2 = exp2f(acc[j][2] * EC) * invl[1];
            float p3 = exp2f(acc[j][3] * EC) * invl[1];
            acc[j][0] = p0; acc[j][1] = p1; acc[j][2] = p2; acc[j][3] = p3;
            stg_cs_f2(wb + j * 8, p0, p1);
            stg_cs_f2(wb + 8 * (size_t)T_DIM + j * 8, p2, p3);
        }

        // PV: p hi-only x Vh (single MMA)
#pragma unroll
        for (int g = 0; g < 4; g++) {
            unsigned a0 = packh_f(acc[2 * g][0],     acc[2 * g][1]);
            unsigned a1 = packh_f(acc[2 * g][2],     acc[2 * g][3]);
            unsigned a2 = packh_f(acc[2 * g + 1][0], acc[2 * g + 1][1]);
            unsigned a3 = packh_f(acc[2 * g + 1][2], acc[2 * g + 1][3]);
#pragma unroll
            for (int j = 0; j < 8; j++) {
                int voff = (co + g * 16 + (lane & 15)) * ASTR + j * 8;
                unsigned bh0, bh1;
                ldmBT(smem_u32(&Vh[voff]), bh0, bh1);
                mma16816(o[j], a0, a1, a2, a3, bh0, bh1);
            }
        }
    }

    // ---------------- merge partial O across the two halves ----------------
    float* os = (float*)sm;   // Q region no longer needed
    __syncthreads();
    if (hv == 1) {
#pragma unroll
        for (int j = 0; j < 8; j++)
#pragma unroll
            for (int q = 0; q < 4; q++)
                os[(rowgrp * 32 + lane) * 32 + j * 4 + q] = o[j][q];
    }
    __syncthreads();
    if (hv == 0) {
#pragma unroll
        for (int j = 0; j < 8; j++)
#pragma unroll
            for (int q = 0; q < 4; q++)
                o[j][q] += os[(rowgrp * 32 + lane) * 32 + j * 4 + q];

        const int bsel = n >> 4, h = n & 15;
        const int t0   = qb + wr + (lane >> 2);
        const int dcol = (lane & 3) * 2;
#pragma unroll
        for (int j = 0; j < 8; j++) {
            int d = j * 8 + dcol;
            size_t off = (size_t)(t0 * 2 + bsel) * E_DIM + h * 64 + d;
            *(unsigned*)&g_ah[off] = packh_f(o[j][0], o[j][1]);
            off = (size_t)((t0 + 8) * 2 + bsel) * E_DIM + h * 64 + d;
            *(unsigned*)&g_ah[off] = packh_f(o[j][2], o[j][3]);
        }
    }
}

// ---------------------------------------------------------------------------
// Output projection (fp16x2), cp.async 3-stage, single sync per k-tile.
// ---------------------------------------------------------------------------
__global__ __launch_bounds__(256, 2) void gemm_out(
    const float* __restrict__ bo, float* __restrict__ out)
{
    extern __shared__ __half sb[];

    const int n0 = blockIdx.y * 128;
    const int m0 = blockIdx.x * 128;

    const int tid = threadIdx.x, lane = tid & 31, wid = tid >> 5;
    const int wm = (wid >> 2) * 64, wn = (wid & 3) * 32;
    const int lr = tid >> 2;
    const int lc = (tid & 3) * 8;

    float acc[4][4][4];
#pragma unroll
    for (int i = 0; i < 4; i++)
#pragma unroll
        for (int j = 0; j < 4; j++)
#pragma unroll
            for (int q = 0; q < 4; q++) acc[i][j][q] = 0.f;

    auto load_stage = [&](int s, int k0) {
        __half* base = sb + s * GSTG;
#pragma unroll
        for (int rr = 0; rr < 128; rr += 64) {
            int row = rr + lr;
            size_t ga = (size_t)(m0 + row) * 1024 + k0 + lc;
            size_t gb = (size_t)(n0 + row) * 1024 + k0 + lc;
            unsigned d = smem_u32(base + row * GSTR + lc);
            cp16(d,           g_ah + ga);
            cp16(d + GPL * 2, g_woh + gb);
            cp16(d + GPL * 4, g_wol + gb);
        }
    };

    load_stage(0, 0);  cp_commit();
    load_stage(1, 32); cp_commit();

    for (int kt = 0; kt < 32; kt++) {
        if (kt < 31) cp_wait<1>(); else cp_wait<0>();
        __syncthreads();
        if (kt + 2 < 32) { load_stage((kt + 2) % 3, (kt + 2) * 32); cp_commit(); }

        const __half* Ah = sb + (kt % 3) * GSTG;
        const __half* Bh = Ah + GPL;
        const __half* Bl = Bh + GPL;

#pragma unroll
        for (int kf = 0; kf < 2; kf++) {
            unsigned ah[4][4];
#pragma unroll
            for (int i = 0; i < 4; i++) {
                int aoff = (wm + i * 16 + (lane & 15)) * GSTR + kf * 16 + (lane >> 4) * 8;
                ldmA(smem_u32(&Ah[aoff]), ah[i][0], ah[i][1], ah[i][2], ah[i][3]);
            }
#pragma unroll
            for (int j = 0; j < 4; j++) {
                int boff = (wn + j * 8 + (lane & 7)) * GSTR + kf * 16 + ((lane >> 3) & 1) * 8;
                unsigned bh0, bh1, bl0, bl1;
                ldmB(smem_u32(&Bh[boff]), bh0, bh1);
                ldmB(smem_u32(&Bl[boff]), bl0, bl1);
#pragma unroll
                for (int i = 0; i < 4; i++) {
                    mma16816(acc[i][j], ah[i][0], ah[i][1], ah[i][2], ah[i][3], bh0, bh1);
                    mma16816(acc[i][j], ah[i][0], ah[i][1], ah[i][2], ah[i][3], bl0, bl1);
                }
            }
        }
    }

    const float inv64 = 0.015625f;
#pragma unroll
    for (int i = 0; i < 4; i++) {
#pragma unroll
        for (int j = 0; j < 4; j++) {
            int col = n0 + wn + j * 8 + (lane & 3) * 2;
            float b0 = bo[col], b1 = bo[col + 1];
#pragma unroll
            for (int hf = 0; hf < 2; hf++) {
                int r = m0 + wm + i * 16 + (lane >> 2) + hf * 8;
                float2 v;
                v.x = acc[i][j][2 * hf + 0] * inv64 + b0;
                v.y = acc[i][j][2 * hf + 1] * inv64 + b1;
                *(float2*)(out + (size_t)r * 1024 + col) = v;
            }
        }
    }
}

// ---------------------------------------------------------------------------
// d_out = [ out (4096*1024 fp32) | attn_weights (32*2048*2048 fp32) ]
// ---------------------------------------------------------------------------
extern "C" void kernel_launch(void* const* d_in, const int* in_sizes, int n_in,
                              void* d_out, int out_size)
{
    const float* query = (const float*)d_in[0];
    const float* wq    = (const float*)d_in[1];
    const float* bq    = (const float*)d_in[2];
    const float* wk    = (const float*)d_in[3];
    const float* bk    = (const float*)d_in[4];
    const float* wv    = (const float*)d_in[5];
    const float* bv    = (const float*)d_in[6];
    const float* wo    = (const float*)d_in[7];
    const float* bo    = (const float*)d_in[8];

    float* out   = (float*)d_out;
    float* w_out = out + (size_t)M_DIM * E_DIM;

    const int gemm_smem = 3 * GSTG * (int)sizeof(__half);   // 92,160 B
    const int attn_smem = 8 * APL * (int)sizeof(__half);    // 147,456 B
    cudaFuncSetAttribute(gemm_qkv,    cudaFuncAttributeMaxDynamicSharedMemorySize, gemm_smem);
    cudaFuncSetAttribute(attn_kernel, cudaFuncAttributeMaxDynamicSharedMemorySize, attn_smem);
    cudaFuncSetAttribute(gemm_out,    cudaFuncAttributeMaxDynamicSharedMemorySize, gemm_smem);

    split_all<<<8192, 256>>>(query, wq, wk, wv, wo);
    gemm_qkv<<<dim3(32, 24), 256, gemm_smem>>>(bq, bk, bv);
    attn_kernel<<<dim3(16, 32), 512, attn_smem>>>(w_out);
    gemm_out<<<dim3(32, 8), 256, gemm_smem>>>(bo, out);
}

// round 14
// speedup vs baseline: 4.9009x; 1.0754x over previous
#include <cuda_runtime.h>
#include <cuda_bf16.h>
#include <cuda_fp16.h>

// T=2048, B=2, E=1024, H=16, D=64
#define T_DIM 2048
#define E_DIM 1024
#define NH    32            // B*H
#define M_DIM 4096          // T*B
#define HD    (T_DIM * 64)  // per-head plane elems

// 0.125 * log2(e): score scaling folded into exp2
#define EC 0.18033688011112042f

// ---------------------------------------------------------------------------
// Device-global scratch (fp16 planes). Weights stored pre-scaled by 64 so the
// lo plane stays in fp16 normal range; epilogues divide by 64.
// q/k/v/attn-result are all hi-only now; only wv and wo keep lo planes.
// ---------------------------------------------------------------------------
__device__ __half g_xh[(size_t)M_DIM * E_DIM];
__device__ __half g_wqh[1024 * 1024];
__device__ __half g_wkh[1024 * 1024];
__device__ __half g_wvh[1024 * 1024], g_wvl[1024 * 1024];
__device__ __half g_woh[1024 * 1024], g_wol[1024 * 1024];
__device__ __half g_qh[(size_t)NH * HD];                          // q hi only, unscaled
__device__ __half g_kh[(size_t)NH * HD];                          // k hi only
__device__ __half g_vh[(size_t)NH * HD];                          // v hi only
__device__ __half g_ah[(size_t)M_DIM * E_DIM];                    // attn result hi only

// ---------------------------------------------------------------------------
// Helpers
// ---------------------------------------------------------------------------
__device__ __forceinline__ unsigned smem_u32(const void* p) {
    return (unsigned)__cvta_generic_to_shared(p);
}
__device__ __forceinline__ void cp16(unsigned dst, const void* src) {
    asm volatile("cp.async.cg.shared.global [%0], [%1], 16;" :: "r"(dst), "l"(src));
}
__device__ __forceinline__ void cp_commit() {
    asm volatile("cp.async.commit_group;");
}
template <int N> __device__ __forceinline__ void cp_wait() {
    asm volatile("cp.async.wait_group %0;" :: "n"(N));
}
__device__ __forceinline__ void ldmA(unsigned addr, unsigned& r0, unsigned& r1,
                                     unsigned& r2, unsigned& r3) {
    asm volatile("ldmatrix.sync.aligned.m8n8.x4.shared.b16 {%0,%1,%2,%3}, [%4];"
                 : "=r"(r0), "=r"(r1), "=r"(r2), "=r"(r3) : "r"(addr));
}
__device__ __forceinline__ void ldmB(unsigned addr, unsigned& r0, unsigned& r1) {
    asm volatile("ldmatrix.sync.aligned.m8n8.x2.shared.b16 {%0,%1}, [%2];"
                 : "=r"(r0), "=r"(r1) : "r"(addr));
}
__device__ __forceinline__ void ldmBT(unsigned addr, unsigned& r0, unsigned& r1) {
    asm volatile("ldmatrix.sync.aligned.m8n8.x2.trans.shared.b16 {%0,%1}, [%2];"
                 : "=r"(r0), "=r"(r1) : "r"(addr));
}
// fp16 MMA, fp32 accumulate
__device__ __forceinline__ void mma16816(float* c, unsigned a0, unsigned a1,
                                         unsigned a2, unsigned a3,
                                         unsigned b0, unsigned b1) {
    asm volatile(
        "mma.sync.aligned.m16n8k16.row.col.f32.f16.f16.f32 "
        "{%0,%1,%2,%3}, {%4,%5,%6,%7}, {%8,%9}, {%0,%1,%2,%3};"
        : "+f"(c[0]), "+f"(c[1]), "+f"(c[2]), "+f"(c[3])
        : "r"(a0), "r"(a1), "r"(a2), "r"(a3), "r"(b0), "r"(b1));
}
__device__ __forceinline__ unsigned packh(__half a, __half b) {
    unsigned short ua = *(unsigned short*)&a, ub = *(unsigned short*)&b;
    return (unsigned)ua | ((unsigned)ub << 16);
}
__device__ __forceinline__ unsigned packh_f(float x, float y) {
    return packh(__float2half_rn(x), __float2half_rn(y));
}
__device__ __forceinline__ void split_pair_h(float x, float y, unsigned& hi, unsigned& lo) {
    __half xh = __float2half_rn(x), yh = __float2half_rn(y);
    float xr = x - __half2float(xh), yr = y - __half2float(yh);
    hi = packh(xh, yh);
    lo = packh(__float2half_rn(xr), __float2half_rn(yr));
}
__device__ __forceinline__ void stg_cs_f2(float* p, float a, float b) {
    asm volatile("st.global.cs.v2.f32 [%0], {%1,%2};" :: "l"(p), "f"(a), "f"(b));
}

// ---------------------------------------------------------------------------
// Split fp32 inputs into fp16 planes. X/wq/wk: hi only. wv/wo (x64): hi + lo.
// ---------------------------------------------------------------------------
__global__ __launch_bounds__(256) void split_all(
    const float* __restrict__ X, const float* __restrict__ wq,
    const float* __restrict__ wk, const float* __restrict__ wv,
    const float* __restrict__ wo)
{
    size_t i = (size_t)blockIdx.x * 256 + threadIdx.x;
    if (i < 1048576) {
        float4 v = ((const float4*)X)[i];
        ((unsigned*)g_xh)[i * 2]     = packh_f(v.x, v.y);
        ((unsigned*)g_xh)[i * 2 + 1] = packh_f(v.z, v.w);
        return;
    }
    size_t j = i - 1048576;
    int w = (int)(j >> 18);
    size_t off = j & 262143;
    const float* src; __half *dh, *dl;
    if      (w == 0) { src = wq; dh = g_wqh; dl = nullptr; }
    else if (w == 1) { src = wk; dh = g_wkh; dl = nullptr; }
    else if (w == 2) { src = wv; dh = g_wvh; dl = g_wvl; }
    else             { src = wo; dh = g_woh; dl = g_wol; }
    float4 v = ((const float4*)src)[off];
    unsigned h0, l0, h1, l1;
    split_pair_h(v.x * 64.f, v.y * 64.f, h0, l0);
    split_pair_h(v.z * 64.f, v.w * 64.f, h1, l1);
    ((unsigned*)dh)[off * 2] = h0; ((unsigned*)dh)[off * 2 + 1] = h1;
    if (dl) {
        ((unsigned*)dl)[off * 2] = l0; ((unsigned*)dl)[off * 2 + 1] = l1;
    }
}

// ---------------------------------------------------------------------------
// GEMM tile constants: up to 3 planes per stage (Ah, Bh, Bl), K-chunk 32.
// ---------------------------------------------------------------------------
#define GSTR  40
#define GPL   (128 * GSTR)
#define GSTG  (3 * GPL)

// ---------------------------------------------------------------------------
// QKV projection GEMM, cp.async 3-stage, single sync per k-tile.
// q,k: 1 MMA (Wh only). v: 2 MMA (Wh+Wl). Outputs hi-only, unscaled by 0.125.
// ---------------------------------------------------------------------------
__global__ __launch_bounds__(256, 2) void gemm_qkv(
    const float* __restrict__ bq, const float* __restrict__ bk, const float* __restrict__ bv)
{
    extern __shared__ __half sb[];

    const int wsel = blockIdx.y >> 3;
    const int n0   = (blockIdx.y & 7) * 128;
    const int m0   = blockIdx.x * 128;

    const __half* Wh = (wsel == 0) ? g_wqh : (wsel == 1) ? g_wkh : g_wvh;
    const float* bias = (wsel == 0) ? bq : (wsel == 1) ? bk : bv;
    __half* dh = (wsel == 0) ? g_qh : (wsel == 1) ? g_kh : g_vh;
    const bool use_lo = (wsel == 2);

    const int tid = threadIdx.x, lane = tid & 31, wid = tid >> 5;
    const int wm = (wid >> 2) * 64, wn = (wid & 3) * 32;
    const int lr = tid >> 2;
    const int lc = (tid & 3) * 8;

    float acc[4][4][4];
#pragma unroll
    for (int i = 0; i < 4; i++)
#pragma unroll
        for (int j = 0; j < 4; j++)
#pragma unroll
            for (int q = 0; q < 4; q++) acc[i][j][q] = 0.f;

    auto load_stage = [&](int s, int k0) {
        __half* base = sb + s * GSTG;
#pragma unroll
        for (int rr = 0; rr < 128; rr += 64) {
            int row = rr + lr;
            size_t ga = (size_t)(m0 + row) * 1024 + k0 + lc;
            size_t gb = (size_t)(n0 + row) * 1024 + k0 + lc;
            unsigned d = smem_u32(base + row * GSTR + lc);
            cp16(d,           g_xh + ga);
            cp16(d + GPL * 2, Wh + gb);
            if (use_lo) cp16(d + GPL * 4, g_wvl + gb);
        }
    };

    load_stage(0, 0);  cp_commit();
    load_stage(1, 32); cp_commit();

    for (int kt = 0; kt < 32; kt++) {
        if (kt < 31) cp_wait<1>(); else cp_wait<0>();
        __syncthreads();
        if (kt + 2 < 32) { load_stage((kt + 2) % 3, (kt + 2) * 32); cp_commit(); }

        const __half* Ah = sb + (kt % 3) * GSTG;
        const __half* Bh = Ah + GPL;
        const __half* Bl = Bh + GPL;

#pragma unroll
        for (int kf = 0; kf < 2; kf++) {
            unsigned ah[4][4];
#pragma unroll
            for (int i = 0; i < 4; i++) {
                int aoff = (wm + i * 16 + (lane & 15)) * GSTR + kf * 16 + (lane >> 4) * 8;
                ldmA(smem_u32(&Ah[aoff]), ah[i][0], ah[i][1], ah[i][2], ah[i][3]);
            }
#pragma unroll
            for (int j = 0; j < 4; j++) {
                int boff = (wn + j * 8 + (lane & 7)) * GSTR + kf * 16 + ((lane >> 3) & 1) * 8;
                unsigned bh0, bh1;
                ldmB(smem_u32(&Bh[boff]), bh0, bh1);
#pragma unroll
                for (int i = 0; i < 4; i++)
                    mma16816(acc[i][j], ah[i][0], ah[i][1], ah[i][2], ah[i][3], bh0, bh1);
                if (use_lo) {
                    unsigned bl0, bl1;
                    ldmB(smem_u32(&Bl[boff]), bl0, bl1);
#pragma unroll
                    for (int i = 0; i < 4; i++)
                        mma16816(acc[i][j], ah[i][0], ah[i][1], ah[i][2], ah[i][3], bl0, bl1);
                }
            }
        }
    }

    const float inv64 = 0.015625f;
#pragma unroll
    for (int i = 0; i < 4; i++) {
#pragma unroll
        for (int j = 0; j < 4; j++) {
            int col = n0 + wn + j * 8 + (lane & 3) * 2;
            float b0 = bias[col], b1 = bias[col + 1];
            int h = col >> 6, d = col & 63;
#pragma unroll
            for (int hf = 0; hf < 2; hf++) {
                int r = m0 + wm + i * 16 + (lane >> 2) + hf * 8;
                float v0 = acc[i][j][2 * hf + 0] * inv64 + b0;
                float v1 = acc[i][j][2 * hf + 1] * inv64 + b1;
                size_t off = (size_t)((r & 1) * 16 + h) * HD + (size_t)(r >> 1) * 64 + d;
                *(unsigned*)&dh[off] = packh_f(v0, v1);
            }
        }
    }
}

// ---------------------------------------------------------------------------
// Attention score half-tile (fp16, single plane): acc = qh(16 rows) @ kh^T(64)
// Used identically in BOTH passes (l exactly consistent with weights).
// ---------------------------------------------------------------------------
#define ASTR 72
#define APL  (128 * ASTR)

__device__ __forceinline__ void compute_scores1(
    const __half* Qh, const __half* Kh,
    int wr, int co, int lane, float acc[8][4])
{
#pragma unroll
    for (int j = 0; j < 8; j++)
#pragma unroll
        for (int q = 0; q < 4; q++) acc[j][q] = 0.f;

#pragma unroll
    for (int kf = 0; kf < 4; kf++) {
        unsigned ah[4];
        int qoff = (wr + (lane & 15)) * ASTR + kf * 16 + (lane >> 4) * 8;
        ldmA(smem_u32(&Qh[qoff]), ah[0], ah[1], ah[2], ah[3]);
#pragma unroll
        for (int j = 0; j < 8; j++) {
            int koff = (co + j * 8 + (lane & 7)) * ASTR + kf * 16 + ((lane >> 3) & 1) * 8;
            unsigned bh0, bh1;
            ldmB(smem_u32(&Kh[koff]), bh0, bh1);
            mma16816(acc[j], ah[0], ah[1], ah[2], ah[3], bh0, bh1);
        }
    }
}

// ---------------------------------------------------------------------------
// Attention: per (head n, 128-row q-block). 512 threads / 16 warps.
// rowgrp = wid&7 (16 rows); column half hv = wid>>3 (64 of 128 cols).
// Max-free softmax (scores bounded). 3-stage cp.async, 1 sync per tile.
// smem planes: Qh(1) + 3 stages x (Kh,Vh) = 7 APL = 129,024 B.
// ---------------------------------------------------------------------------
__global__ __launch_bounds__(512, 1) void attn_kernel(float* __restrict__ w_out)
{
    extern __shared__ __half sm[];
    __half* Qh = sm;
    // stage s (s=0..2): sm + APL + s*2*APL -> Kh, Vh

    const int n   = blockIdx.y;
    const int qb  = blockIdx.x * 128;
    const int tid = threadIdx.x, lane = tid & 31, wid = tid >> 5;
    const int rowgrp = wid & 7, hv = wid >> 3;
    const int wr = rowgrp * 16, co = hv * 64;

    const __half* qhg = g_qh + (size_t)n * HD + (size_t)qb * 64;
    const __half* khg = g_kh + (size_t)n * HD;
    const __half* vhg = g_vh + (size_t)n * HD;

    for (int idx = tid; idx < 128 * 8; idx += 512) {
        int row = idx >> 3, c = (idx & 7) * 8;
        *(uint4*)&Qh[row * ASTR + c] = *(const uint4*)(qhg + (size_t)row * 64 + c);
    }

    const int ar = tid >> 3, ac = (tid & 7) * 8;

    auto load_k1 = [&](int s, int sc) {
        __half* kh = sm + APL + s * 2 * APL;
#pragma unroll
        for (int rr = 0; rr < 128; rr += 64) {
            int row = rr + ar;
            size_t g = (size_t)(sc * 128 + row) * 64 + ac;
            cp16(smem_u32(&kh[row * ASTR + ac]), khg + g);
        }
    };
    auto load_kv = [&](int s, int sc) {
        __half* kh = sm + APL + s * 2 * APL;
#pragma unroll
        for (int rr = 0; rr < 128; rr += 64) {
            int row = rr + ar;
            size_t g = (size_t)(sc * 128 + row) * 64 + ac;
            unsigned d = smem_u32(&kh[row * ASTR + ac]);
            cp16(d,           khg + g);
            cp16(d + APL * 2, vhg + g);
        }
    };

    float lv[2] = {0.f, 0.f};

    // ---------------- pass 1: l partials (qh*kh scores, no max) ------------
    load_k1(0, 0); cp_commit();
    load_k1(1, 1); cp_commit();
    for (int sc = 0; sc < 16; sc++) {
        if (sc < 15) cp_wait<1>(); else cp_wait<0>();
        __syncthreads();
        if (sc + 2 < 16) { load_k1((sc + 2) % 3, sc + 2); cp_commit(); }

        const __half* Kh = sm + APL + (sc % 3) * 2 * APL;

        float acc[8][4];
        compute_scores1(Qh, Kh, wr, co, lane, acc);

#pragma unroll
        for (int j = 0; j < 8; j++) {
            lv[0] += exp2f(acc[j][0] * EC) + exp2f(acc[j][1] * EC);
            lv[1] += exp2f(acc[j][2] * EC) + exp2f(acc[j][3] * EC);
        }
    }

    // single reduction: across lane quad, then across column halves via smem
#pragma unroll
    for (int hf = 0; hf < 2; hf++) {
        lv[hf] += __shfl_xor_sync(0xffffffffu, lv[hf], 1);
        lv[hf] += __shfl_xor_sync(0xffffffffu, lv[hf], 2);
    }
    float* st = (float*)(sm + APL);   // overlaps stage bufs; sync first
    __syncthreads();
    if ((lane & 3) == 0) {
        int r_ = lane >> 2;
        st[hv * 128 + rowgrp * 16 + r_]     = lv[0];
        st[hv * 128 + rowgrp * 16 + r_ + 8] = lv[1];
    }
    __syncthreads();
    float invl[2];
#pragma unroll
    for (int hf = 0; hf < 2; hf++) {
        int r_ = (lane >> 2) + hf * 8;
        invl[hf] = 1.0f / (st[rowgrp * 16 + r_] + st[128 + rowgrp * 16 + r_]);
    }
    __syncthreads();   // st reads done before pass-2 loads overwrite

    float o[8][4];
#pragma unroll
    for (int j = 0; j < 8; j++)
#pragma unroll
        for (int q = 0; q < 4; q++) o[j][q] = 0.f;

    // ---------------- pass 2: weights out + partial P@V ----------------
    load_kv(0, 0); cp_commit();
    load_kv(1, 1); cp_commit();
    for (int sc = 0; sc < 16; sc++) {
        if (sc < 15) cp_wait<1>(); else cp_wait<0>();
        __syncthreads();
        if (sc + 2 < 16) { load_kv((sc + 2) % 3, sc + 2); cp_commit(); }

        const __half* Kh = sm + APL + (sc % 3) * 2 * APL;
        const __half* Vh = Kh + APL;

        float acc[8][4];
        compute_scores1(Qh, Kh, wr, co, lane, acc);

        float* wb = w_out + (size_t)n * ((size_t)T_DIM * T_DIM)
                  + (size_t)(qb + wr + (lane >> 2)) * T_DIM + sc * 128 + co + (lane & 3) * 2;
#pragma unroll
        for (int j = 0; j < 8; j++) {
            float p0 = exp2f(acc[j][0] * EC) * invl[0];
            float p1 = exp2f(acc[j][1] * EC) * invl[0];
            float p2 = exp2f(acc[j][2] * EC) * invl[1];
            float p3 = exp2f(acc[j][3] * EC) * invl[1];
            acc[j][0] = p0; acc[j][1] = p1; acc[j][2] = p2; acc[j][3] = p3;
            stg_cs_f2(wb + j * 8, p0, p1);
            stg_cs_f2(wb + 8 * (size_t)T_DIM + j * 8, p2, p3);
        }

        // PV: p hi-only x Vh (single MMA)
#pragma unroll
        for (int g = 0; g < 4; g++) {
            unsigned a0 = packh_f(acc[2 * g][0],     acc[2 * g][1]);
            unsigned a1 = packh_f(acc[2 * g][2],     acc[2 * g][3]);
            unsigned a2 = packh_f(acc[2 * g + 1][0], acc[2 * g + 1][1]);
            unsigned a3 = packh_f(acc[2 * g + 1][2], acc[2 * g + 1][3]);
#pragma unroll
            for (int j = 0; j < 8; j++) {
                int voff = (co + g * 16 + (lane & 15)) * ASTR + j * 8;
                unsigned bh0, bh1;
                ldmBT(smem_u32(&Vh[voff]), bh0, bh1);
                mma16816(o[j], a0, a1, a2, a3, bh0, bh1);
            }
        }
    }

    // ---------------- merge partial O across the two halves ----------------
    float* os = (float*)sm;   // Qh + head of stage 0; all reads done after sync
    __syncthreads();
    if (hv == 1) {
#pragma unroll
        for (int j = 0; j < 8; j++)
#pragma unroll
            for (int q = 0; q < 4; q++)
                os[(rowgrp * 32 + lane) * 32 + j * 4 + q] = o[j][q];
    }
    __syncthreads();
    if (hv == 0) {
#pragma unroll
        for (int j = 0; j < 8; j++)
#pragma unroll
            for (int q = 0; q < 4; q++)
                o[j][q] += os[(rowgrp * 32 + lane) * 32 + j * 4 + q];

        const int bsel = n >> 4, h = n & 15;
        const int t0   = qb + wr + (lane >> 2);
        const int dcol = (lane & 3) * 2;
#pragma unroll
        for (int j = 0; j < 8; j++) {
            int d = j * 8 + dcol;
            size_t off = (size_t)(t0 * 2 + bsel) * E_DIM + h * 64 + d;
            *(unsigned*)&g_ah[off] = packh_f(o[j][0], o[j][1]);
            off = (size_t)((t0 + 8) * 2 + bsel) * E_DIM + h * 64 + d;
            *(unsigned*)&g_ah[off] = packh_f(o[j][2], o[j][3]);
        }
    }
}

// ---------------------------------------------------------------------------
// Output projection (fp16x2), cp.async 3-stage, single sync per k-tile.
// ---------------------------------------------------------------------------
__global__ __launch_bounds__(256, 2) void gemm_out(
    const float* __restrict__ bo, float* __restrict__ out)
{
    extern __shared__ __half sb[];

    const int n0 = blockIdx.y * 128;
    const int m0 = blockIdx.x * 128;

    const int tid = threadIdx.x, lane = tid & 31, wid = tid >> 5;
    const int wm = (wid >> 2) * 64, wn = (wid & 3) * 32;
    const int lr = tid >> 2;
    const int lc = (tid & 3) * 8;

    float acc[4][4][4];
#pragma unroll
    for (int i = 0; i < 4; i++)
#pragma unroll
        for (int j = 0; j < 4; j++)
#pragma unroll
            for (int q = 0; q < 4; q++) acc[i][j][q] = 0.f;

    auto load_stage = [&](int s, int k0) {
        __half* base = sb + s * GSTG;
#pragma unroll
        for (int rr = 0; rr < 128; rr += 64) {
            int row = rr + lr;
            size_t ga = (size_t)(m0 + row) * 1024 + k0 + lc;
            size_t gb = (size_t)(n0 + row) * 1024 + k0 + lc;
            unsigned d = smem_u32(base + row * GSTR + lc);
            cp16(d,           g_ah + ga);
            cp16(d + GPL * 2, g_woh + gb);
            cp16(d + GPL * 4, g_wol + gb);
        }
    };

    load_stage(0, 0);  cp_commit();
    load_stage(1, 32); cp_commit();

    for (int kt = 0; kt < 32; kt++) {
        if (kt < 31) cp_wait<1>(); else cp_wait<0>();
        __syncthreads();
        if (kt + 2 < 32) { load_stage((kt + 2) % 3, (kt + 2) * 32); cp_commit(); }

        const __half* Ah = sb + (kt % 3) * GSTG;
        const __half* Bh = Ah + GPL;
        const __half* Bl = Bh + GPL;

#pragma unroll
        for (int kf = 0; kf < 2; kf++) {
            unsigned ah[4][4];
#pragma unroll
            for (int i = 0; i < 4; i++) {
                int aoff = (wm + i * 16 + (lane & 15)) * GSTR + kf * 16 + (lane >> 4) * 8;
                ldmA(smem_u32(&Ah[aoff]), ah[i][0], ah[i][1], ah[i][2], ah[i][3]);
            }
#pragma unroll
            for (int j = 0; j < 4; j++) {
                int boff = (wn + j * 8 + (lane & 7)) * GSTR + kf * 16 + ((lane >> 3) & 1) * 8;
                unsigned bh0, bh1, bl0, bl1;
                ldmB(smem_u32(&Bh[boff]), bh0, bh1);
                ldmB(smem_u32(&Bl[boff]), bl0, bl1);
#pragma unroll
                for (int i = 0; i < 4; i++) {
                    mma16816(acc[i][j], ah[i][0], ah[i][1], ah[i][2], ah[i][3], bh0, bh1);
                    mma16816(acc[i][j], ah[i][0], ah[i][1], ah[i][2], ah[i][3], bl0, bl1);
                }
            }
        }
    }

    const float inv64 = 0.015625f;
#pragma unroll
    for (int i = 0; i < 4; i++) {
#pragma unroll
        for (int j = 0; j < 4; j++) {
            int col = n0 + wn + j * 8 + (lane & 3) * 2;
            float b0 = bo[col], b1 = bo[col + 1];
#pragma unroll
            for (int hf = 0; hf < 2; hf++) {
                int r = m0 + wm + i * 16 + (lane >> 2) + hf * 8;
                float2 v;
                v.x = acc[i][j][2 * hf + 0] * inv64 + b0;
                v.y = acc[i][j][2 * hf + 1] * inv64 + b1;
                *(float2*)(out + (size_t)r * 1024 + col) = v;
            }
        }
    }
}

// ---------------------------------------------------------------------------
// d_out = [ out (4096*1024 fp32) | attn_weights (32*2048*2048 fp32) ]
// ---------------------------------------------------------------------------
extern "C" void kernel_launch(void* const* d_in, const int* in_sizes, int n_in,
                              void* d_out, int out_size)
{
    const float* query = (const float*)d_in[0];
    const float* wq    = (const float*)d_in[1];
    const float* bq    = (const float*)d_in[2];
    const float* wk    = (const float*)d_in[3];
    const float* bk    = (const float*)d_in[4];
    const float* wv    = (const float*)d_in[5];
    const float* bv    = (const float*)d_in[6];
    const float* wo    = (const float*)d_in[7];
    const float* bo    = (const float*)d_in[8];

    float* out   = (float*)d_out;
    float* w_out = out + (size_t)M_DIM * E_DIM;

    const int gemm_smem = 3 * GSTG * (int)sizeof(__half);   // 92,160 B
    const int attn_smem = 7 * APL * (int)sizeof(__half);    // 129,024 B
    cudaFuncSetAttribute(gemm_qkv,    cudaFuncAttributeMaxDynamicSharedMemorySize, gemm_smem);
    cudaFuncSetAttribute(attn_kernel, cudaFuncAttributeMaxDynamicSharedMemorySize, attn_smem);
    cudaFuncSetAttribute(gemm_out,    cudaFuncAttributeMaxDynamicSharedMemorySize, gemm_smem);

    split_all<<<8192, 256>>>(query, wq, wk, wv, wo);
    gemm_qkv<<<dim3(32, 24), 256, gemm_smem>>>(bq, bk, bv);
    attn_kernel<<<dim3(16, 32), 512, attn_smem>>>(w_out);
    gemm_out<<<dim3(32, 8), 256, gemm_smem>>>(bo, out);
}

// round 15
// speedup vs baseline: 5.4010x; 1.1020x over previous
#include <cuda_runtime.h>
#include <cuda_bf16.h>
#include <cuda_fp16.h>

// T=2048, B=2, E=1024, H=16, D=64
#define T_DIM 2048
#define E_DIM 1024
#define NH    32            // B*H
#define M_DIM 4096          // T*B
#define HD    (T_DIM * 64)  // per-head plane elems

// 0.125 * log2(e): score scaling folded into exp2
#define EC 0.18033688011112042f

// ---------------------------------------------------------------------------
// Device-global scratch (fp16 planes). Weights stored pre-scaled by 64 so the
// lo plane stays in fp16 normal range; epilogues divide by 64.
// q/k/v/attn-result hi-only; only wv and wo keep lo planes.
// ---------------------------------------------------------------------------
__device__ __half g_xh[(size_t)M_DIM * E_DIM];
__device__ __half g_wqh[1024 * 1024];
__device__ __half g_wkh[1024 * 1024];
__device__ __half g_wvh[1024 * 1024], g_wvl[1024 * 1024];
__device__ __half g_woh[1024 * 1024], g_wol[1024 * 1024];
__device__ __half g_qh[(size_t)NH * HD];                          // q hi only, unscaled
__device__ __half g_kh[(size_t)NH * HD];                          // k hi only
__device__ __half g_vh[(size_t)NH * HD];                          // v hi only
__device__ __half g_ah[(size_t)M_DIM * E_DIM];                    // attn result hi only

// ---------------------------------------------------------------------------
// Helpers
// ---------------------------------------------------------------------------
__device__ __forceinline__ unsigned smem_u32(const void* p) {
    return (unsigned)__cvta_generic_to_shared(p);
}
__device__ __forceinline__ void cp16(unsigned dst, const void* src) {
    asm volatile("cp.async.cg.shared.global [%0], [%1], 16;" :: "r"(dst), "l"(src));
}
__device__ __forceinline__ void cp_commit() {
    asm volatile("cp.async.commit_group;");
}
template <int N> __device__ __forceinline__ void cp_wait() {
    asm volatile("cp.async.wait_group %0;" :: "n"(N));
}
__device__ __forceinline__ void ldmA(unsigned addr, unsigned& r0, unsigned& r1,
                                     unsigned& r2, unsigned& r3) {
    asm volatile("ldmatrix.sync.aligned.m8n8.x4.shared.b16 {%0,%1,%2,%3}, [%4];"
                 : "=r"(r0), "=r"(r1), "=r"(r2), "=r"(r3) : "r"(addr));
}
// x4 load of TWO adjacent n8k16 B-fragments (j, j+1)
__device__ __forceinline__ void ldmB4(unsigned addr, unsigned& r0, unsigned& r1,
                                      unsigned& r2, unsigned& r3) {
    asm volatile("ldmatrix.sync.aligned.m8n8.x4.shared.b16 {%0,%1,%2,%3}, [%4];"
                 : "=r"(r0), "=r"(r1), "=r"(r2), "=r"(r3) : "r"(addr));
}
// x4 transposed load of TWO adjacent B-fragments for PV
__device__ __forceinline__ void ldmBT4(unsigned addr, unsigned& r0, unsigned& r1,
                                       unsigned& r2, unsigned& r3) {
    asm volatile("ldmatrix.sync.aligned.m8n8.x4.trans.shared.b16 {%0,%1,%2,%3}, [%4];"
                 : "=r"(r0), "=r"(r1), "=r"(r2), "=r"(r3) : "r"(addr));
}
// fp16 MMA, fp32 accumulate
__device__ __forceinline__ void mma16816(float* c, unsigned a0, unsigned a1,
                                         unsigned a2, unsigned a3,
                                         unsigned b0, unsigned b1) {
    asm volatile(
        "mma.sync.aligned.m16n8k16.row.col.f32.f16.f16.f32 "
        "{%0,%1,%2,%3}, {%4,%5,%6,%7}, {%8,%9}, {%0,%1,%2,%3};"
        : "+f"(c[0]), "+f"(c[1]), "+f"(c[2]), "+f"(c[3])
        : "r"(a0), "r"(a1), "r"(a2), "r"(a3), "r"(b0), "r"(b1));
}
__device__ __forceinline__ unsigned packh(__half a, __half b) {
    unsigned short ua = *(unsigned short*)&a, ub = *(unsigned short*)&b;
    return (unsigned)ua | ((unsigned)ub << 16);
}
__device__ __forceinline__ unsigned packh_f(float x, float y) {
    return packh(__float2half_rn(x), __float2half_rn(y));
}
__device__ __forceinline__ void split_pair_h(float x, float y, unsigned& hi, unsigned& lo) {
    __half xh = __float2half_rn(x), yh = __float2half_rn(y);
    float xr = x - __half2float(xh), yr = y - __half2float(yh);
    hi = packh(xh, yh);
    lo = packh(__float2half_rn(xr), __float2half_rn(yr));
}
__device__ __forceinline__ void stg_cs_f2(float* p, float a, float b) {
    asm volatile("st.global.cs.v2.f32 [%0], {%1,%2};" :: "l"(p), "f"(a), "f"(b));
}

// ---------------------------------------------------------------------------
// Split fp32 inputs into fp16 planes. X/wq/wk: hi only. wv/wo (x64): hi + lo.
// ---------------------------------------------------------------------------
__global__ __launch_bounds__(256) void split_all(
    const float* __restrict__ X, const float* __restrict__ wq,
    const float* __restrict__ wk, const float* __restrict__ wv,
    const float* __restrict__ wo)
{
    size_t i = (size_t)blockIdx.x * 256 + threadIdx.x;
    if (i < 1048576) {
        float4 v = ((const float4*)X)[i];
        ((unsigned*)g_xh)[i * 2]     = packh_f(v.x, v.y);
        ((unsigned*)g_xh)[i * 2 + 1] = packh_f(v.z, v.w);
        return;
    }
    size_t j = i - 1048576;
    int w = (int)(j >> 18);
    size_t off = j & 262143;
    const float* src; __half *dh, *dl;
    if      (w == 0) { src = wq; dh = g_wqh; dl = nullptr; }
    else if (w == 1) { src = wk; dh = g_wkh; dl = nullptr; }
    else if (w == 2) { src = wv; dh = g_wvh; dl = g_wvl; }
    else             { src = wo; dh = g_woh; dl = g_wol; }
    float4 v = ((const float4*)src)[off];
    unsigned h0, l0, h1, l1;
    split_pair_h(v.x * 64.f, v.y * 64.f, h0, l0);
    split_pair_h(v.z * 64.f, v.w * 64.f, h1, l1);
    ((unsigned*)dh)[off * 2] = h0; ((unsigned*)dh)[off * 2 + 1] = h1;
    if (dl) {
        ((unsigned*)dl)[off * 2] = l0; ((unsigned*)dl)[off * 2 + 1] = l1;
    }
}

// ---------------------------------------------------------------------------
// GEMM tile constants: up to 3 planes per stage (Ah, Bh, Bl), K-chunk 32.
// ---------------------------------------------------------------------------
#define GSTR  40
#define GPL   (128 * GSTR)
#define GSTG  (3 * GPL)

// ---------------------------------------------------------------------------
// QKV projection GEMM, cp.async 3-stage, single sync per k-tile.
// q,k: 1 MMA (Wh only). v: 2 MMA (Wh+Wl). Outputs hi-only, unscaled by 0.125.
// ---------------------------------------------------------------------------
__global__ __launch_bounds__(256, 2) void gemm_qkv(
    const float* __restrict__ bq, const float* __restrict__ bk, const float* __restrict__ bv)
{
    extern __shared__ __half sb[];

    const int wsel = blockIdx.y >> 3;
    const int n0   = (blockIdx.y & 7) * 128;
    const int m0   = blockIdx.x * 128;

    const __half* Wh = (wsel == 0) ? g_wqh : (wsel == 1) ? g_wkh : g_wvh;
    const float* bias = (wsel == 0) ? bq : (wsel == 1) ? bk : bv;
    __half* dh = (wsel == 0) ? g_qh : (wsel == 1) ? g_kh : g_vh;
    const bool use_lo = (wsel == 2);

    const int tid = threadIdx.x, lane = tid & 31, wid = tid >> 5;
    const int wm = (wid >> 2) * 64, wn = (wid & 3) * 32;
    const int lr = tid >> 2;
    const int lc = (tid & 3) * 8;

    float acc[4][4][4];
#pragma unroll
    for (int i = 0; i < 4; i++)
#pragma unroll
        for (int j = 0; j < 4; j++)
#pragma unroll
            for (int q = 0; q < 4; q++) acc[i][j][q] = 0.f;

    auto load_stage = [&](int s, int k0) {
        __half* base = sb + s * GSTG;
#pragma unroll
        for (int rr = 0; rr < 128; rr += 64) {
            int row = rr + lr;
            size_t ga = (size_t)(m0 + row) * 1024 + k0 + lc;
            size_t gb = (size_t)(n0 + row) * 1024 + k0 + lc;
            unsigned d = smem_u32(base + row * GSTR + lc);
            cp16(d,           g_xh + ga);
            cp16(d + GPL * 2, Wh + gb);
            if (use_lo) cp16(d + GPL * 4, g_wvl + gb);
        }
    };

    load_stage(0, 0);  cp_commit();
    load_stage(1, 32); cp_commit();

    for (int kt = 0; kt < 32; kt++) {
        if (kt < 31) cp_wait<1>(); else cp_wait<0>();
        __syncthreads();
        if (kt + 2 < 32) { load_stage((kt + 2) % 3, (kt + 2) * 32); cp_commit(); }

        const __half* Ah = sb + (kt % 3) * GSTG;
        const __half* Bh = Ah + GPL;
        const __half* Bl = Bh + GPL;

#pragma unroll
        for (int kf = 0; kf < 2; kf++) {
            unsigned ah[4][4];
#pragma unroll
            for (int i = 0; i < 4; i++) {
                int aoff = (wm + i * 16 + (lane & 15)) * GSTR + kf * 16 + (lane >> 4) * 8;
                ldmA(smem_u32(&Ah[aoff]), ah[i][0], ah[i][1], ah[i][2], ah[i][3]);
            }
#pragma unroll
            for (int jj = 0; jj < 2; jj++) {
                int boff = (wn + jj * 16 + (lane & 7) + ((lane >> 4) & 1) * 8) * GSTR
                         + kf * 16 + ((lane >> 3) & 1) * 8;
                unsigned b0, b1, b2, b3;
                ldmB4(smem_u32(&Bh[boff]), b0, b1, b2, b3);
#pragma unroll
                for (int i = 0; i < 4; i++) {
                    mma16816(acc[i][2 * jj],     ah[i][0], ah[i][1], ah[i][2], ah[i][3], b0, b1);
                    mma16816(acc[i][2 * jj + 1], ah[i][0], ah[i][1], ah[i][2], ah[i][3], b2, b3);
                }
                if (use_lo) {
                    unsigned l0, l1, l2, l3;
                    ldmB4(smem_u32(&Bl[boff]), l0, l1, l2, l3);
#pragma unroll
                    for (int i = 0; i < 4; i++) {
                        mma16816(acc[i][2 * jj],     ah[i][0], ah[i][1], ah[i][2], ah[i][3], l0, l1);
                        mma16816(acc[i][2 * jj + 1], ah[i][0], ah[i][1], ah[i][2], ah[i][3], l2, l3);
                    }
                }
            }
        }
    }

    const float inv64 = 0.015625f;
#pragma unroll
    for (int i = 0; i < 4; i++) {
#pragma unroll
        for (int j = 0; j < 4; j++) {
            int col = n0 + wn + j * 8 + (lane & 3) * 2;
            float b0 = bias[col], b1 = bias[col + 1];
            int h = col >> 6, d = col & 63;
#pragma unroll
            for (int hf = 0; hf < 2; hf++) {
                int r = m0 + wm + i * 16 + (lane >> 2) + hf * 8;
                float v0 = acc[i][j][2 * hf + 0] * inv64 + b0;
                float v1 = acc[i][j][2 * hf + 1] * inv64 + b1;
                size_t off = (size_t)((r & 1) * 16 + h) * HD + (size_t)(r >> 1) * 64 + d;
                *(unsigned*)&dh[off] = packh_f(v0, v1);
            }
        }
    }
}

// ---------------------------------------------------------------------------
// Attention score half-tile (fp16): acc = qh(16 rows) @ kh^T(64 cols at `co`).
// x4 B-loads: one ldmatrix per TWO n8 fragments.
// ---------------------------------------------------------------------------
#define ASTR 72
#define APL  (128 * ASTR)

__device__ __forceinline__ void compute_scores1(
    const __half* Qh, const __half* Kh,
    int wr, int co, int lane, float acc[8][4])
{
#pragma unroll
    for (int j = 0; j < 8; j++)
#pragma unroll
        for (int q = 0; q < 4; q++) acc[j][q] = 0.f;

#pragma unroll
    for (int kf = 0; kf < 4; kf++) {
        unsigned ah[4];
        int qoff = (wr + (lane & 15)) * ASTR + kf * 16 + (lane >> 4) * 8;
        ldmA(smem_u32(&Qh[qoff]), ah[0], ah[1], ah[2], ah[3]);
#pragma unroll
        for (int jj = 0; jj < 4; jj++) {
            int koff = (co + jj * 16 + (lane & 7) + ((lane >> 4) & 1) * 8) * ASTR
                     + kf * 16 + ((lane >> 3) & 1) * 8;
            unsigned b0, b1, b2, b3;
            ldmB4(smem_u32(&Kh[koff]), b0, b1, b2, b3);
            mma16816(acc[2 * jj],     ah[0], ah[1], ah[2], ah[3], b0, b1);
            mma16816(acc[2 * jj + 1], ah[0], ah[1], ah[2], ah[3], b2, b3);
        }
    }
}

// ---------------------------------------------------------------------------
// Attention: per (head n, 128-row q-block). 512 threads / 16 warps.
// rowgrp = wid&7 (16 rows); column half hv = wid>>3 (64 of 128 cols).
// Max-free softmax. 3-stage cp.async, 1 sync per tile.
// smem planes: Qh(1) + 3 stages x (Kh,Vh) = 7 APL = 129,024 B.
// ---------------------------------------------------------------------------
__global__ __launch_bounds__(512, 1) void attn_kernel(float* __restrict__ w_out)
{
    extern __shared__ __half sm[];
    __half* Qh = sm;
    // stage s (s=0..2): sm + APL + s*2*APL -> Kh, Vh

    const int n   = blockIdx.y;
    const int qb  = blockIdx.x * 128;
    const int tid = threadIdx.x, lane = tid & 31, wid = tid >> 5;
    const int rowgrp = wid & 7, hv = wid >> 3;
    const int wr = rowgrp * 16, co = hv * 64;

    const __half* qhg = g_qh + (size_t)n * HD + (size_t)qb * 64;
    const __half* khg = g_kh + (size_t)n * HD;
    const __half* vhg = g_vh + (size_t)n * HD;

    for (int idx = tid; idx < 128 * 8; idx += 512) {
        int row = idx >> 3, c = (idx & 7) * 8;
        *(uint4*)&Qh[row * ASTR + c] = *(const uint4*)(qhg + (size_t)row * 64 + c);
    }

    const int ar = tid >> 3, ac = (tid & 7) * 8;

    auto load_k1 = [&](int s, int sc) {
        __half* kh = sm + APL + s * 2 * APL;
#pragma unroll
        for (int rr = 0; rr < 128; rr += 64) {
            int row = rr + ar;
            size_t g = (size_t)(sc * 128 + row) * 64 + ac;
            cp16(smem_u32(&kh[row * ASTR + ac]), khg + g);
        }
    };
    auto load_kv = [&](int s, int sc) {
        __half* kh = sm + APL + s * 2 * APL;
#pragma unroll
        for (int rr = 0; rr < 128; rr += 64) {
            int row = rr + ar;
            size_t g = (size_t)(sc * 128 + row) * 64 + ac;
            unsigned d = smem_u32(&kh[row * ASTR + ac]);
            cp16(d,           khg + g);
            cp16(d + APL * 2, vhg + g);
        }
    };

    float lv[2] = {0.f, 0.f};

    // ---------------- pass 1: l partials (qh*kh scores, no max) ------------
    load_k1(0, 0); cp_commit();
    load_k1(1, 1); cp_commit();
    for (int sc = 0; sc < 16; sc++) {
        if (sc < 15) cp_wait<1>(); else cp_wait<0>();
        __syncthreads();
        if (sc + 2 < 16) { load_k1((sc + 2) % 3, sc + 2); cp_commit(); }

        const __half* Kh = sm + APL + (sc % 3) * 2 * APL;

        float acc[8][4];
        compute_scores1(Qh, Kh, wr, co, lane, acc);

#pragma unroll
        for (int j = 0; j < 8; j++) {
            lv[0] += exp2f(acc[j][0] * EC) + exp2f(acc[j][1] * EC);
            lv[1] += exp2f(acc[j][2] * EC) + exp2f(acc[j][3] * EC);
        }
    }

    // single reduction: across lane quad, then across column halves via smem
#pragma unroll
    for (int hf = 0; hf < 2; hf++) {
        lv[hf] += __shfl_xor_sync(0xffffffffu, lv[hf], 1);
        lv[hf] += __shfl_xor_sync(0xffffffffu, lv[hf], 2);
    }
    float* st = (float*)(sm + APL);   // overlaps stage bufs; sync first
    __syncthreads();
    if ((lane & 3) == 0) {
        int r_ = lane >> 2;
        st[hv * 128 + rowgrp * 16 + r_]     = lv[0];
        st[hv * 128 + rowgrp * 16 + r_ + 8] = lv[1];
    }
    __syncthreads();
    float invl[2];
#pragma unroll
    for (int hf = 0; hf < 2; hf++) {
        int r_ = (lane >> 2) + hf * 8;
        invl[hf] = 1.0f / (st[rowgrp * 16 + r_] + st[128 + rowgrp * 16 + r_]);
    }
    __syncthreads();   // st reads done before pass-2 loads overwrite

    float o[8][4];
#pragma unroll
    for (int j = 0; j < 8; j++)
#pragma unroll
        for (int q = 0; q < 4; q++) o[j][q] = 0.f;

    // ---------------- pass 2: weights out + partial P@V ----------------
    load_kv(0, 0); cp_commit();
    load_kv(1, 1); cp_commit();
    for (int sc = 0; sc < 16; sc++) {
        if (sc < 15) cp_wait<1>(); else cp_wait<0>();
        __syncthreads();
        if (sc + 2 < 16) { load_kv((sc + 2) % 3, sc + 2); cp_commit(); }

        const __half* Kh = sm + APL + (sc % 3) * 2 * APL;
        const __half* Vh = Kh + APL;

        float acc[8][4];
        compute_scores1(Qh, Kh, wr, co, lane, acc);

        float* wb = w_out + (size_t)n * ((size_t)T_DIM * T_DIM)
                  + (size_t)(qb + wr + (lane >> 2)) * T_DIM + sc * 128 + co + (lane & 3) * 2;
#pragma unroll
        for (int j = 0; j < 8; j++) {
            float p0 = exp2f(acc[j][0] * EC) * invl[0];
            float p1 = exp2f(acc[j][1] * EC) * invl[0];
            float p2 = exp2f(acc[j][2] * EC) * invl[1];
            float p3 = exp2f(acc[j][3] * EC) * invl[1];
            acc[j][0] = p0; acc[j][1] = p1; acc[j][2] = p2; acc[j][3] = p3;
            stg_cs_f2(wb + j * 8, p0, p1);
            stg_cs_f2(wb + 8 * (size_t)T_DIM + j * 8, p2, p3);
        }

        // PV: p hi-only x Vh; x4 trans loads = 1 ldmatrix per 2 d8-fragments
#pragma unroll
        for (int g = 0; g < 4; g++) {
            unsigned a0 = packh_f(acc[2 * g][0],     acc[2 * g][1]);
            unsigned a1 = packh_f(acc[2 * g][2],     acc[2 * g][3]);
            unsigned a2 = packh_f(acc[2 * g + 1][0], acc[2 * g + 1][1]);
            unsigned a3 = packh_f(acc[2 * g + 1][2], acc[2 * g + 1][3]);
#pragma unroll
            for (int jj = 0; jj < 4; jj++) {
                int voff = (co + g * 16 + (lane & 7) + ((lane >> 3) & 1) * 8) * ASTR
                         + jj * 16 + ((lane >> 4) & 1) * 8;
                unsigned b0, b1, b2, b3;
                ldmBT4(smem_u32(&Vh[voff]), b0, b1, b2, b3);
                mma16816(o[2 * jj],     a0, a1, a2, a3, b0, b1);
                mma16816(o[2 * jj + 1], a0, a1, a2, a3, b2, b3);
            }
        }
    }

    // ---------------- merge partial O across the two halves ----------------
    float* os = (float*)sm;
    __syncthreads();
    if (hv == 1) {
#pragma unroll
        for (int j = 0; j < 8; j++)
#pragma unroll
            for (int q = 0; q < 4; q++)
                os[(rowgrp * 32 + lane) * 32 + j * 4 + q] = o[j][q];
    }
    __syncthreads();
    if (hv == 0) {
#pragma unroll
        for (int j = 0; j < 8; j++)
#pragma unroll
            for (int q = 0; q < 4; q++)
                o[j][q] += os[(rowgrp * 32 + lane) * 32 + j * 4 + q];

        const int bsel = n >> 4, h = n & 15;
        const int t0   = qb + wr + (lane >> 2);
        const int dcol = (lane & 3) * 2;
#pragma unroll
        for (int j = 0; j < 8; j++) {
            int d = j * 8 + dcol;
            size_t off = (size_t)(t0 * 2 + bsel) * E_DIM + h * 64 + d;
            *(unsigned*)&g_ah[off] = packh_f(o[j][0], o[j][1]);
            off = (size_t)((t0 + 8) * 2 + bsel) * E_DIM + h * 64 + d;
            *(unsigned*)&g_ah[off] = packh_f(o[j][2], o[j][3]);
        }
    }
}

// ---------------------------------------------------------------------------
// Output projection (fp16x2), cp.async 3-stage, single sync per k-tile.
// ---------------------------------------------------------------------------
__global__ __launch_bounds__(256, 2) void gemm_out(
    const float* __restrict__ bo, float* __restrict__ out)
{
    extern __shared__ __half sb[];

    const int n0 = blockIdx.y * 128;
    const int m0 = blockIdx.x * 128;

    const int tid = threadIdx.x, lane = tid & 31, wid = tid >> 5;
    const int wm = (wid >> 2) * 64, wn = (wid & 3) * 32;
    const int lr = tid >> 2;
    const int lc = (tid & 3) * 8;

    float acc[4][4][4];
#pragma unroll
    for (int i = 0; i < 4; i++)
#pragma unroll
        for (int j = 0; j < 4; j++)
#pragma unroll
            for (int q = 0; q < 4; q++) acc[i][j][q] = 0.f;

    auto load_stage = [&](int s, int k0) {
        __half* base = sb + s * GSTG;
#pragma unroll
        for (int rr = 0; rr < 128; rr += 64) {
            int row = rr + lr;
            size_t ga = (size_t)(m0 + row) * 1024 + k0 + lc;
            size_t gb = (size_t)(n0 + row) * 1024 + k0 + lc;
            unsigned d = smem_u32(base + row * GSTR + lc);
            cp16(d,           g_ah + ga);
            cp16(d + GPL * 2, g_woh + gb);
            cp16(d + GPL * 4, g_wol + gb);
        }
    };

    load_stage(0, 0);  cp_commit();
    load_stage(1, 32); cp_commit();

    for (int kt = 0; kt < 32; kt++) {
        if (kt < 31) cp_wait<1>(); else cp_wait<0>();
        __syncthreads();
        if (kt + 2 < 32) { load_stage((kt + 2) % 3, (kt + 2) * 32); cp_commit(); }

        const __half* Ah = sb + (kt % 3) * GSTG;
        const __half* Bh = Ah + GPL;
        const __half* Bl = Bh + GPL;

#pragma unroll
        for (int kf = 0; kf < 2; kf++) {
            unsigned ah[4][4];
#pragma unroll
            for (int i = 0; i < 4; i++) {
                int aoff = (wm + i * 16 + (lane & 15)) * GSTR + kf * 16 + (lane >> 4) * 8;
                ldmA(smem_u32(&Ah[aoff]), ah[i][0], ah[i][1], ah[i][2], ah[i][3]);
            }
#pragma unroll
            for (int jj = 0; jj < 2; jj++) {
                int boff = (wn + jj * 16 + (lane & 7) + ((lane >> 4) & 1) * 8) * GSTR
                         + kf * 16 + ((lane >> 3) & 1) * 8;
                unsigned b0, b1, b2, b3, l0, l1, l2, l3;
                ldmB4(smem_u32(&Bh[boff]), b0, b1, b2, b3);
                ldmB4(smem_u32(&Bl[boff]), l0, l1, l2, l3);
#pragma unroll
                for (int i = 0; i < 4; i++) {
                    mma16816(acc[i][2 * jj],     ah[i][0], ah[i][1], ah[i][2], ah[i][3], b0, b1);
                    mma16816(acc[i][2 * jj],     ah[i][0], ah[i][1], ah[i][2], ah[i][3], l0, l1);
                    mma16816(acc[i][2 * jj + 1], ah[i][0], ah[i][1], ah[i][2], ah[i][3], b2, b3);
                    mma16816(acc[i][2 * jj + 1], ah[i][0], ah[i][1], ah[i][2], ah[i][3], l2, l3);
                }
            }
        }
    }

    const float inv64 = 0.015625f;
#pragma unroll
    for (int i = 0; i < 4; i++) {
#pragma unroll
        for (int j = 0; j < 4; j++) {
            int col = n0 + wn + j * 8 + (lane & 3) * 2;
            float b0 = bo[col], b1 = bo[col + 1];
#pragma unroll
            for (int hf = 0; hf < 2; hf++) {
                int r = m0 + wm + i * 16 + (lane >> 2) + hf * 8;
                float2 v;
                v.x = acc[i][j][2 * hf + 0] * inv64 + b0;
                v.y = acc[i][j][2 * hf + 1] * inv64 + b1;
                *(float2*)(out + (size_t)r * 1024 + col) = v;
            }
        }
    }
}

// ---------------------------------------------------------------------------
// d_out = [ out (4096*1024 fp32) | attn_weights (32*2048*2048 fp32) ]
// ---------------------------------------------------------------------------
extern "C" void kernel_launch(void* const* d_in, const int* in_sizes, int n_in,
                              void* d_out, int out_size)
{
    const float* query = (const float*)d_in[0];
    const float* wq    = (const float*)d_in[1];
    const float* bq    = (const float*)d_in[2];
    const float* wk    = (const float*)d_in[3];
    const float* bk    = (const float*)d_in[4];
    const float* wv    = (const float*)d_in[5];
    const float* bv    = (const float*)d_in[6];
    const float* wo    = (const float*)d_in[7];
    const float* bo    = (const float*)d_in[8];

    float* out   = (float*)d_out;
    float* w_out = out + (size_t)M_DIM * E_DIM;

    const int gemm_smem = 3 * GSTG * (int)sizeof(__half);   // 92,160 B
    const int attn_smem = 7 * APL * (int)sizeof(__half);    // 129,024 B
    cudaFuncSetAttribute(gemm_qkv,    cudaFuncAttributeMaxDynamicSharedMemorySize, gemm_smem);
    cudaFuncSetAttribute(attn_kernel, cudaFuncAttributeMaxDynamicSharedMemorySize, attn_smem);
    cudaFuncSetAttribute(gemm_out,    cudaFuncAttributeMaxDynamicSharedMemorySize, gemm_smem);

    split_all<<<8192, 256>>>(query, wq, wk, wv, wo);
    gemm_qkv<<<dim3(32, 24), 256, gemm_smem>>>(bq, bk, bv);
    attn_kernel<<<dim3(16, 32), 512, attn_smem>>>(w_out);
    gemm_out<<<dim3(32, 8), 256, gemm_smem>>>(bo, out);
}

// round 16
// speedup vs baseline: 6.2293x; 1.1534x over previous
#include <cuda_runtime.h>
#include <cuda_bf16.h>
#include <cuda_fp16.h>

// T=2048, B=2, E=1024, H=16, D=64
#define T_DIM 2048
#define E_DIM 1024
#define NH    32            // B*H
#define M_DIM 4096          // T*B
#define HD    (T_DIM * 64)  // per-head plane elems

// 0.125 * log2(e): score scaling folded into exp2
#define EC 0.18033688011112042f

// ---------------------------------------------------------------------------
// Device-global scratch: single fp16 plane everywhere (fp32 accumulation in
// all MMAs carries the precision; error budget calibrated over rounds 11-15).
// ---------------------------------------------------------------------------
__device__ __half g_xh[(size_t)M_DIM * E_DIM];
__device__ __half g_wqh[1024 * 1024];
__device__ __half g_wkh[1024 * 1024];
__device__ __half g_wvh[1024 * 1024];
__device__ __half g_woh[1024 * 1024];
__device__ __half g_qh[(size_t)NH * HD];                          // q, unscaled
__device__ __half g_kh[(size_t)NH * HD];
__device__ __half g_vh[(size_t)NH * HD];
__device__ __half g_ah[(size_t)M_DIM * E_DIM];                    // attn result

// ---------------------------------------------------------------------------
// Helpers
// ---------------------------------------------------------------------------
__device__ __forceinline__ unsigned smem_u32(const void* p) {
    return (unsigned)__cvta_generic_to_shared(p);
}
__device__ __forceinline__ void cp16(unsigned dst, const void* src) {
    asm volatile("cp.async.cg.shared.global [%0], [%1], 16;" :: "r"(dst), "l"(src));
}
__device__ __forceinline__ void cp_commit() {
    asm volatile("cp.async.commit_group;");
}
template <int N> __device__ __forceinline__ void cp_wait() {
    asm volatile("cp.async.wait_group %0;" :: "n"(N));
}
__device__ __forceinline__ void ldmA(unsigned addr, unsigned& r0, unsigned& r1,
                                     unsigned& r2, unsigned& r3) {
    asm volatile("ldmatrix.sync.aligned.m8n8.x4.shared.b16 {%0,%1,%2,%3}, [%4];"
                 : "=r"(r0), "=r"(r1), "=r"(r2), "=r"(r3) : "r"(addr));
}
// x4 load of TWO adjacent n8k16 B-fragments (j, j+1)
__device__ __forceinline__ void ldmB4(unsigned addr, unsigned& r0, unsigned& r1,
                                      unsigned& r2, unsigned& r3) {
    asm volatile("ldmatrix.sync.aligned.m8n8.x4.shared.b16 {%0,%1,%2,%3}, [%4];"
                 : "=r"(r0), "=r"(r1), "=r"(r2), "=r"(r3) : "r"(addr));
}
// x4 transposed load of TWO adjacent B-fragments for PV
__device__ __forceinline__ void ldmBT4(unsigned addr, unsigned& r0, unsigned& r1,
                                       unsigned& r2, unsigned& r3) {
    asm volatile("ldmatrix.sync.aligned.m8n8.x4.trans.shared.b16 {%0,%1,%2,%3}, [%4];"
                 : "=r"(r0), "=r"(r1), "=r"(r2), "=r"(r3) : "r"(addr));
}
// fp16 MMA, fp32 accumulate
__device__ __forceinline__ void mma16816(float* c, unsigned a0, unsigned a1,
                                         unsigned a2, unsigned a3,
                                         unsigned b0, unsigned b1) {
    asm volatile(
        "mma.sync.aligned.m16n8k16.row.col.f32.f16.f16.f32 "
        "{%0,%1,%2,%3}, {%4,%5,%6,%7}, {%8,%9}, {%0,%1,%2,%3};"
        : "+f"(c[0]), "+f"(c[1]), "+f"(c[2]), "+f"(c[3])
        : "r"(a0), "r"(a1), "r"(a2), "r"(a3), "r"(b0), "r"(b1));
}
// single-instruction f32 pair -> packed f16x2 (lo = x, hi = y), round-nearest
__device__ __forceinline__ unsigned packh_f(float x, float y) {
    unsigned r;
    asm("cvt.rn.f16x2.f32 %0, %1, %2;" : "=r"(r) : "f"(y), "f"(x));
    return r;
}
__device__ __forceinline__ void stg_cs_f2(float* p, float a, float b) {
    asm volatile("st.global.cs.v2.f32 [%0], {%1,%2};" :: "l"(p), "f"(a), "f"(b));
}

// ---------------------------------------------------------------------------
// Split fp32 inputs into fp16 (all hi-only). 2M float4 elems total.
// ---------------------------------------------------------------------------
__global__ __launch_bounds__(256) void split_all(
    const float* __restrict__ X, const float* __restrict__ wq,
    const float* __restrict__ wk, const float* __restrict__ wv,
    const float* __restrict__ wo)
{
    size_t i = (size_t)blockIdx.x * 256 + threadIdx.x;
    const float* src; __half* dh; size_t off;
    if (i < 1048576) { src = X; dh = g_xh; off = i; }
    else {
        size_t j = i - 1048576;
        int w = (int)(j >> 18);
        off = j & 262143;
        if      (w == 0) { src = wq; dh = g_wqh; }
        else if (w == 1) { src = wk; dh = g_wkh; }
        else if (w == 2) { src = wv; dh = g_wvh; }
        else             { src = wo; dh = g_woh; }
    }
    float4 v = ((const float4*)src)[off];
    ((unsigned*)dh)[off * 2]     = packh_f(v.x, v.y);
    ((unsigned*)dh)[off * 2 + 1] = packh_f(v.z, v.w);
}

// ---------------------------------------------------------------------------
// GEMM tile constants: 2 planes per stage (A, B), K-chunk 32, 3 stages.
// ---------------------------------------------------------------------------
#define GSTR  40
#define GPL   (128 * GSTR)
#define GSTG  (2 * GPL)

// ---------------------------------------------------------------------------
// QKV projection GEMM (single-plane fp16), cp.async 3-stage, 1 sync/k-tile.
// Outputs unscaled by 0.125 (applied via EC at score stage).
// ---------------------------------------------------------------------------
__global__ __launch_bounds__(256, 2) void gemm_qkv(
    const float* __restrict__ bq, const float* __restrict__ bk, const float* __restrict__ bv)
{
    extern __shared__ __half sb[];

    const int wsel = blockIdx.y >> 3;
    const int n0   = (blockIdx.y & 7) * 128;
    const int m0   = blockIdx.x * 128;

    const __half* Wh = (wsel == 0) ? g_wqh : (wsel == 1) ? g_wkh : g_wvh;
    const float* bias = (wsel == 0) ? bq : (wsel == 1) ? bk : bv;
    __half* dh = (wsel == 0) ? g_qh : (wsel == 1) ? g_kh : g_vh;

    const int tid = threadIdx.x, lane = tid & 31, wid = tid >> 5;
    const int wm = (wid >> 2) * 64, wn = (wid & 3) * 32;
    const int lr = tid >> 2;
    const int lc = (tid & 3) * 8;

    float acc[4][4][4];
#pragma unroll
    for (int i = 0; i < 4; i++)
#pragma unroll
        for (int j = 0; j < 4; j++)
#pragma unroll
            for (int q = 0; q < 4; q++) acc[i][j][q] = 0.f;

    auto load_stage = [&](int s, int k0) {
        __half* base = sb + s * GSTG;
#pragma unroll
        for (int rr = 0; rr < 128; rr += 64) {
            int row = rr + lr;
            size_t ga = (size_t)(m0 + row) * 1024 + k0 + lc;
            size_t gb = (size_t)(n0 + row) * 1024 + k0 + lc;
            unsigned d = smem_u32(base + row * GSTR + lc);
            cp16(d,           g_xh + ga);
            cp16(d + GPL * 2, Wh + gb);
        }
    };

    load_stage(0, 0);  cp_commit();
    load_stage(1, 32); cp_commit();

    for (int kt = 0; kt < 32; kt++) {
        if (kt < 31) cp_wait<1>(); else cp_wait<0>();
        __syncthreads();
        if (kt + 2 < 32) { load_stage((kt + 2) % 3, (kt + 2) * 32); cp_commit(); }

        const __half* Ah = sb + (kt % 3) * GSTG;
        const __half* Bh = Ah + GPL;

#pragma unroll
        for (int kf = 0; kf < 2; kf++) {
            unsigned ah[4][4];
#pragma unroll
            for (int i = 0; i < 4; i++) {
                int aoff = (wm + i * 16 + (lane & 15)) * GSTR + kf * 16 + (lane >> 4) * 8;
                ldmA(smem_u32(&Ah[aoff]), ah[i][0], ah[i][1], ah[i][2], ah[i][3]);
            }
#pragma unroll
            for (int jj = 0; jj < 2; jj++) {
                int boff = (wn + jj * 16 + (lane & 7) + ((lane >> 4) & 1) * 8) * GSTR
                         + kf * 16 + ((lane >> 3) & 1) * 8;
                unsigned b0, b1, b2, b3;
                ldmB4(smem_u32(&Bh[boff]), b0, b1, b2, b3);
#pragma unroll
                for (int i = 0; i < 4; i++) {
                    mma16816(acc[i][2 * jj],     ah[i][0], ah[i][1], ah[i][2], ah[i][3], b0, b1);
                    mma16816(acc[i][2 * jj + 1], ah[i][0], ah[i][1], ah[i][2], ah[i][3], b2, b3);
                }
            }
        }
    }

#pragma unroll
    for (int i = 0; i < 4; i++) {
#pragma unroll
        for (int j = 0; j < 4; j++) {
            int col = n0 + wn + j * 8 + (lane & 3) * 2;
            float b0 = bias[col], b1 = bias[col + 1];
            int h = col >> 6, d = col & 63;
#pragma unroll
            for (int hf = 0; hf < 2; hf++) {
                int r = m0 + wm + i * 16 + (lane >> 2) + hf * 8;
                float v0 = acc[i][j][2 * hf + 0] + b0;
                float v1 = acc[i][j][2 * hf + 1] + b1;
                size_t off = (size_t)((r & 1) * 16 + h) * HD + (size_t)(r >> 1) * 64 + d;
                *(unsigned*)&dh[off] = packh_f(v0, v1);
            }
        }
    }
}

// ---------------------------------------------------------------------------
// Attention score half-tile (fp16): acc = qh(16 rows) @ kh^T(64 cols at `co`).
// ---------------------------------------------------------------------------
#define ASTR 72
#define APL  (128 * ASTR)

__device__ __forceinline__ void compute_scores1(
    const __half* Qh, const __half* Kh,
    int wr, int co, int lane, float acc[8][4])
{
#pragma unroll
    for (int j = 0; j < 8; j++)
#pragma unroll
        for (int q = 0; q < 4; q++) acc[j][q] = 0.f;

#pragma unroll
    for (int kf = 0; kf < 4; kf++) {
        unsigned ah[4];
        int qoff = (wr + (lane & 15)) * ASTR + kf * 16 + (lane >> 4) * 8;
        ldmA(smem_u32(&Qh[qoff]), ah[0], ah[1], ah[2], ah[3]);
#pragma unroll
        for (int jj = 0; jj < 4; jj++) {
            int koff = (co + jj * 16 + (lane & 7) + ((lane >> 4) & 1) * 8) * ASTR
                     + kf * 16 + ((lane >> 3) & 1) * 8;
            unsigned b0, b1, b2, b3;
            ldmB4(smem_u32(&Kh[koff]), b0, b1, b2, b3);
            mma16816(acc[2 * jj],     ah[0], ah[1], ah[2], ah[3], b0, b1);
            mma16816(acc[2 * jj + 1], ah[0], ah[1], ah[2], ah[3], b2, b3);
        }
    }
}

// ---------------------------------------------------------------------------
// Attention: per (head n, 128-row q-block). 512 threads / 16 warps.
// rowgrp = wid&7 (16 rows); column half hv = wid>>3 (64 of 128 cols).
// Max-free softmax. 3-stage cp.async, 1 sync per tile.
// smem planes: Qh(1) + 3 stages x (Kh,Vh) = 7 APL = 129,024 B.
// ---------------------------------------------------------------------------
__global__ __launch_bounds__(512, 1) void attn_kernel(float* __restrict__ w_out)
{
    extern __shared__ __half sm[];
    __half* Qh = sm;
    // stage s (s=0..2): sm + APL + s*2*APL -> Kh, Vh

    const int n   = blockIdx.y;
    const int qb  = blockIdx.x * 128;
    const int tid = threadIdx.x, lane = tid & 31, wid = tid >> 5;
    const int rowgrp = wid & 7, hv = wid >> 3;
    const int wr = rowgrp * 16, co = hv * 64;

    const __half* qhg = g_qh + (size_t)n * HD + (size_t)qb * 64;
    const __half* khg = g_kh + (size_t)n * HD;
    const __half* vhg = g_vh + (size_t)n * HD;

    for (int idx = tid; idx < 128 * 8; idx += 512) {
        int row = idx >> 3, c = (idx & 7) * 8;
        *(uint4*)&Qh[row * ASTR + c] = *(const uint4*)(qhg + (size_t)row * 64 + c);
    }

    const int ar = tid >> 3, ac = (tid & 7) * 8;

    auto load_k1 = [&](int s, int sc) {
        __half* kh = sm + APL + s * 2 * APL;
#pragma unroll
        for (int rr = 0; rr < 128; rr += 64) {
            int row = rr + ar;
            size_t g = (size_t)(sc * 128 + row) * 64 + ac;
            cp16(smem_u32(&kh[row * ASTR + ac]), khg + g);
        }
    };
    auto load_kv = [&](int s, int sc) {
        __half* kh = sm + APL + s * 2 * APL;
#pragma unroll
        for (int rr = 0; rr < 128; rr += 64) {
            int row = rr + ar;
            size_t g = (size_t)(sc * 128 + row) * 64 + ac;
            unsigned d = smem_u32(&kh[row * ASTR + ac]);
            cp16(d,           khg + g);
            cp16(d + APL * 2, vhg + g);
        }
    };

    float lv[2] = {0.f, 0.f};

    // ---------------- pass 1: l partials (qh*kh scores, no max) ------------
    load_k1(0, 0); cp_commit();
    load_k1(1, 1); cp_commit();
    for (int sc = 0; sc < 16; sc++) {
        if (sc < 15) cp_wait<1>(); else cp_wait<0>();
        __syncthreads();
        if (sc + 2 < 16) { load_k1((sc + 2) % 3, sc + 2); cp_commit(); }

        const __half* Kh = sm + APL + (sc % 3) * 2 * APL;

        float acc[8][4];
        compute_scores1(Qh, Kh, wr, co, lane, acc);

#pragma unroll
        for (int j = 0; j < 8; j++) {
            lv[0] += exp2f(acc[j][0] * EC) + exp2f(acc[j][1] * EC);
            lv[1] += exp2f(acc[j][2] * EC) + exp2f(acc[j][3] * EC);
        }
    }

    // single reduction: across lane quad, then across column halves via smem
#pragma unroll
    for (int hf = 0; hf < 2; hf++) {
        lv[hf] += __shfl_xor_sync(0xffffffffu, lv[hf], 1);
        lv[hf] += __shfl_xor_sync(0xffffffffu, lv[hf], 2);
    }
    float* st = (float*)(sm + APL);   // overlaps stage bufs; sync first
    __syncthreads();
    if ((lane & 3) == 0) {
        int r_ = lane >> 2;
        st[hv * 128 + rowgrp * 16 + r_]     = lv[0];
        st[hv * 128 + rowgrp * 16 + r_ + 8] = lv[1];
    }
    __syncthreads();
    float invl[2];
#pragma unroll
    for (int hf = 0; hf < 2; hf++) {
        int r_ = (lane >> 2) + hf * 8;
        invl[hf] = 1.0f / (st[rowgrp * 16 + r_] + st[128 + rowgrp * 16 + r_]);
    }
    __syncthreads();   // st reads done before pass-2 loads overwrite

    float o[8][4];
#pragma unroll
    for (int j = 0; j < 8; j++)
#pragma unroll
        for (int q = 0; q < 4; q++) o[j][q] = 0.f;

    // ---------------- pass 2: weights out + partial P@V ----------------
    load_kv(0, 0); cp_commit();
    load_kv(1, 1); cp_commit();
    for (int sc = 0; sc < 16; sc++) {
        if (sc < 15) cp_wait<1>(); else cp_wait<0>();
        __syncthreads();
        if (sc + 2 < 16) { load_kv((sc + 2) % 3, sc + 2); cp_commit(); }

        const __half* Kh = sm + APL + (sc % 3) * 2 * APL;
        const __half* Vh = Kh + APL;

        float acc[8][4];
        compute_scores1(Qh, Kh, wr, co, lane, acc);

        float* wb = w_out + (size_t)n * ((size_t)T_DIM * T_DIM)
                  + (size_t)(qb + wr + (lane >> 2)) * T_DIM + sc * 128 + co + (lane & 3) * 2;
#pragma unroll
        for (int j = 0; j < 8; j++) {
            float p0 = exp2f(acc[j][0] * EC) * invl[0];
            float p1 = exp2f(acc[j][1] * EC) * invl[0];
            float p2 = exp2f(acc[j][2] * EC) * invl[1];
            float p3 = exp2f(acc[j][3] * EC) * invl[1];
            acc[j][0] = p0; acc[j][1] = p1; acc[j][2] = p2; acc[j][3] = p3;
            stg_cs_f2(wb + j * 8, p0, p1);
            stg_cs_f2(wb + 8 * (size_t)T_DIM + j * 8, p2, p3);
        }

        // PV: p x Vh; x4 trans loads = 1 ldmatrix per 2 d8-fragments
#pragma unroll
        for (int g = 0; g < 4; g++) {
            unsigned a0 = packh_f(acc[2 * g][0],     acc[2 * g][1]);
            unsigned a1 = packh_f(acc[2 * g][2],     acc[2 * g][3]);
            unsigned a2 = packh_f(acc[2 * g + 1][0], acc[2 * g + 1][1]);
            unsigned a3 = packh_f(acc[2 * g + 1][2], acc[2 * g + 1][3]);
#pragma unroll
            for (int jj = 0; jj < 4; jj++) {
                int voff = (co + g * 16 + (lane & 7) + ((lane >> 3) & 1) * 8) * ASTR
                         + jj * 16 + ((lane >> 4) & 1) * 8;
                unsigned b0, b1, b2, b3;
                ldmBT4(smem_u32(&Vh[voff]), b0, b1, b2, b3);
                mma16816(o[2 * jj],     a0, a1, a2, a3, b0, b1);
                mma16816(o[2 * jj + 1], a0, a1, a2, a3, b2, b3);
            }
        }
    }

    // ---------------- merge partial O across the two halves ----------------
    float* os = (float*)sm;
    __syncthreads();
    if (hv == 1) {
#pragma unroll
        for (int j = 0; j < 8; j++)
#pragma unroll
            for (int q = 0; q < 4; q++)
                os[(rowgrp * 32 + lane) * 32 + j * 4 + q] = o[j][q];
    }
    __syncthreads();
    if (hv == 0) {
#pragma unroll
        for (int j = 0; j < 8; j++)
#pragma unroll
            for (int q = 0; q < 4; q++)
                o[j][q] += os[(rowgrp * 32 + lane) * 32 + j * 4 + q];

        const int bsel = n >> 4, h = n & 15;
        const int t0   = qb + wr + (lane >> 2);
        const int dcol = (lane & 3) * 2;
#pragma unroll
        for (int j = 0; j < 8; j++) {
            int d = j * 8 + dcol;
            size_t off = (size_t)(t0 * 2 + bsel) * E_DIM + h * 64 + d;
            *(unsigned*)&g_ah[off] = packh_f(o[j][0], o[j][1]);
            off = (size_t)((t0 + 8) * 2 + bsel) * E_DIM + h * 64 + d;
            *(unsigned*)&g_ah[off] = packh_f(o[j][2], o[j][3]);
        }
    }
}

// ---------------------------------------------------------------------------
// Output projection (single-plane fp16), cp.async 3-stage, 1 sync/k-tile.
// ---------------------------------------------------------------------------
__global__ __launch_bounds__(256, 2) void gemm_out(
    const float* __restrict__ bo, float* __restrict__ out)
{
    extern __shared__ __half sb[];

    const int n0 = blockIdx.y * 128;
    const int m0 = blockIdx.x * 128;

    const int tid = threadIdx.x, lane = tid & 31, wid = tid >> 5;
    const int wm = (wid >> 2) * 64, wn = (wid & 3) * 32;
    const int lr = tid >> 2;
    const int lc = (tid & 3) * 8;

    float acc[4][4][4];
#pragma unroll
    for (int i = 0; i < 4; i++)
#pragma unroll
        for (int j = 0; j < 4; j++)
#pragma unroll
            for (int q = 0; q < 4; q++) acc[i][j][q] = 0.f;

    auto load_stage = [&](int s, int k0) {
        __half* base = sb + s * GSTG;
#pragma unroll
        for (int rr = 0; rr < 128; rr += 64) {
            int row = rr + lr;
            size_t ga = (size_t)(m0 + row) * 1024 + k0 + lc;
            size_t gb = (size_t)(n0 + row) * 1024 + k0 + lc;
            unsigned d = smem_u32(base + row * GSTR + lc);
            cp16(d,           g_ah + ga);
            cp16(d + GPL * 2, g_woh + gb);
        }
    };

    load_stage(0, 0);  cp_commit();
    load_stage(1, 32); cp_commit();

    for (int kt = 0; kt < 32; kt++) {
        if (kt < 31) cp_wait<1>(); else cp_wait<0>();
        __syncthreads();
        if (kt + 2 < 32) { load_stage((kt + 2) % 3, (kt + 2) * 32); cp_commit(); }

        const __half* Ah = sb + (kt % 3) * GSTG;
        const __half* Bh = Ah + GPL;

#pragma unroll
        for (int kf = 0; kf < 2; kf++) {
            unsigned ah[4][4];
#pragma unroll
            for (int i = 0; i < 4; i++) {
                int aoff = (wm + i * 16 + (lane & 15)) * GSTR + kf * 16 + (lane >> 4) * 8;
                ldmA(smem_u32(&Ah[aoff]), ah[i][0], ah[i][1], ah[i][2], ah[i][3]);
            }
#pragma unroll
            for (int jj = 0; jj < 2; jj++) {
                int boff = (wn + jj * 16 + (lane & 7) + ((lane >> 4) & 1) * 8) * GSTR
                         + kf * 16 + ((lane >> 3) & 1) * 8;
                unsigned b0, b1, b2, b3;
                ldmB4(smem_u32(&Bh[boff]), b0, b1, b2, b3);
#pragma unroll
                for (int i = 0; i < 4; i++) {
                    mma16816(acc[i][2 * jj],     ah[i][0], ah[i][1], ah[i][2], ah[i][3], b0, b1);
                    mma16816(acc[i][2 * jj + 1], ah[i][0], ah[i][1], ah[i][2], ah[i][3], b2, b3);
                }
            }
        }
    }

#pragma unroll
    for (int i = 0; i < 4; i++) {
#pragma unroll
        for (int j = 0; j < 4; j++) {
            int col = n0 + wn + j * 8 + (lane & 3) * 2;
            float b0 = bo[col], b1 = bo[col + 1];
#pragma unroll
            for (int hf = 0; hf < 2; hf++) {
                int r = m0 + wm + i * 16 + (lane >> 2) + hf * 8;
                float2 v;
                v.x = acc[i][j][2 * hf + 0] + b0;
                v.y = acc[i][j][2 * hf + 1] + b1;
                *(float2*)(out + (size_t)r * 1024 + col) = v;
            }
        }
    }
}

// ---------------------------------------------------------------------------
// d_out = [ out (4096*1024 fp32) | attn_weights (32*2048*2048 fp32) ]
// ---------------------------------------------------------------------------
extern "C" void kernel_launch(void* const* d_in, const int* in_sizes, int n_in,
                              void* d_out, int out_size)
{
    const float* query = (const float*)d_in[0];
    const float* wq    = (const float*)d_in[1];
    const float* bq    = (const float*)d_in[2];
    const float* wk    = (const float*)d_in[3];
    const float* bk    = (const float*)d_in[4];
    const float* wv    = (const float*)d_in[5];
    const float* bv    = (const float*)d_in[6];
    const float* wo    = (const float*)d_in[7];
    const float* bo    = (const float*)d_in[8];

    float* out   = (float*)d_out;
    float* w_out = out + (size_t)M_DIM * E_DIM;

    const int gemm_smem = 3 * GSTG * (int)sizeof(__half);   // 61,440 B
    const int attn_smem = 7 * APL * (int)sizeof(__half);    // 129,024 B
    cudaFuncSetAttribute(gemm_qkv,    cudaFuncAttributeMaxDynamicSharedMemorySize, gemm_smem);
    cudaFuncSetAttribute(attn_kernel, cudaFuncAttributeMaxDynamicSharedMemorySize, attn_smem);
    cudaFuncSetAttribute(gemm_out,    cudaFuncAttributeMaxDynamicSharedMemorySize, gemm_smem);

    split_all<<<8192, 256>>>(query, wq, wk, wv, wo);
    gemm_qkv<<<dim3(32, 24), 256, gemm_smem>>>(bq, bk, bv);
    attn_kernel<<<dim3(16, 32), 512, attn_smem>>>(w_out);
    gemm_out<<<dim3(32, 8), 256, gemm_smem>>>(bo, out);
}

// round 17
// speedup vs baseline: 6.3658x; 1.0219x over previous
#include <cuda_runtime.h>
#include <cuda_bf16.h>
#include <cuda_fp16.h>

// T=2048, B=2, E=1024, H=16, D=64
#define T_DIM 2048
#define E_DIM 1024
#define NH    32            // B*H
#define M_DIM 4096          // T*B
#define HD    (T_DIM * 64)  // per-head plane elems

// 0.125 * log2(e): score scaling folded into exp2
#define EC 0.18033688011112042f

// ---------------------------------------------------------------------------
// Device-global scratch: single fp16 plane everywhere.
// ---------------------------------------------------------------------------
__device__ __half g_xh[(size_t)M_DIM * E_DIM];
__device__ __half g_wqh[1024 * 1024];
__device__ __half g_wkh[1024 * 1024];
__device__ __half g_wvh[1024 * 1024];
__device__ __half g_woh[1024 * 1024];
__device__ __half g_qh[(size_t)NH * HD];                          // q, unscaled
__device__ __half g_kh[(size_t)NH * HD];
__device__ __half g_vh[(size_t)NH * HD];
__device__ __half g_ah[(size_t)M_DIM * E_DIM];                    // attn result

// ---------------------------------------------------------------------------
// Helpers
// ---------------------------------------------------------------------------
__device__ __forceinline__ unsigned smem_u32(const void* p) {
    return (unsigned)__cvta_generic_to_shared(p);
}
__device__ __forceinline__ void cp16(unsigned dst, const void* src) {
    asm volatile("cp.async.cg.shared.global [%0], [%1], 16;" :: "r"(dst), "l"(src));
}
__device__ __forceinline__ void cp_commit() {
    asm volatile("cp.async.commit_group;");
}
template <int N> __device__ __forceinline__ void cp_wait() {
    asm volatile("cp.async.wait_group %0;" :: "n"(N));
}
__device__ __forceinline__ void ldmA(unsigned addr, unsigned& r0, unsigned& r1,
                                     unsigned& r2, unsigned& r3) {
    asm volatile("ldmatrix.sync.aligned.m8n8.x4.shared.b16 {%0,%1,%2,%3}, [%4];"
                 : "=r"(r0), "=r"(r1), "=r"(r2), "=r"(r3) : "r"(addr));
}
// x4 load of TWO adjacent n8k16 B-fragments (j, j+1)
__device__ __forceinline__ void ldmB4(unsigned addr, unsigned& r0, unsigned& r1,
                                      unsigned& r2, unsigned& r3) {
    asm volatile("ldmatrix.sync.aligned.m8n8.x4.shared.b16 {%0,%1,%2,%3}, [%4];"
                 : "=r"(r0), "=r"(r1), "=r"(r2), "=r"(r3) : "r"(addr));
}
// x4 transposed load of TWO adjacent B-fragments for PV
__device__ __forceinline__ void ldmBT4(unsigned addr, unsigned& r0, unsigned& r1,
                                       unsigned& r2, unsigned& r3) {
    asm volatile("ldmatrix.sync.aligned.m8n8.x4.trans.shared.b16 {%0,%1,%2,%3}, [%4];"
                 : "=r"(r0), "=r"(r1), "=r"(r2), "=r"(r3) : "r"(addr));
}
// fp16 MMA, fp32 accumulate
__device__ __forceinline__ void mma16816(float* c, unsigned a0, unsigned a1,
                                         unsigned a2, unsigned a3,
                                         unsigned b0, unsigned b1) {
    asm volatile(
        "mma.sync.aligned.m16n8k16.row.col.f32.f16.f16.f32 "
        "{%0,%1,%2,%3}, {%4,%5,%6,%7}, {%8,%9}, {%0,%1,%2,%3};"
        : "+f"(c[0]), "+f"(c[1]), "+f"(c[2]), "+f"(c[3])
        : "r"(a0), "r"(a1), "r"(a2), "r"(a3), "r"(b0), "r"(b1));
}
// single-instruction f32 pair -> packed f16x2 (lo = x, hi = y), round-nearest
__device__ __forceinline__ unsigned packh_f(float x, float y) {
    unsigned r;
    asm("cvt.rn.f16x2.f32 %0, %1, %2;" : "=r"(r) : "f"(y), "f"(x));
    return r;
}
__device__ __forceinline__ void stg_cs_f2(float* p, float a, float b) {
    asm volatile("st.global.cs.v2.f32 [%0], {%1,%2};" :: "l"(p), "f"(a), "f"(b));
}

// ---------------------------------------------------------------------------
// Split fp32 inputs into fp16. 2M float4 elems total.
// ---------------------------------------------------------------------------
__global__ __launch_bounds__(256) void split_all(
    const float* __restrict__ X, const float* __restrict__ wq,
    const float* __restrict__ wk, const float* __restrict__ wv,
    const float* __restrict__ wo)
{
    size_t i = (size_t)blockIdx.x * 256 + threadIdx.x;
    const float* src; __half* dh; size_t off;
    if (i < 1048576) { src = X; dh = g_xh; off = i; }
    else {
        size_t j = i - 1048576;
        int w = (int)(j >> 18);
        off = j & 262143;
        if      (w == 0) { src = wq; dh = g_wqh; }
        else if (w == 1) { src = wk; dh = g_wkh; }
        else if (w == 2) { src = wv; dh = g_wvh; }
        else             { src = wo; dh = g_woh; }
    }
    float4 v = ((const float4*)src)[off];
    ((unsigned*)dh)[off * 2]     = packh_f(v.x, v.y);
    ((unsigned*)dh)[off * 2 + 1] = packh_f(v.z, v.w);
}

// ---------------------------------------------------------------------------
// GEMM tile constants: 2 planes per stage (A, B), K-chunk 32, 3 stages.
// 512 threads, warp grid 4x4, warp tile 32x32, 2 CTAs/SM (32 warps).
// ---------------------------------------------------------------------------
#define GSTR  40
#define GPL   (128 * GSTR)
#define GSTG  (2 * GPL)

// ---------------------------------------------------------------------------
// QKV projection GEMM (single-plane fp16), cp.async 3-stage, 1 sync/k-tile.
// Outputs unscaled by 0.125 (applied via EC at score stage).
// ---------------------------------------------------------------------------
__global__ __launch_bounds__(512, 2) void gemm_qkv(
    const float* __restrict__ bq, const float* __restrict__ bk, const float* __restrict__ bv)
{
    extern __shared__ __half sb[];

    const int wsel = blockIdx.y >> 3;
    const int n0   = (blockIdx.y & 7) * 128;
    const int m0   = blockIdx.x * 128;

    const __half* Wh = (wsel == 0) ? g_wqh : (wsel == 1) ? g_wkh : g_wvh;
    const float* bias = (wsel == 0) ? bq : (wsel == 1) ? bk : bv;
    __half* dh = (wsel == 0) ? g_qh : (wsel == 1) ? g_kh : g_vh;

    const int tid = threadIdx.x, lane = tid & 31, wid = tid >> 5;
    const int wm = (wid >> 2) * 32, wn = (wid & 3) * 32;
    const int lr = tid >> 2;           // 0..127
    const int lc = (tid & 3) * 8;      // 0..24

    float acc[2][4][4];
#pragma unroll
    for (int i = 0; i < 2; i++)
#pragma unroll
        for (int j = 0; j < 4; j++)
#pragma unroll
            for (int q = 0; q < 4; q++) acc[i][j][q] = 0.f;

    auto load_stage = [&](int s, int k0) {
        __half* base = sb + s * GSTG;
        size_t ga = (size_t)(m0 + lr) * 1024 + k0 + lc;
        size_t gb = (size_t)(n0 + lr) * 1024 + k0 + lc;
        unsigned d = smem_u32(base + lr * GSTR + lc);
        cp16(d,           g_xh + ga);
        cp16(d + GPL * 2, Wh + gb);
    };

    load_stage(0, 0);  cp_commit();
    load_stage(1, 32); cp_commit();

    for (int kt = 0; kt < 32; kt++) {
        if (kt < 31) cp_wait<1>(); else cp_wait<0>();
        __syncthreads();
        if (kt + 2 < 32) { load_stage((kt + 2) % 3, (kt + 2) * 32); cp_commit(); }

        const __half* Ah = sb + (kt % 3) * GSTG;
        const __half* Bh = Ah + GPL;

#pragma unroll
        for (int kf = 0; kf < 2; kf++) {
            unsigned ah[2][4];
#pragma unroll
            for (int i = 0; i < 2; i++) {
                int aoff = (wm + i * 16 + (lane & 15)) * GSTR + kf * 16 + (lane >> 4) * 8;
                ldmA(smem_u32(&Ah[aoff]), ah[i][0], ah[i][1], ah[i][2], ah[i][3]);
            }
#pragma unroll
            for (int jj = 0; jj < 2; jj++) {
                int boff = (wn + jj * 16 + (lane & 7) + ((lane >> 4) & 1) * 8) * GSTR
                         + kf * 16 + ((lane >> 3) & 1) * 8;
                unsigned b0, b1, b2, b3;
                ldmB4(smem_u32(&Bh[boff]), b0, b1, b2, b3);
#pragma unroll
                for (int i = 0; i < 2; i++) {
                    mma16816(acc[i][2 * jj],     ah[i][0], ah[i][1], ah[i][2], ah[i][3], b0, b1);
                    mma16816(acc[i][2 * jj + 1], ah[i][0], ah[i][1], ah[i][2], ah[i][3], b2, b3);
                }
            }
        }
    }

#pragma unroll
    for (int i = 0; i < 2; i++) {
#pragma unroll
        for (int j = 0; j < 4; j++) {
            int col = n0 + wn + j * 8 + (lane & 3) * 2;
            float b0 = bias[col], b1 = bias[col + 1];
            int h = col >> 6, d = col & 63;
#pragma unroll
            for (int hf = 0; hf < 2; hf++) {
                int r = m0 + wm + i * 16 + (lane >> 2) + hf * 8;
                float v0 = acc[i][j][2 * hf + 0] + b0;
                float v1 = acc[i][j][2 * hf + 1] + b1;
                size_t off = (size_t)((r & 1) * 16 + h) * HD + (size_t)(r >> 1) * 64 + d;
                *(unsigned*)&dh[off] = packh_f(v0, v1);
            }
        }
    }
}

// ---------------------------------------------------------------------------
// Attention score half-tile (fp16): acc = qh(16 rows) @ kh^T(64 cols at `co`).
// ---------------------------------------------------------------------------
#define ASTR 72
#define APL  (128 * ASTR)

__device__ __forceinline__ void compute_scores1(
    const __half* Qh, const __half* Kh,
    int wr, int co, int lane, float acc[8][4])
{
#pragma unroll
    for (int j = 0; j < 8; j++)
#pragma unroll
        for (int q = 0; q < 4; q++) acc[j][q] = 0.f;

#pragma unroll
    for (int kf = 0; kf < 4; kf++) {
        unsigned ah[4];
        int qoff = (wr + (lane & 15)) * ASTR + kf * 16 + (lane >> 4) * 8;
        ldmA(smem_u32(&Qh[qoff]), ah[0], ah[1], ah[2], ah[3]);
#pragma unroll
        for (int jj = 0; jj < 4; jj++) {
            int koff = (co + jj * 16 + (lane & 7) + ((lane >> 4) & 1) * 8) * ASTR
                     + kf * 16 + ((lane >> 3) & 1) * 8;
            unsigned b0, b1, b2, b3;
            ldmB4(smem_u32(&Kh[koff]), b0, b1, b2, b3);
            mma16816(acc[2 * jj],     ah[0], ah[1], ah[2], ah[3], b0, b1);
            mma16816(acc[2 * jj + 1], ah[0], ah[1], ah[2], ah[3], b2, b3);
        }
    }
}

// ---------------------------------------------------------------------------
// Attention: per (head n, 128-row q-block). 512 threads / 16 warps.
// rowgrp = wid&7 (16 rows); column half hv = wid>>3 (64 of 128 cols).
// Max-free softmax. 3-stage cp.async, 1 sync per tile.
// smem planes: Qh(1) + 3 stages x (Kh,Vh) = 7 APL = 129,024 B.
// ---------------------------------------------------------------------------
__global__ __launch_bounds__(512, 1) void attn_kernel(float* __restrict__ w_out)
{
    extern __shared__ __half sm[];
    __half* Qh = sm;
    // stage s (s=0..2): sm + APL + s*2*APL -> Kh, Vh

    const int n   = blockIdx.y;
    const int qb  = blockIdx.x * 128;
    const int tid = threadIdx.x, lane = tid & 31, wid = tid >> 5;
    const int rowgrp = wid & 7, hv = wid >> 3;
    const int wr = rowgrp * 16, co = hv * 64;

    const __half* qhg = g_qh + (size_t)n * HD + (size_t)qb * 64;
    const __half* khg = g_kh + (size_t)n * HD;
    const __half* vhg = g_vh + (size_t)n * HD;

    for (int idx = tid; idx < 128 * 8; idx += 512) {
        int row = idx >> 3, c = (idx & 7) * 8;
        *(uint4*)&Qh[row * ASTR + c] = *(const uint4*)(qhg + (size_t)row * 64 + c);
    }

    const int ar = tid >> 3, ac = (tid & 7) * 8;

    auto load_k1 = [&](int s, int sc) {
        __half* kh = sm + APL + s * 2 * APL;
#pragma unroll
        for (int rr = 0; rr < 128; rr += 64) {
            int row = rr + ar;
            size_t g = (size_t)(sc * 128 + row) * 64 + ac;
            cp16(smem_u32(&kh[row * ASTR + ac]), khg + g);
        }
    };
    auto load_kv = [&](int s, int sc) {
        __half* kh = sm + APL + s * 2 * APL;
#pragma unroll
        for (int rr = 0; rr < 128; rr += 64) {
            int row = rr + ar;
            size_t g = (size_t)(sc * 128 + row) * 64 + ac;
            unsigned d = smem_u32(&kh[row * ASTR + ac]);
            cp16(d,           khg + g);
            cp16(d + APL * 2, vhg + g);
        }
    };

    float lv[2] = {0.f, 0.f};

    // ---------------- pass 1: l partials (qh*kh scores, no max) ------------
    load_k1(0, 0); cp_commit();
    load_k1(1, 1); cp_commit();
    for (int sc = 0; sc < 16; sc++) {
        if (sc < 15) cp_wait<1>(); else cp_wait<0>();
        __syncthreads();
        if (sc + 2 < 16) { load_k1((sc + 2) % 3, sc + 2); cp_commit(); }

        const __half* Kh = sm + APL + (sc % 3) * 2 * APL;

        float acc[8][4];
        compute_scores1(Qh, Kh, wr, co, lane, acc);

#pragma unroll
        for (int j = 0; j < 8; j++) {
            lv[0] += exp2f(acc[j][0] * EC) + exp2f(acc[j][1] * EC);
            lv[1] += exp2f(acc[j][2] * EC) + exp2f(acc[j][3] * EC);
        }
    }

    // single reduction: across lane quad, then across column halves via smem
#pragma unroll
    for (int hf = 0; hf < 2; hf++) {
        lv[hf] += __shfl_xor_sync(0xffffffffu, lv[hf], 1);
        lv[hf] += __shfl_xor_sync(0xffffffffu, lv[hf], 2);
    }
    float* st = (float*)(sm + APL);   // overlaps stage bufs; sync first
    __syncthreads();
    if ((lane & 3) == 0) {
        int r_ = lane >> 2;
        st[hv * 128 + rowgrp * 16 + r_]     = lv[0];
        st[hv * 128 + rowgrp * 16 + r_ + 8] = lv[1];
    }
    __syncthreads();
    float invl[2];
#pragma unroll
    for (int hf = 0; hf < 2; hf++) {
        int r_ = (lane >> 2) + hf * 8;
        invl[hf] = 1.0f / (st[rowgrp * 16 + r_] + st[128 + rowgrp * 16 + r_]);
    }
    __syncthreads();   // st reads done before pass-2 loads overwrite

    float o[8][4];
#pragma unroll
    for (int j = 0; j < 8; j++)
#pragma unroll
        for (int q = 0; q < 4; q++) o[j][q] = 0.f;

    // ---------------- pass 2: weights out + partial P@V ----------------
    load_kv(0, 0); cp_commit();
    load_kv(1, 1); cp_commit();
    for (int sc = 0; sc < 16; sc++) {
        if (sc < 15) cp_wait<1>(); else cp_wait<0>();
        __syncthreads();
        if (sc + 2 < 16) { load_kv((sc + 2) % 3, sc + 2); cp_commit(); }

        const __half* Kh = sm + APL + (sc % 3) * 2 * APL;
        const __half* Vh = Kh + APL;

        float acc[8][4];
        compute_scores1(Qh, Kh, wr, co, lane, acc);

        float* wb = w_out + (size_t)n * ((size_t)T_DIM * T_DIM)
                  + (size_t)(qb + wr + (lane >> 2)) * T_DIM + sc * 128 + co + (lane & 3) * 2;
#pragma unroll
        for (int j = 0; j < 8; j++) {
            float p0 = exp2f(acc[j][0] * EC) * invl[0];
            float p1 = exp2f(acc[j][1] * EC) * invl[0];
            float p2 = exp2f(acc[j][2] * EC) * invl[1];
            float p3 = exp2f(acc[j][3] * EC) * invl[1];
            acc[j][0] = p0; acc[j][1] = p1; acc[j][2] = p2; acc[j][3] = p3;
            stg_cs_f2(wb + j * 8, p0, p1);
            stg_cs_f2(wb + 8 * (size_t)T_DIM + j * 8, p2, p3);
        }

        // PV: p x Vh; x4 trans loads = 1 ldmatrix per 2 d8-fragments
#pragma unroll
        for (int g = 0; g < 4; g++) {
            unsigned a0 = packh_f(acc[2 * g][0],     acc[2 * g][1]);
            unsigned a1 = packh_f(acc[2 * g][2],     acc[2 * g][3]);
            unsigned a2 = packh_f(acc[2 * g + 1][0], acc[2 * g + 1][1]);
            unsigned a3 = packh_f(acc[2 * g + 1][2], acc[2 * g + 1][3]);
#pragma unroll
            for (int jj = 0; jj < 4; jj++) {
                int voff = (co + g * 16 + (lane & 7) + ((lane >> 3) & 1) * 8) * ASTR
                         + jj * 16 + ((lane >> 4) & 1) * 8;
                unsigned b0, b1, b2, b3;
                ldmBT4(smem_u32(&Vh[voff]), b0, b1, b2, b3);
                mma16816(o[2 * jj],     a0, a1, a2, a3, b0, b1);
                mma16816(o[2 * jj + 1], a0, a1, a2, a3, b2, b3);
            }
        }
    }

    // ---------------- merge partial O across the two halves ----------------
    float* os = (float*)sm;
    __syncthreads();
    if (hv == 1) {
#pragma unroll
        for (int j = 0; j < 8; j++)
#pragma unroll
            for (int q = 0; q < 4; q++)
                os[(rowgrp * 32 + lane) * 32 + j * 4 + q] = o[j][q];
    }
    __syncthreads();
    if (hv == 0) {
#pragma unroll
        for (int j = 0; j < 8; j++)
#pragma unroll
            for (int q = 0; q < 4; q++)
                o[j][q] += os[(rowgrp * 32 + lane) * 32 + j * 4 + q];

        const int bsel = n >> 4, h = n & 15;
        const int t0   = qb + wr + (lane >> 2);
        const int dcol = (lane & 3) * 2;
#pragma unroll
        for (int j = 0; j < 8; j++) {
            int d = j * 8 + dcol;
            size_t off = (size_t)(t0 * 2 + bsel) * E_DIM + h * 64 + d;
            *(unsigned*)&g_ah[off] = packh_f(o[j][0], o[j][1]);
            off = (size_t)((t0 + 8) * 2 + bsel) * E_DIM + h * 64 + d;
            *(unsigned*)&g_ah[off] = packh_f(o[j][2], o[j][3]);
        }
    }
}

// ---------------------------------------------------------------------------
// Output projection (single-plane fp16), 512 threads, 32x32 warp tiles,
// cp.async 3-stage, 1 sync/k-tile, 2 CTAs/SM.
// ---------------------------------------------------------------------------
__global__ __launch_bounds__(512, 2) void gemm_out(
    const float* __restrict__ bo, float* __restrict__ out)
{
    extern __shared__ __half sb[];

    const int n0 = blockIdx.y * 128;
    const int m0 = blockIdx.x * 128;

    const int tid = threadIdx.x, lane = tid & 31, wid = tid >> 5;
    const int wm = (wid >> 2) * 32, wn = (wid & 3) * 32;
    const int lr = tid >> 2;
    const int lc = (tid & 3) * 8;

    float acc[2][4][4];
#pragma unroll
    for (int i = 0; i < 2; i++)
#pragma unroll
        for (int j = 0; j < 4; j++)
#pragma unroll
            for (int q = 0; q < 4; q++) acc[i][j][q] = 0.f;

    auto load_stage = [&](int s, int k0) {
        __half* base = sb + s * GSTG;
        size_t ga = (size_t)(m0 + lr) * 1024 + k0 + lc;
        size_t gb = (size_t)(n0 + lr) * 1024 + k0 + lc;
        unsigned d = smem_u32(base + lr * GSTR + lc);
        cp16(d,           g_ah + ga);
        cp16(d + GPL * 2, g_woh + gb);
    };

    load_stage(0, 0);  cp_commit();
    load_stage(1, 32); cp_commit();

    for (int kt = 0; kt < 32; kt++) {
        if (kt < 31) cp_wait<1>(); else cp_wait<0>();
        __syncthreads();
        if (kt + 2 < 32) { load_stage((kt + 2) % 3, (kt + 2) * 32); cp_commit(); }

        const __half* Ah = sb + (kt % 3) * GSTG;
        const __half* Bh = Ah + GPL;

#pragma unroll
        for (int kf = 0; kf < 2; kf++) {
            unsigned ah[2][4];
#pragma unroll
            for (int i = 0; i < 2; i++) {
                int aoff = (wm + i * 16 + (lane & 15)) * GSTR + kf * 16 + (lane >> 4) * 8;
                ldmA(smem_u32(&Ah[aoff]), ah[i][0], ah[i][1], ah[i][2], ah[i][3]);
            }
#pragma unroll
            for (int jj = 0; jj < 2; jj++) {
                int boff = (wn + jj * 16 + (lane & 7) + ((lane >> 4) & 1) * 8) * GSTR
                         + kf * 16 + ((lane >> 3) & 1) * 8;
                unsigned b0, b1, b2, b3;
                ldmB4(smem_u32(&Bh[boff]), b0, b1, b2, b3);
#pragma unroll
                for (int i = 0; i < 2; i++) {
                    mma16816(acc[i][2 * jj],     ah[i][0], ah[i][1], ah[i][2], ah[i][3], b0, b1);
                    mma16816(acc[i][2 * jj + 1], ah[i][0], ah[i][1], ah[i][2], ah[i][3], b2, b3);
                }
            }
        }
    }

#pragma unroll
    for (int i = 0; i < 2; i++) {
#pragma unroll
        for (int j = 0; j < 4; j++) {
            int col = n0 + wn + j * 8 + (lane & 3) * 2;
            float b0 = bo[col], b1 = bo[col + 1];
#pragma unroll
            for (int hf = 0; hf < 2; hf++) {
                int r = m0 + wm + i * 16 + (lane >> 2) + hf * 8;
                float2 v;
                v.x = acc[i][j][2 * hf + 0] + b0;
                v.y = acc[i][j][2 * hf + 1] + b1;
                *(float2*)(out + (size_t)r * 1024 + col) = v;
            }
        }
    }
}

// ---------------------------------------------------------------------------
// d_out = [ out (4096*1024 fp32) | attn_weights (32*2048*2048 fp32) ]
// ---------------------------------------------------------------------------
extern "C" void kernel_launch(void* const* d_in, const int* in_sizes, int n_in,
                              void* d_out, int out_size)
{
    const float* query = (const float*)d_in[0];
    const float* wq    = (const float*)d_in[1];
    const float* bq    = (const float*)d_in[2];
    const float* wk    = (const float*)d_in[3];
    const float* bk    = (const float*)d_in[4];
    const float* wv    = (const float*)d_in[5];
    const float* bv    = (const float*)d_in[6];
    const float* wo    = (const float*)d_in[7];
    const float* bo    = (const float*)d_in[8];

    float* out   = (float*)d_out;
    float* w_out = out + (size_t)M_DIM * E_DIM;

    const int gemm_smem = 3 * GSTG * (int)sizeof(__half);   // 61,440 B
    const int attn_smem = 7 * APL * (int)sizeof(__half);    // 129,024 B
    cudaFuncSetAttribute(gemm_qkv,    cudaFuncAttributeMaxDynamicSharedMemorySize, gemm_smem);
    cudaFuncSetAttribute(attn_kernel, cudaFuncAttributeMaxDynamicSharedMemorySize, attn_smem);
    cudaFuncSetAttribute(gemm_out,    cudaFuncAttributeMaxDynamicSharedMemorySize, gemm_smem);

    split_all<<<8192, 256>>>(query, wq, wk, wv, wo);
    gemm_qkv<<<dim3(32, 24), 512, gemm_smem>>>(bq, bk, bv);
    attn_kernel<<<dim3(16, 32), 512, attn_smem>>>(w_out);
    gemm_out<<<dim3(32, 8), 512, gemm_smem>>>(bo, out);
}